// round 7
// baseline (speedup 1.0000x reference)
#include <cuda_runtime.h>
#include <cuda_bf16.h>
#include <stdint.h>

#define NN 20000
#define NE 320000
#define DN 128
#define DE 128
#define DA 16
#define NH 256
#define NG 64
#define K1TOT 528
#define ST 12              // smem row stride in u32 words (8 used + 4 pad)

// ---------------- scratch ----------------
__device__ float g_nproj[NN * 8];
__device__ float g_eproj[NE * 2];
__device__ float g_logit[NE];
__device__ float g_nmax[NN];
__device__ float g_nsum[NN];
__device__ float g_nodefeat[NN * DE];
__device__ uint32_t g_xh[NN * 64],  g_xl[NN * 64];        // x packed hi/lo [n][kpair]
__device__ uint32_t g_nfh[NN * 64], g_nfl[NN * 64];       // node_feat packed
__device__ uint32_t g_ath[NE * 8],  g_atl[NE * 8];        // attr packed
__device__ uint32_t g_w1h[256 * 264], g_w1l[256 * 264];   // W1 split, [n][kpair]
__device__ uint32_t g_w2h[128 * 128], g_w2l[128 * 128];   // W2 split, [n][kpair]
__device__ uint32_t g_hh[40960000], g_hl[40960000];       // hidden packed [m][kpair]
__device__ float g_rlogit[NE];
__device__ float g_rw[NE];
__device__ float g_gmax[NG];
__device__ float g_gsum[NG];
__device__ float g_graphfeat[NG * DE];

// ---------------- helpers ----------------
__device__ __forceinline__ float dot4(float4 a, float4 b) {
    return fmaf(a.x, b.x, fmaf(a.y, b.y, fmaf(a.z, b.z, a.w * b.w)));
}

__device__ __forceinline__ float wred(float v) {
    v += __shfl_xor_sync(0xffffffffu, v, 16);
    v += __shfl_xor_sync(0xffffffffu, v, 8);
    v += __shfl_xor_sync(0xffffffffu, v, 4);
    v += __shfl_xor_sync(0xffffffffu, v, 2);
    v += __shfl_xor_sync(0xffffffffu, v, 1);
    return v;
}

__device__ __forceinline__ void atomicMaxF(float* addr, float v) {
    int* ia = (int*)addr;
    int old = __float_as_int(*addr);
    while (__int_as_float(old) < v) {
        int prev = atomicCAS(ia, old, __float_as_int(v));
        if (prev == old) break;
        old = prev;
    }
}

__device__ __forceinline__ uint32_t packhi(float f0, float f1) {
    __nv_bfloat162 h = __floats2bfloat162_rn(f0, f1);
    return *(uint32_t*)&h;
}
__device__ __forceinline__ uint32_t packlo(float f0, float f1, uint32_t hi) {
    __nv_bfloat162 h = *(__nv_bfloat162*)&hi;
    float l0 = f0 - __bfloat162float(h.x);
    float l1 = f1 - __bfloat162float(h.y);
    __nv_bfloat162 l = __floats2bfloat162_rn(l0, l1);
    return *(uint32_t*)&l;
}

__device__ __forceinline__ void mma16(float* c, const uint32_t* a, uint32_t b0, uint32_t b1) {
    asm volatile("mma.sync.aligned.m16n8k16.row.col.f32.bf16.bf16.f32 "
        "{%0,%1,%2,%3}, {%4,%5,%6,%7}, {%8,%9}, {%0,%1,%2,%3};"
        : "+f"(c[0]), "+f"(c[1]), "+f"(c[2]), "+f"(c[3])
        : "r"(a[0]), "r"(a[1]), "r"(a[2]), "r"(a[3]), "r"(b0), "r"(b1));
}

__device__ __forceinline__ void ldsm4(uint32_t* r, uint32_t addr) {
    asm volatile("ldmatrix.sync.aligned.m8n8.x4.shared.b16 {%0,%1,%2,%3}, [%4];"
        : "=r"(r[0]), "=r"(r[1]), "=r"(r[2]), "=r"(r[3]) : "r"(addr));
}

// ---------------- init ----------------
__global__ void k_init() {
    int i = blockIdx.x * 256 + threadIdx.x;
    if (i < NN * DE) g_nodefeat[i] = 0.f;
    if (i < NN) { g_nmax[i] = -1e30f; g_nsum[i] = 0.f; }
    if (i < NG * DE) g_graphfeat[i] = 0.f;
    if (i < NG) { g_gmax[i] = -1e30f; g_gsum[i] = 0.f; }
}

// ---------------- one-time splits: x, attr ----------------
__global__ void k_xsplit(const float* __restrict__ x, const float* __restrict__ attr) {
    int i = blockIdx.x * 256 + threadIdx.x;
    if (i < NN * 64) {
        float f0 = x[2 * i], f1 = x[2 * i + 1];
        uint32_t h = packhi(f0, f1);
        g_xh[i] = h; g_xl[i] = packlo(f0, f1, h);
    }
    if (i < NE * 8) {
        float f0 = attr[2 * i], f1 = attr[2 * i + 1];
        uint32_t h = packhi(f0, f1);
        g_ath[i] = h; g_atl[i] = packlo(f0, f1, h);
    }
}

// ---------------- one-time weight bf16 hi/lo split (transposed [n][kp]) ----------------
__global__ void k_wsplit(const float* __restrict__ W1, const float* __restrict__ W2) {
    int i = blockIdx.x * 256 + threadIdx.x;
    if (i < 256 * 264) {
        int n = i / 264, kp = i % 264;
        float f0 = W1[(2 * kp) * 256 + n], f1 = W1[(2 * kp + 1) * 256 + n];
        uint32_t h = packhi(f0, f1);
        g_w1h[i] = h; g_w1l[i] = packlo(f0, f1, h);
    }
    if (i < 128 * 128) {
        int n = i >> 7, kp = i & 127;
        float f0 = W2[(2 * kp) * 128 + n], f1 = W2[(2 * kp + 1) * 128 + n];
        uint32_t h = packhi(f0, f1);
        g_w2h[i] = h; g_w2l[i] = packlo(f0, f1, h);
    }
}

// ---------------- per-node scalar projections ----------------
__global__ void k_nodeproj(const float* __restrict__ x, const float* __restrict__ Wagg,
                           const float* __restrict__ Wupd, const float* __restrict__ Wread) {
    int warp = threadIdx.x >> 5, lane = threadIdx.x & 31;
    int n = blockIdx.x * 8 + warp;
    if (n >= NN) return;
    float4 xv = ((const float4*)x)[n * 32 + lane];
    const float4* wa = (const float4*)Wagg;
    const float4* wu = (const float4*)Wupd;
    const float4* wr = (const float4*)Wread;
    float s0 = dot4(xv, wa[lane]);
    float s1 = dot4(xv, wa[32 + lane]);
    float s2 = dot4(xv, wu[lane]);
    float s3 = dot4(xv, wu[32 + lane]);
    float s4 = dot4(xv, wr[lane]);
    float s5 = dot4(xv, wr[32 + lane]);
    s0 = wred(s0); s1 = wred(s1); s2 = wred(s2);
    s3 = wred(s3); s4 = wred(s4); s5 = wred(s5);
    if (lane == 0) {
        g_nproj[n * 8 + 0] = s0; g_nproj[n * 8 + 1] = s1;
        g_nproj[n * 8 + 2] = s2; g_nproj[n * 8 + 3] = s3;
        g_nproj[n * 8 + 4] = s4; g_nproj[n * 8 + 5] = s5;
    }
}

// ---------------- agg logits + segment max + attr projections ----------------
__global__ void k_agglogit(const float* __restrict__ hef, const float* __restrict__ attr,
                           const int* __restrict__ ei, const float* __restrict__ Wagg,
                           const float* __restrict__ bagg, const float* __restrict__ Wupd,
                           const float* __restrict__ Wread) {
    int warp = threadIdx.x >> 5, lane = threadIdx.x & 31;
    int e = blockIdx.x * 8 + warp;
    if (e >= NE) return;
    int r = ei[e], c = ei[NE + e];
    float4 h4 = ((const float4*)hef)[e * 32 + lane];
    float4 wh = *(const float4*)&Wagg[272 + lane * 4];
    float p = dot4(h4, wh);
    float pu = 0.f, pr = 0.f;
    if (lane < 4) {
        float4 a4 = ((const float4*)attr)[e * 4 + lane];
        p += dot4(a4, *(const float4*)&Wagg[256 + lane * 4]);
        pu = dot4(a4, *(const float4*)&Wupd[256 + lane * 4]);
        pr = dot4(a4, *(const float4*)&Wread[384 + lane * 4]);
    }
    p = wred(p); pu = wred(pu); pr = wred(pr);
    if (lane == 0) {
        float logit = p + g_nproj[r * 8 + 0] + g_nproj[c * 8 + 1] + bagg[0];
        g_logit[e] = logit;
        g_eproj[e * 2 + 0] = pu;
        g_eproj[e * 2 + 1] = pr;
        atomicMaxF(&g_nmax[c], logit);
    }
}

// ---------------- exp + unnormalized scatter + segment sum ----------------
__global__ void k_expscatter(const float* __restrict__ hef, const int* __restrict__ ei) {
    int warp = threadIdx.x >> 5, lane = threadIdx.x & 31;
    int e = blockIdx.x * 8 + warp;
    if (e >= NE) return;
    int c = ei[NE + e];
    float w = expf(g_logit[e] - g_nmax[c]);
    float4 h4 = ((const float4*)hef)[e * 32 + lane];
    float* p = &g_nodefeat[c * 128 + lane * 4];
    asm volatile("red.global.add.v4.f32 [%0], {%1,%2,%3,%4};"
        :: "l"(p), "f"(w * h4.x), "f"(w * h4.y), "f"(w * h4.z), "f"(w * h4.w)
        : "memory");
    if (lane == 0) atomicAdd(&g_nsum[c], w);
}

// ---------------- normalize node_feat + pack hi/lo ----------------
__global__ void k_nnorm() {
    int i = blockIdx.x * 256 + threadIdx.x;
    if (i >= NN * 64) return;
    int n = i >> 6;
    float inv = 1.f / (g_nsum[n] + 1e-16f);
    float f0 = g_nodefeat[2 * i] * inv;
    float f1 = g_nodefeat[2 * i + 1] * inv;
    g_nodefeat[2 * i] = f0;
    g_nodefeat[2 * i + 1] = f1;
    uint32_t h = packhi(f0, f1);
    g_nfh[i] = h; g_nfl[i] = packlo(f0, f1, h);
}

// ==================== GEMM1 (all operands pre-split, ldmatrix) ====================
#define G1_WORDS 12544

__global__ void __launch_bounds__(256, 2)
k_gemm1(const int* __restrict__ ei, const float* __restrict__ b1) {
    extern __shared__ uint32_t sm_[];
    uint32_t* AsH = sm_;
    uint32_t* AsL = sm_ + 3072;
    uint32_t* BsH = sm_ + 6144;
    uint32_t* BsL = sm_ + 9216;
    int* srol = (int*)(sm_ + 12288);
    int* scol = srol + 128;

    int t = threadIdx.x;
    int me0 = blockIdx.x * 128, hn0 = blockIdx.y * 128;
    if (t < 128) srol[t] = ei[me0 + t];
    else scol[t - 128] = ei[NE + me0 + t - 128];
    __syncthreads();

    int am = t >> 1, sw = (t & 1) * 4;
    int lane = t & 31, w = t >> 5;
    int wm = (w & 3) * 32, wn = (w >> 2) * 64;
    int grp = lane >> 2, quad = lane & 3;

    uint32_t smb = (uint32_t)__cvta_generic_to_shared(sm_);
    int arow = wm + (lane & 15);
    uint32_t rA = smb + arow * (ST * 4) + ((lane & 16) ? 16 : 0);
    int brow = wn + (lane & 7) + ((lane & 16) ? 8 : 0);
    uint32_t rB = smb + 6144 * 4 + brow * (ST * 4) + ((lane & 8) ? 16 : 0);
    const uint32_t BUFB = 1536 * 4;
    const uint32_t LOFF = 3072 * 4;

    // k-tile kt covers k-pairs kt*8 .. kt*8+7; each tile lies wholly in one region:
    // kt 0-7: x[rol]  8-15: nf[rol]  16-23: x[col]  24-31: nf[col]  32: attr
    auto ldA16 = [&](int kt, uint4& h, uint4& l) {
        int kp = kt * 8 + sw;
        size_t off;
        const uint32_t *ph, *pl;
        if (kp < 64)       { ph = g_xh;  pl = g_xl;  off = (size_t)srol[am] * 64 + kp; }
        else if (kp < 128) { ph = g_nfh; pl = g_nfl; off = (size_t)srol[am] * 64 + (kp - 64); }
        else if (kp < 192) { ph = g_xh;  pl = g_xl;  off = (size_t)scol[am] * 64 + (kp - 128); }
        else if (kp < 256) { ph = g_nfh; pl = g_nfl; off = (size_t)scol[am] * 64 + (kp - 192); }
        else               { ph = g_ath; pl = g_atl; off = (size_t)(me0 + am) * 8 + (kp - 256); }
        h = *(const uint4*)&ph[off];
        l = *(const uint4*)&pl[off];
    };

    auto stage = [&](int buf, uint4 ah, uint4 al, uint4 bh, uint4 bl) {
        int o = buf * 1536 + am * ST + sw;
        *(uint4*)&AsH[o] = ah;
        *(uint4*)&AsL[o] = al;
        *(uint4*)&BsH[o] = bh;
        *(uint4*)&BsL[o] = bl;
    };

    uint4 ah, al;
    ldA16(0, ah, al);
    uint4 bh = *(const uint4*)&g_w1h[(size_t)(hn0 + am) * 264 + sw];
    uint4 bl = *(const uint4*)&g_w1l[(size_t)(hn0 + am) * 264 + sw];
    stage(0, ah, al, bh, bl);
    __syncthreads();

    float acc[2][8][4];
#pragma unroll
    for (int i = 0; i < 2; i++)
#pragma unroll
        for (int j = 0; j < 8; j++)
#pragma unroll
            for (int k = 0; k < 4; k++) acc[i][j][k] = 0.f;

    const int KT = K1TOT / 16;  // 33
    for (int kt = 0; kt < KT; ++kt) {
        int cur = kt & 1;
        if (kt < KT - 1) {
            ldA16(kt + 1, ah, al);
            bh = *(const uint4*)&g_w1h[(size_t)(hn0 + am) * 264 + (kt + 1) * 8 + sw];
            bl = *(const uint4*)&g_w1l[(size_t)(hn0 + am) * 264 + (kt + 1) * 8 + sw];
        }
        uint32_t aH[2][4], aL[2][4];
#pragma unroll
        for (int mf = 0; mf < 2; mf++) {
            uint32_t ad = rA + cur * BUFB + mf * (16 * ST * 4);
            ldsm4(aH[mf], ad);
            ldsm4(aL[mf], ad + LOFF);
        }
#pragma unroll
        for (int j = 0; j < 4; j++) {
            uint32_t bH[4], bL[4];
            uint32_t bd = rB + cur * BUFB + j * (16 * ST * 4);
            ldsm4(bH, bd);
            ldsm4(bL, bd + LOFF);
#pragma unroll
            for (int mf = 0; mf < 2; mf++) {
                mma16(acc[mf][2 * j],     aH[mf], bH[0], bH[1]);
                mma16(acc[mf][2 * j],     aH[mf], bL[0], bL[1]);
                mma16(acc[mf][2 * j],     aL[mf], bH[0], bH[1]);
                mma16(acc[mf][2 * j + 1], aH[mf], bH[2], bH[3]);
                mma16(acc[mf][2 * j + 1], aH[mf], bL[2], bL[3]);
                mma16(acc[mf][2 * j + 1], aL[mf], bH[2], bH[3]);
            }
        }
        if (kt < KT - 1) stage(cur ^ 1, ah, al, bh, bl);
        __syncthreads();
    }

#pragma unroll
    for (int mf = 0; mf < 2; mf++) {
        int m = me0 + wm + mf * 16 + grp;
#pragma unroll
        for (int nf = 0; nf < 8; nf++) {
            int c0 = hn0 + wn + nf * 8 + quad * 2;
            float bb0 = b1[c0], bb1 = b1[c0 + 1];
            int kp = c0 >> 1;
            float v0 = fmaxf(acc[mf][nf][0] + bb0, 0.f);
            float v1 = fmaxf(acc[mf][nf][1] + bb1, 0.f);
            uint32_t h = packhi(v0, v1);
            g_hh[(size_t)m * 128 + kp] = h;
            g_hl[(size_t)m * 128 + kp] = packlo(v0, v1, h);
            float v2 = fmaxf(acc[mf][nf][2] + bb0, 0.f);
            float v3 = fmaxf(acc[mf][nf][3] + bb1, 0.f);
            h = packhi(v2, v3);
            g_hh[(size_t)(m + 8) * 128 + kp] = h;
            g_hl[(size_t)(m + 8) * 128 + kp] = packlo(v2, v3, h);
        }
    }
}

// ==================== GEMM2 fused: cand -> gate -> ef(out) -> readout logit ====================
#define G2_WORDS 12928

__global__ void __launch_bounds__(256, 2)
k_gemm2f(const float* __restrict__ hef, const int* __restrict__ ei,
         const int* __restrict__ batch, const float* __restrict__ b2,
         const float* __restrict__ Wupd, const float* __restrict__ bupd,
         const float* __restrict__ Wread, const float* __restrict__ bread,
         float* __restrict__ out) {
    extern __shared__ uint32_t sm_[];
    uint32_t* AsH = sm_;
    uint32_t* AsL = sm_ + 3072;
    uint32_t* BsH = sm_ + 6144;
    uint32_t* BsL = sm_ + 9216;
    int*   srol = (int*)(sm_ + 12288);
    int*   scol = (int*)(sm_ + 12416);
    float* sred = (float*)(sm_ + 12544);
    float* sg   = (float*)(sm_ + 12800);

    int t = threadIdx.x;
    int me0 = blockIdx.x * 128;
    if (t < 128) srol[t] = ei[me0 + t];
    else scol[t - 128] = ei[NE + me0 + t - 128];

    int am = t >> 1, sw = (t & 1) * 4;
    int lane = t & 31, w = t >> 5;
    int wm = (w & 3) * 32, wn = (w >> 2) * 64;
    int grp = lane >> 2, quad = lane & 3;

    uint32_t smb = (uint32_t)__cvta_generic_to_shared(sm_);
    int arow = wm + (lane & 15);
    uint32_t rA = smb + arow * (ST * 4) + ((lane & 16) ? 16 : 0);
    int brow = wn + (lane & 7) + ((lane & 16) ? 8 : 0);
    uint32_t rB = smb + 6144 * 4 + brow * (ST * 4) + ((lane & 8) ? 16 : 0);
    const uint32_t BUFB = 1536 * 4;
    const uint32_t LOFF = 3072 * 4;

    auto stage = [&](int buf, uint4 ah, uint4 al, uint4 bh, uint4 bl) {
        int o = buf * 1536 + am * ST + sw;
        *(uint4*)&AsH[o] = ah;
        *(uint4*)&AsL[o] = al;
        *(uint4*)&BsH[o] = bh;
        *(uint4*)&BsL[o] = bl;
    };

    uint4 ah = *(const uint4*)&g_hh[(size_t)(me0 + am) * 128 + sw];
    uint4 al = *(const uint4*)&g_hl[(size_t)(me0 + am) * 128 + sw];
    uint4 bh = *(const uint4*)&g_w2h[am * 128 + sw];
    uint4 bl = *(const uint4*)&g_w2l[am * 128 + sw];
    stage(0, ah, al, bh, bl);
    __syncthreads();

    float acc[2][8][4];
#pragma unroll
    for (int i = 0; i < 2; i++)
#pragma unroll
        for (int j = 0; j < 8; j++)
#pragma unroll
            for (int k = 0; k < 4; k++) acc[i][j][k] = 0.f;

    const int KT = NH / 16;  // 16
    for (int kt = 0; kt < KT; ++kt) {
        int cur = kt & 1;
        if (kt < KT - 1) {
            int o = (kt + 1) * 8 + sw;
            ah = *(const uint4*)&g_hh[(size_t)(me0 + am) * 128 + o];
            al = *(const uint4*)&g_hl[(size_t)(me0 + am) * 128 + o];
            bh = *(const uint4*)&g_w2h[am * 128 + o];
            bl = *(const uint4*)&g_w2l[am * 128 + o];
        }
        uint32_t aH[2][4], aL[2][4];
#pragma unroll
        for (int mf = 0; mf < 2; mf++) {
            uint32_t ad = rA + cur * BUFB + mf * (16 * ST * 4);
            ldsm4(aH[mf], ad);
            ldsm4(aL[mf], ad + LOFF);
        }
#pragma unroll
        for (int j = 0; j < 4; j++) {
            uint32_t bH[4], bL[4];
            uint32_t bd = rB + cur * BUFB + j * (16 * ST * 4);
            ldsm4(bH, bd);
            ldsm4(bL, bd + LOFF);
#pragma unroll
            for (int mf = 0; mf < 2; mf++) {
                mma16(acc[mf][2 * j],     aH[mf], bH[0], bH[1]);
                mma16(acc[mf][2 * j],     aH[mf], bL[0], bL[1]);
                mma16(acc[mf][2 * j],     aL[mf], bH[0], bH[1]);
                mma16(acc[mf][2 * j + 1], aH[mf], bH[2], bH[3]);
                mma16(acc[mf][2 * j + 1], aH[mf], bL[2], bL[3]);
                mma16(acc[mf][2 * j + 1], aL[mf], bH[2], bH[3]);
            }
        }
        if (kt < KT - 1) stage(cur ^ 1, ah, al, bh, bl);
        __syncthreads();
    }

    // acc += b2 -> cand
#pragma unroll
    for (int mf = 0; mf < 2; mf++)
#pragma unroll
        for (int nf = 0; nf < 8; nf++) {
            int c0 = wn + nf * 8 + quad * 2;
            float bb0 = b2[c0], bb1 = b2[c0 + 1];
            acc[mf][nf][0] += bb0; acc[mf][nf][1] += bb1;
            acc[mf][nf][2] += bb0; acc[mf][nf][3] += bb1;
        }

    // ---- epilogue pass 1: gate logit dot ----
    float s0 = 0.f, s1 = 0.f, s2 = 0.f, s3 = 0.f;
#pragma unroll
    for (int mf = 0; mf < 2; mf++) {
        int r0 = wm + mf * 16 + grp;
#pragma unroll
        for (int nf = 0; nf < 8; nf++) {
            int c = wn + nf * 8 + quad * 2;
            float2 wc = *(const float2*)&Wupd[400 + c];
            float2 whv = *(const float2*)&Wupd[272 + c];
            float2 h0 = *(const float2*)&hef[(size_t)(me0 + r0) * 128 + c];
            float2 h1 = *(const float2*)&hef[(size_t)(me0 + r0 + 8) * 128 + c];
            float p0 = acc[mf][nf][0] * wc.x + acc[mf][nf][1] * wc.y + h0.x * whv.x + h0.y * whv.y;
            float p1 = acc[mf][nf][2] * wc.x + acc[mf][nf][3] * wc.y + h1.x * whv.x + h1.y * whv.y;
            if (mf == 0) { s0 += p0; s1 += p1; } else { s2 += p0; s3 += p1; }
        }
    }
    s0 += __shfl_xor_sync(0xffffffffu, s0, 1); s0 += __shfl_xor_sync(0xffffffffu, s0, 2);
    s1 += __shfl_xor_sync(0xffffffffu, s1, 1); s1 += __shfl_xor_sync(0xffffffffu, s1, 2);
    s2 += __shfl_xor_sync(0xffffffffu, s2, 1); s2 += __shfl_xor_sync(0xffffffffu, s2, 2);
    s3 += __shfl_xor_sync(0xffffffffu, s3, 1); s3 += __shfl_xor_sync(0xffffffffu, s3, 2);
    if (quad == 0) {
        int nh = w >> 2;
        sred[(wm + grp) * 2 + nh] = s0;
        sred[(wm + 8 + grp) * 2 + nh] = s1;
        sred[(wm + 16 + grp) * 2 + nh] = s2;
        sred[(wm + 24 + grp) * 2 + nh] = s3;
    }
    __syncthreads();
    if (t < 128) {
        int e = me0 + t, r = srol[t], c = scol[t];
        float tot = sred[t * 2] + sred[t * 2 + 1];
        float gv = tot + g_eproj[e * 2] + g_nproj[r * 8 + 2] + g_nproj[c * 8 + 3] + bupd[0];
        sg[t] = 1.f / (1.f + expf(-gv));
    }
    __syncthreads();

    // ---- epilogue pass 2: ef = g*cand + (1-g)*hef, write out, readout dot ----
    s0 = s1 = s2 = s3 = 0.f;
#pragma unroll
    for (int mf = 0; mf < 2; mf++) {
        int r0 = wm + mf * 16 + grp;
        float g0 = sg[r0], g1 = sg[r0 + 8];
#pragma unroll
        for (int nf = 0; nf < 8; nf++) {
            int c = wn + nf * 8 + quad * 2;
            float2 h0 = *(const float2*)&hef[(size_t)(me0 + r0) * 128 + c];
            float2 h1 = *(const float2*)&hef[(size_t)(me0 + r0 + 8) * 128 + c];
            float2 e0, e1;
            e0.x = fmaf(g0, acc[mf][nf][0] - h0.x, h0.x);
            e0.y = fmaf(g0, acc[mf][nf][1] - h0.y, h0.y);
            e1.x = fmaf(g1, acc[mf][nf][2] - h1.x, h1.x);
            e1.y = fmaf(g1, acc[mf][nf][3] - h1.y, h1.y);
            *(float2*)&out[(size_t)(me0 + r0) * 128 + c] = e0;
            *(float2*)&out[(size_t)(me0 + r0 + 8) * 128 + c] = e1;
            float2 wr = *(const float2*)&Wread[256 + c];
            float p0 = e0.x * wr.x + e0.y * wr.y;
            float p1 = e1.x * wr.x + e1.y * wr.y;
            if (mf == 0) { s0 += p0; s1 += p1; } else { s2 += p0; s3 += p1; }
        }
    }
    s0 += __shfl_xor_sync(0xffffffffu, s0, 1); s0 += __shfl_xor_sync(0xffffffffu, s0, 2);
    s1 += __shfl_xor_sync(0xffffffffu, s1, 1); s1 += __shfl_xor_sync(0xffffffffu, s1, 2);
    s2 += __shfl_xor_sync(0xffffffffu, s2, 1); s2 += __shfl_xor_sync(0xffffffffu, s2, 2);
    s3 += __shfl_xor_sync(0xffffffffu, s3, 1); s3 += __shfl_xor_sync(0xffffffffu, s3, 2);
    if (quad == 0) {
        int nh = w >> 2;
        sred[(wm + grp) * 2 + nh] = s0;
        sred[(wm + 8 + grp) * 2 + nh] = s1;
        sred[(wm + 16 + grp) * 2 + nh] = s2;
        sred[(wm + 24 + grp) * 2 + nh] = s3;
    }
    __syncthreads();
    if (t < 128) {
        int e = me0 + t, r = srol[t], c = scol[t];
        float tot = sred[t * 2] + sred[t * 2 + 1];
        float rl = tot + g_eproj[e * 2 + 1] + g_nproj[r * 8 + 4] + g_nproj[c * 8 + 5] + bread[0];
        g_rlogit[e] = rl;
        atomicMaxF(&g_gmax[batch[r]], rl);
    }
}

// ---------------- readout exp + segment sum ----------------
__global__ void k_rexp(const int* __restrict__ ei, const int* __restrict__ batch) {
    __shared__ float ss[NG];
    int t = threadIdx.x;
    if (t < NG) ss[t] = 0.f;
    __syncthreads();
    int e = blockIdx.x * 256 + t;
    if (e < NE) {
        int gi = batch[ei[e]];
        float rw = expf(g_rlogit[e] - g_gmax[gi]);
        g_rw[e] = rw;
        atomicAdd(&ss[gi], rw);
    }
    __syncthreads();
    if (t < NG && ss[t] != 0.f) atomicAdd(&g_gsum[t], ss[t]);
}

// ---------------- readout scatter ----------------
__global__ void k_rscatter(const int* __restrict__ ei, const int* __restrict__ batch,
                           const float* __restrict__ out) {
    __shared__ float sacc[NG * DE];
    int t = threadIdx.x;
    for (int i = t; i < NG * DE; i += 256) sacc[i] = 0.f;
    __syncthreads();
    int warp = t >> 5, lane = t & 31;
    for (int e = blockIdx.x * 8 + warp; e < NE; e += gridDim.x * 8) {
        int gi = batch[ei[e]];
        float rn = g_rw[e] / (g_gsum[gi] + 1e-16f);
        float4 ef = ((const float4*)out)[e * 32 + lane];
        float* p = &sacc[gi * 128 + lane * 4];
        atomicAdd(p + 0, rn * ef.x);
        atomicAdd(p + 1, rn * ef.y);
        atomicAdd(p + 2, rn * ef.z);
        atomicAdd(p + 3, rn * ef.w);
    }
    __syncthreads();
    for (int i = t; i < NG * DE; i += 256)
        if (sacc[i] != 0.f) atomicAdd(&g_graphfeat[i], sacc[i]);
}

// ---------------- confidence ----------------
__global__ void k_conf(const float* __restrict__ Wscore, const float* __restrict__ bscore,
                       float* __restrict__ out) {
    int g = blockIdx.x, t = threadIdx.x;
    float v = g_graphfeat[g * 128 + t] * Wscore[t];
    v = wred(v);
    __shared__ float sm[4];
    if ((t & 31) == 0) sm[t >> 5] = v;
    __syncthreads();
    if (t == 0) {
        float s = sm[0] + sm[1] + sm[2] + sm[3] + bscore[0];
        out[(size_t)NE * DE + g] = 1.f / (1.f + expf(-s));
    }
}

// ---------------- launch ----------------
extern "C" void kernel_launch(void* const* d_in, const int* in_sizes, int n_in,
                              void* d_out, int out_size) {
    const float* x      = (const float*)d_in[0];
    const float* hef    = (const float*)d_in[1];
    const float* attr   = (const float*)d_in[2];
    const int*   ei     = (const int*)d_in[3];
    const int*   batch  = (const int*)d_in[4];
    const float* Wagg   = (const float*)d_in[6];
    const float* bagg   = (const float*)d_in[7];
    const float* W1     = (const float*)d_in[8];
    const float* b1     = (const float*)d_in[9];
    const float* W2     = (const float*)d_in[10];
    const float* b2     = (const float*)d_in[11];
    const float* Wupd   = (const float*)d_in[12];
    const float* bupd   = (const float*)d_in[13];
    const float* Wread  = (const float*)d_in[14];
    const float* bread  = (const float*)d_in[15];
    const float* Wscore = (const float*)d_in[16];
    const float* bscore = (const float*)d_in[17];
    float* out = (float*)d_out;

    static bool attr_set = false;
    if (!attr_set) {
        cudaFuncSetAttribute(k_gemm1, cudaFuncAttributeMaxDynamicSharedMemorySize, G1_WORDS * 4);
        cudaFuncSetAttribute(k_gemm2f, cudaFuncAttributeMaxDynamicSharedMemorySize, G2_WORDS * 4);
        attr_set = true;
    }

    k_init<<<(NN * DE + 255) / 256, 256>>>();
    k_xsplit<<<(NE * 8 + 255) / 256, 256>>>(x, attr);
    k_wsplit<<<(256 * 264 + 255) / 256, 256>>>(W1, W2);
    k_nodeproj<<<(NN + 7) / 8, 256>>>(x, Wagg, Wupd, Wread);
    k_agglogit<<<NE / 8, 256>>>(hef, attr, ei, Wagg, bagg, Wupd, Wread);
    k_expscatter<<<NE / 8, 256>>>(hef, ei);
    k_nnorm<<<(NN * 64 + 255) / 256, 256>>>();
    k_gemm1<<<dim3(NE / 128, 2), 256, G1_WORDS * 4>>>(ei, b1);
    k_gemm2f<<<NE / 128, 256, G2_WORDS * 4>>>(hef, ei, batch, b2, Wupd, bupd,
                                              Wread, bread, out);
    k_rexp<<<NE / 256, 256>>>(ei, batch);
    k_rscatter<<<296, 256>>>(ei, batch, out);
    k_conf<<<NG, 128>>>(Wscore, bscore, out);
}

// round 9
// speedup vs baseline: 1.5544x; 1.5544x over previous
#include <cuda_runtime.h>
#include <cuda_bf16.h>
#include <stdint.h>

#define NN 20000
#define NE 320000
#define DN 128
#define DE 128
#define DA 16
#define NH 256
#define NG 64
#define K1TOT 528
#define ST 12              // smem row stride in u32 words (8 used + 4 pad)

// ---------------- scratch ----------------
__device__ float g_nproj[NN * 8];
__device__ float g_eproj[NE * 2];
__device__ float g_logit[NE];
__device__ float g_nmax[NN];
__device__ float g_nsum[NN];
__device__ float g_nodefeat[NN * DE];
__device__ uint32_t g_xh[NN * 64],  g_xl[NN * 64];        // x packed hi/lo [n][kpair]
__device__ uint32_t g_nfh[NN * 64], g_nfl[NN * 64];       // node_feat packed
__device__ uint32_t g_ath[NE * 8],  g_atl[NE * 8];        // attr packed
__device__ uint32_t g_w1h[256 * 264], g_w1l[256 * 264];   // W1 split, [n][kpair]
__device__ uint32_t g_w2h[128 * 128], g_w2l[128 * 128];   // W2 split, [n][kpair]
__device__ uint32_t g_hh[40960000], g_hl[40960000];       // hidden packed [m][kpair]
__device__ float g_rlogit[NE];
__device__ float g_gmax[NG];
__device__ float g_gsum[NG];
__device__ float g_graphfeat[NG * DE];

// ---------------- helpers ----------------
__device__ __forceinline__ float dot4(float4 a, float4 b) {
    return fmaf(a.x, b.x, fmaf(a.y, b.y, fmaf(a.z, b.z, a.w * b.w)));
}

__device__ __forceinline__ float wred(float v) {
    v += __shfl_xor_sync(0xffffffffu, v, 16);
    v += __shfl_xor_sync(0xffffffffu, v, 8);
    v += __shfl_xor_sync(0xffffffffu, v, 4);
    v += __shfl_xor_sync(0xffffffffu, v, 2);
    v += __shfl_xor_sync(0xffffffffu, v, 1);
    return v;
}

__device__ __forceinline__ void atomicMaxF(float* addr, float v) {
    int* ia = (int*)addr;
    int old = __float_as_int(*addr);
    while (__int_as_float(old) < v) {
        int prev = atomicCAS(ia, old, __float_as_int(v));
        if (prev == old) break;
        old = prev;
    }
}

__device__ __forceinline__ uint32_t packhi(float f0, float f1) {
    __nv_bfloat162 h = __floats2bfloat162_rn(f0, f1);
    return *(uint32_t*)&h;
}
__device__ __forceinline__ uint32_t packlo(float f0, float f1, uint32_t hi) {
    __nv_bfloat162 h = *(__nv_bfloat162*)&hi;
    float l0 = f0 - __bfloat162float(h.x);
    float l1 = f1 - __bfloat162float(h.y);
    __nv_bfloat162 l = __floats2bfloat162_rn(l0, l1);
    return *(uint32_t*)&l;
}

__device__ __forceinline__ void mma16(float* c, const uint32_t* a, uint32_t b0, uint32_t b1) {
    asm volatile("mma.sync.aligned.m16n8k16.row.col.f32.bf16.bf16.f32 "
        "{%0,%1,%2,%3}, {%4,%5,%6,%7}, {%8,%9}, {%0,%1,%2,%3};"
        : "+f"(c[0]), "+f"(c[1]), "+f"(c[2]), "+f"(c[3])
        : "r"(a[0]), "r"(a[1]), "r"(a[2]), "r"(a[3]), "r"(b0), "r"(b1));
}

__device__ __forceinline__ void ldsm4(uint32_t* r, uint32_t addr) {
    asm volatile("ldmatrix.sync.aligned.m8n8.x4.shared.b16 {%0,%1,%2,%3}, [%4];"
        : "=r"(r[0]), "=r"(r[1]), "=r"(r[2]), "=r"(r[3]) : "r"(addr));
}

__device__ __forceinline__ void cpa16(uint32_t dst, const void* src) {
    asm volatile("cp.async.cg.shared.global [%0], [%1], 16;" :: "r"(dst), "l"(src) : "memory");
}
#define CP_COMMIT() asm volatile("cp.async.commit_group;" ::: "memory")
#define CP_WAIT0()  asm volatile("cp.async.wait_group 0;" ::: "memory")

// ---------------- init ----------------
__global__ void k_init() {
    int i = blockIdx.x * 256 + threadIdx.x;
    if (i < NN * DE) g_nodefeat[i] = 0.f;
    if (i < NN) { g_nmax[i] = -1e30f; g_nsum[i] = 0.f; }
    if (i < NG * DE) g_graphfeat[i] = 0.f;
    if (i < NG) { g_gmax[i] = -1e30f; g_gsum[i] = 0.f; }
}

// ---------------- one-time splits: x, attr ----------------
__global__ void k_xsplit(const float* __restrict__ x, const float* __restrict__ attr) {
    int i = blockIdx.x * 256 + threadIdx.x;
    if (i < NN * 64) {
        float f0 = x[2 * i], f1 = x[2 * i + 1];
        uint32_t h = packhi(f0, f1);
        g_xh[i] = h; g_xl[i] = packlo(f0, f1, h);
    }
    if (i < NE * 8) {
        float f0 = attr[2 * i], f1 = attr[2 * i + 1];
        uint32_t h = packhi(f0, f1);
        g_ath[i] = h; g_atl[i] = packlo(f0, f1, h);
    }
}

// ---------------- one-time weight bf16 hi/lo split (transposed [n][kp]) ----------------
__global__ void k_wsplit(const float* __restrict__ W1, const float* __restrict__ W2) {
    int i = blockIdx.x * 256 + threadIdx.x;
    if (i < 256 * 264) {
        int n = i / 264, kp = i % 264;
        float f0 = W1[(2 * kp) * 256 + n], f1 = W1[(2 * kp + 1) * 256 + n];
        uint32_t h = packhi(f0, f1);
        g_w1h[i] = h; g_w1l[i] = packlo(f0, f1, h);
    }
    if (i < 128 * 128) {
        int n = i >> 7, kp = i & 127;
        float f0 = W2[(2 * kp) * 128 + n], f1 = W2[(2 * kp + 1) * 128 + n];
        uint32_t h = packhi(f0, f1);
        g_w2h[i] = h; g_w2l[i] = packlo(f0, f1, h);
    }
}

// ---------------- per-node scalar projections ----------------
__global__ void k_nodeproj(const float* __restrict__ x, const float* __restrict__ Wagg,
                           const float* __restrict__ Wupd, const float* __restrict__ Wread) {
    int warp = threadIdx.x >> 5, lane = threadIdx.x & 31;
    int n = blockIdx.x * 8 + warp;
    if (n >= NN) return;
    float4 xv = ((const float4*)x)[n * 32 + lane];
    const float4* wa = (const float4*)Wagg;
    const float4* wu = (const float4*)Wupd;
    const float4* wr = (const float4*)Wread;
    float s0 = dot4(xv, wa[lane]);
    float s1 = dot4(xv, wa[32 + lane]);
    float s2 = dot4(xv, wu[lane]);
    float s3 = dot4(xv, wu[32 + lane]);
    float s4 = dot4(xv, wr[lane]);
    float s5 = dot4(xv, wr[32 + lane]);
    s0 = wred(s0); s1 = wred(s1); s2 = wred(s2);
    s3 = wred(s3); s4 = wred(s4); s5 = wred(s5);
    if (lane == 0) {
        g_nproj[n * 8 + 0] = s0; g_nproj[n * 8 + 1] = s1;
        g_nproj[n * 8 + 2] = s2; g_nproj[n * 8 + 3] = s3;
        g_nproj[n * 8 + 4] = s4; g_nproj[n * 8 + 5] = s5;
    }
}

// ---------------- agg logits + segment max + attr projections ----------------
__global__ void k_agglogit(const float* __restrict__ hef, const float* __restrict__ attr,
                           const int* __restrict__ ei, const float* __restrict__ Wagg,
                           const float* __restrict__ bagg, const float* __restrict__ Wupd,
                           const float* __restrict__ Wread) {
    int warp = threadIdx.x >> 5, lane = threadIdx.x & 31;
    int e = blockIdx.x * 8 + warp;
    if (e >= NE) return;
    int r = ei[e], c = ei[NE + e];
    float4 h4 = ((const float4*)hef)[e * 32 + lane];
    float4 wh = *(const float4*)&Wagg[272 + lane * 4];
    float p = dot4(h4, wh);
    float pu = 0.f, pr = 0.f;
    if (lane < 4) {
        float4 a4 = ((const float4*)attr)[e * 4 + lane];
        p += dot4(a4, *(const float4*)&Wagg[256 + lane * 4]);
        pu = dot4(a4, *(const float4*)&Wupd[256 + lane * 4]);
        pr = dot4(a4, *(const float4*)&Wread[384 + lane * 4]);
    }
    p = wred(p); pu = wred(pu); pr = wred(pr);
    if (lane == 0) {
        float logit = p + g_nproj[r * 8 + 0] + g_nproj[c * 8 + 1] + bagg[0];
        g_logit[e] = logit;
        g_eproj[e * 2 + 0] = pu;
        g_eproj[e * 2 + 1] = pr;
        atomicMaxF(&g_nmax[c], logit);
    }
}

// ---------------- exp + unnormalized scatter + segment sum ----------------
__global__ void k_expscatter(const float* __restrict__ hef, const int* __restrict__ ei) {
    int warp = threadIdx.x >> 5, lane = threadIdx.x & 31;
    int e = blockIdx.x * 8 + warp;
    if (e >= NE) return;
    int c = ei[NE + e];
    float w = expf(g_logit[e] - g_nmax[c]);
    float4 h4 = ((const float4*)hef)[e * 32 + lane];
    float* p = &g_nodefeat[c * 128 + lane * 4];
    asm volatile("red.global.add.v4.f32 [%0], {%1,%2,%3,%4};"
        :: "l"(p), "f"(w * h4.x), "f"(w * h4.y), "f"(w * h4.z), "f"(w * h4.w)
        : "memory");
    if (lane == 0) atomicAdd(&g_nsum[c], w);
}

// ---------------- normalize node_feat + pack hi/lo ----------------
__global__ void k_nnorm() {
    int i = blockIdx.x * 256 + threadIdx.x;
    if (i >= NN * 64) return;
    int n = i >> 6;
    float inv = 1.f / (g_nsum[n] + 1e-16f);
    float f0 = g_nodefeat[2 * i] * inv;
    float f1 = g_nodefeat[2 * i + 1] * inv;
    uint32_t h = packhi(f0, f1);
    g_nfh[i] = h; g_nfl[i] = packlo(f0, f1, h);
}

// ==================== GEMM1 (cp.async staging from pre-split arrays) ====================
#define G1_WORDS 12544

__global__ void __launch_bounds__(256, 2)
k_gemm1(const int* __restrict__ ei, const float* __restrict__ b1) {
    extern __shared__ uint32_t sm_[];
    int* srol = (int*)(sm_ + 12288);
    int* scol = srol + 128;

    int t = threadIdx.x;
    int me0 = blockIdx.x * 128, hn0 = blockIdx.y * 128;
    if (t < 128) srol[t] = ei[me0 + t];
    else scol[t - 128] = ei[NE + me0 + t - 128];
    __syncthreads();

    int am = t >> 1, sw = (t & 1) * 4;
    int lane = t & 31, w = t >> 5;
    int wm = (w & 3) * 32, wn = (w >> 2) * 64;
    int grp = lane >> 2, quad = lane & 3;

    uint32_t smb = (uint32_t)__cvta_generic_to_shared(sm_);
    int arow = wm + (lane & 15);
    uint32_t rA = smb + arow * (ST * 4) + ((lane & 16) ? 16 : 0);
    int brow = wn + (lane & 7) + ((lane & 16) ? 8 : 0);
    uint32_t rB = smb + 6144 * 4 + brow * (ST * 4) + ((lane & 8) ? 16 : 0);
    const uint32_t BUFB = 1536 * 4;   // bytes per buffer
    const uint32_t LOFF = 3072 * 4;   // H -> L region offset
    const uint32_t BOFF = 6144 * 4;   // A -> B region offset

    // cp.async stage of one k-tile: 4x 16B per thread, no data through registers
    auto stage = [&](int kt, int buf) {
        int kp = kt * 8 + sw;
        const uint32_t *ph, *pl;
        if (kp < 64)       { size_t o = (size_t)srol[am] * 64 + kp;        ph = g_xh + o;  pl = g_xl + o; }
        else if (kp < 128) { size_t o = (size_t)srol[am] * 64 + kp - 64;   ph = g_nfh + o; pl = g_nfl + o; }
        else if (kp < 192) { size_t o = (size_t)scol[am] * 64 + kp - 128;  ph = g_xh + o;  pl = g_xl + o; }
        else if (kp < 256) { size_t o = (size_t)scol[am] * 64 + kp - 192;  ph = g_nfh + o; pl = g_nfl + o; }
        else               { size_t o = (size_t)(me0 + am) * 8 + kp - 256; ph = g_ath + o; pl = g_atl + o; }
        uint32_t d = smb + (buf * 1536 + am * ST + sw) * 4;
        cpa16(d, ph);
        cpa16(d + LOFF, pl);
        size_t bo = (size_t)(hn0 + am) * 264 + kp;
        cpa16(d + BOFF, g_w1h + bo);
        cpa16(d + BOFF + LOFF, g_w1l + bo);
    };

    stage(0, 0);
    CP_COMMIT();
    CP_WAIT0();
    __syncthreads();

    float acc[2][8][4];
#pragma unroll
    for (int i = 0; i < 2; i++)
#pragma unroll
        for (int j = 0; j < 8; j++)
#pragma unroll
            for (int k = 0; k < 4; k++) acc[i][j][k] = 0.f;

    const int KT = K1TOT / 16;  // 33
    for (int kt = 0; kt < KT; ++kt) {
        int cur = kt & 1;
        if (kt < KT - 1) {
            stage(kt + 1, cur ^ 1);
            CP_COMMIT();
        }
        uint32_t aH[2][4], aL[2][4];
#pragma unroll
        for (int mf = 0; mf < 2; mf++) {
            uint32_t ad = rA + cur * BUFB + mf * (16 * ST * 4);
            ldsm4(aH[mf], ad);
            ldsm4(aL[mf], ad + LOFF);
        }
#pragma unroll
        for (int j = 0; j < 4; j++) {
            uint32_t bH[4], bL[4];
            uint32_t bd = rB + cur * BUFB + j * (16 * ST * 4);
            ldsm4(bH, bd);
            ldsm4(bL, bd + LOFF);
#pragma unroll
            for (int mf = 0; mf < 2; mf++) {
                mma16(acc[mf][2 * j],     aH[mf], bH[0], bH[1]);
                mma16(acc[mf][2 * j],     aH[mf], bL[0], bL[1]);
                mma16(acc[mf][2 * j],     aL[mf], bH[0], bH[1]);
                mma16(acc[mf][2 * j + 1], aH[mf], bH[2], bH[3]);
                mma16(acc[mf][2 * j + 1], aH[mf], bL[2], bL[3]);
                mma16(acc[mf][2 * j + 1], aL[mf], bH[2], bH[3]);
            }
        }
        if (kt < KT - 1) CP_WAIT0();
        __syncthreads();
    }

#pragma unroll
    for (int mf = 0; mf < 2; mf++) {
        int m = me0 + wm + mf * 16 + grp;
#pragma unroll
        for (int nf = 0; nf < 8; nf++) {
            int c0 = hn0 + wn + nf * 8 + quad * 2;
            float bb0 = b1[c0], bb1 = b1[c0 + 1];
            int kp = c0 >> 1;
            float v0 = fmaxf(acc[mf][nf][0] + bb0, 0.f);
            float v1 = fmaxf(acc[mf][nf][1] + bb1, 0.f);
            uint32_t h = packhi(v0, v1);
            g_hh[(size_t)m * 128 + kp] = h;
            g_hl[(size_t)m * 128 + kp] = packlo(v0, v1, h);
            float v2 = fmaxf(acc[mf][nf][2] + bb0, 0.f);
            float v3 = fmaxf(acc[mf][nf][3] + bb1, 0.f);
            h = packhi(v2, v3);
            g_hh[(size_t)(m + 8) * 128 + kp] = h;
            g_hl[(size_t)(m + 8) * 128 + kp] = packlo(v2, v3, h);
        }
    }
}

// ==================== GEMM2 fused (cp.async staging): cand -> gate -> ef -> readout ====================
#define G2_WORDS 12928

__global__ void __launch_bounds__(256, 2)
k_gemm2f(const float* __restrict__ hef, const int* __restrict__ ei,
         const int* __restrict__ batch, const float* __restrict__ b2,
         const float* __restrict__ Wupd, const float* __restrict__ bupd,
         const float* __restrict__ Wread, const float* __restrict__ bread,
         float* __restrict__ out) {
    extern __shared__ uint32_t sm_[];
    int*   srol = (int*)(sm_ + 12288);
    int*   scol = (int*)(sm_ + 12416);
    float* sred = (float*)(sm_ + 12544);
    float* sg   = (float*)(sm_ + 12800);

    int t = threadIdx.x;
    int me0 = blockIdx.x * 128;
    if (t < 128) srol[t] = ei[me0 + t];
    else scol[t - 128] = ei[NE + me0 + t - 128];

    int am = t >> 1, sw = (t & 1) * 4;
    int lane = t & 31, w = t >> 5;
    int wm = (w & 3) * 32, wn = (w >> 2) * 64;
    int grp = lane >> 2, quad = lane & 3;

    uint32_t smb = (uint32_t)__cvta_generic_to_shared(sm_);
    int arow = wm + (lane & 15);
    uint32_t rA = smb + arow * (ST * 4) + ((lane & 16) ? 16 : 0);
    int brow = wn + (lane & 7) + ((lane & 16) ? 8 : 0);
    uint32_t rB = smb + 6144 * 4 + brow * (ST * 4) + ((lane & 8) ? 16 : 0);
    const uint32_t BUFB = 1536 * 4;
    const uint32_t LOFF = 3072 * 4;
    const uint32_t BOFF = 6144 * 4;

    auto stage = [&](int kt, int buf) {
        int kp = kt * 8 + sw;
        size_t ao = (size_t)(me0 + am) * 128 + kp;
        size_t bo = (size_t)am * 128 + kp;
        uint32_t d = smb + (buf * 1536 + am * ST + sw) * 4;
        cpa16(d, g_hh + ao);
        cpa16(d + LOFF, g_hl + ao);
        cpa16(d + BOFF, g_w2h + bo);
        cpa16(d + BOFF + LOFF, g_w2l + bo);
    };

    stage(0, 0);
    CP_COMMIT();
    CP_WAIT0();
    __syncthreads();

    float acc[2][8][4];
#pragma unroll
    for (int i = 0; i < 2; i++)
#pragma unroll
        for (int j = 0; j < 8; j++)
#pragma unroll
            for (int k = 0; k < 4; k++) acc[i][j][k] = 0.f;

    const int KT = NH / 16;  // 16
    for (int kt = 0; kt < KT; ++kt) {
        int cur = kt & 1;
        if (kt < KT - 1) {
            stage(kt + 1, cur ^ 1);
            CP_COMMIT();
        }
        uint32_t aH[2][4], aL[2][4];
#pragma unroll
        for (int mf = 0; mf < 2; mf++) {
            uint32_t ad = rA + cur * BUFB + mf * (16 * ST * 4);
            ldsm4(aH[mf], ad);
            ldsm4(aL[mf], ad + LOFF);
        }
#pragma unroll
        for (int j = 0; j < 4; j++) {
            uint32_t bH[4], bL[4];
            uint32_t bd = rB + cur * BUFB + j * (16 * ST * 4);
            ldsm4(bH, bd);
            ldsm4(bL, bd + LOFF);
#pragma unroll
            for (int mf = 0; mf < 2; mf++) {
                mma16(acc[mf][2 * j],     aH[mf], bH[0], bH[1]);
                mma16(acc[mf][2 * j],     aH[mf], bL[0], bL[1]);
                mma16(acc[mf][2 * j],     aL[mf], bH[0], bH[1]);
                mma16(acc[mf][2 * j + 1], aH[mf], bH[2], bH[3]);
                mma16(acc[mf][2 * j + 1], aH[mf], bL[2], bL[3]);
                mma16(acc[mf][2 * j + 1], aL[mf], bH[2], bH[3]);
            }
        }
        if (kt < KT - 1) CP_WAIT0();
        __syncthreads();
    }

#pragma unroll
    for (int mf = 0; mf < 2; mf++)
#pragma unroll
        for (int nf = 0; nf < 8; nf++) {
            int c0 = wn + nf * 8 + quad * 2;
            float bb0 = b2[c0], bb1 = b2[c0 + 1];
            acc[mf][nf][0] += bb0; acc[mf][nf][1] += bb1;
            acc[mf][nf][2] += bb0; acc[mf][nf][3] += bb1;
        }

    // ---- epilogue pass 1: gate logit dot ----
    float s0 = 0.f, s1 = 0.f, s2 = 0.f, s3 = 0.f;
#pragma unroll
    for (int mf = 0; mf < 2; mf++) {
        int r0 = wm + mf * 16 + grp;
#pragma unroll
        for (int nf = 0; nf < 8; nf++) {
            int c = wn + nf * 8 + quad * 2;
            float2 wc = *(const float2*)&Wupd[400 + c];
            float2 whv = *(const float2*)&Wupd[272 + c];
            float2 h0 = *(const float2*)&hef[(size_t)(me0 + r0) * 128 + c];
            float2 h1 = *(const float2*)&hef[(size_t)(me0 + r0 + 8) * 128 + c];
            float p0 = acc[mf][nf][0] * wc.x + acc[mf][nf][1] * wc.y + h0.x * whv.x + h0.y * whv.y;
            float p1 = acc[mf][nf][2] * wc.x + acc[mf][nf][3] * wc.y + h1.x * whv.x + h1.y * whv.y;
            if (mf == 0) { s0 += p0; s1 += p1; } else { s2 += p0; s3 += p1; }
        }
    }
    s0 += __shfl_xor_sync(0xffffffffu, s0, 1); s0 += __shfl_xor_sync(0xffffffffu, s0, 2);
    s1 += __shfl_xor_sync(0xffffffffu, s1, 1); s1 += __shfl_xor_sync(0xffffffffu, s1, 2);
    s2 += __shfl_xor_sync(0xffffffffu, s2, 1); s2 += __shfl_xor_sync(0xffffffffu, s2, 2);
    s3 += __shfl_xor_sync(0xffffffffu, s3, 1); s3 += __shfl_xor_sync(0xffffffffu, s3, 2);
    if (quad == 0) {
        int nh = w >> 2;
        sred[(wm + grp) * 2 + nh] = s0;
        sred[(wm + 8 + grp) * 2 + nh] = s1;
        sred[(wm + 16 + grp) * 2 + nh] = s2;
        sred[(wm + 24 + grp) * 2 + nh] = s3;
    }
    __syncthreads();
    if (t < 128) {
        int e = me0 + t, r = srol[t], c = scol[t];
        float tot = sred[t * 2] + sred[t * 2 + 1];
        float gv = tot + g_eproj[e * 2] + g_nproj[r * 8 + 2] + g_nproj[c * 8 + 3] + bupd[0];
        sg[t] = 1.f / (1.f + expf(-gv));
    }
    __syncthreads();

    // ---- epilogue pass 2: ef = g*cand + (1-g)*hef, write out, readout dot ----
    s0 = s1 = s2 = s3 = 0.f;
#pragma unroll
    for (int mf = 0; mf < 2; mf++) {
        int r0 = wm + mf * 16 + grp;
        float g0 = sg[r0], g1 = sg[r0 + 8];
#pragma unroll
        for (int nf = 0; nf < 8; nf++) {
            int c = wn + nf * 8 + quad * 2;
            float2 h0 = *(const float2*)&hef[(size_t)(me0 + r0) * 128 + c];
            float2 h1 = *(const float2*)&hef[(size_t)(me0 + r0 + 8) * 128 + c];
            float2 e0, e1;
            e0.x = fmaf(g0, acc[mf][nf][0] - h0.x, h0.x);
            e0.y = fmaf(g0, acc[mf][nf][1] - h0.y, h0.y);
            e1.x = fmaf(g1, acc[mf][nf][2] - h1.x, h1.x);
            e1.y = fmaf(g1, acc[mf][nf][3] - h1.y, h1.y);
            *(float2*)&out[(size_t)(me0 + r0) * 128 + c] = e0;
            *(float2*)&out[(size_t)(me0 + r0 + 8) * 128 + c] = e1;
            float2 wr = *(const float2*)&Wread[256 + c];
            float p0 = e0.x * wr.x + e0.y * wr.y;
            float p1 = e1.x * wr.x + e1.y * wr.y;
            if (mf == 0) { s0 += p0; s1 += p1; } else { s2 += p0; s3 += p1; }
        }
    }
    s0 += __shfl_xor_sync(0xffffffffu, s0, 1); s0 += __shfl_xor_sync(0xffffffffu, s0, 2);
    s1 += __shfl_xor_sync(0xffffffffu, s1, 1); s1 += __shfl_xor_sync(0xffffffffu, s1, 2);
    s2 += __shfl_xor_sync(0xffffffffu, s2, 1); s2 += __shfl_xor_sync(0xffffffffu, s2, 2);
    s3 += __shfl_xor_sync(0xffffffffu, s3, 1); s3 += __shfl_xor_sync(0xffffffffu, s3, 2);
    if (quad == 0) {
        int nh = w >> 2;
        sred[(wm + grp) * 2 + nh] = s0;
        sred[(wm + 8 + grp) * 2 + nh] = s1;
        sred[(wm + 16 + grp) * 2 + nh] = s2;
        sred[(wm + 24 + grp) * 2 + nh] = s3;
    }
    __syncthreads();
    if (t < 128) {
        int e = me0 + t, r = srol[t], c = scol[t];
        float tot = sred[t * 2] + sred[t * 2 + 1];
        float rl = tot + g_eproj[e * 2 + 1] + g_nproj[r * 8 + 4] + g_nproj[c * 8 + 5] + bread[0];
        g_rlogit[e] = rl;
        atomicMaxF(&g_gmax[batch[r]], rl);
    }
}

// ---------------- readout: exp + unnormalized scatter + segment sum (merged) ----------------
__global__ void k_rscatter(const int* __restrict__ ei, const int* __restrict__ batch,
                           const float* __restrict__ out) {
    __shared__ float sacc[NG * DE];   // 32 KB
    __shared__ float ssum[NG];
    int t = threadIdx.x;
    for (int i = t; i < NG * DE; i += 256) sacc[i] = 0.f;
    if (t < NG) ssum[t] = 0.f;
    __syncthreads();
    int warp = t >> 5, lane = t & 31;
    for (int e = blockIdx.x * 8 + warp; e < NE; e += gridDim.x * 8) {
        int gi = batch[ei[e]];
        float rw = expf(g_rlogit[e] - g_gmax[gi]);
        float4 ef = ((const float4*)out)[e * 32 + lane];
        float* p = &sacc[gi * 128 + lane * 4];
        atomicAdd(p + 0, rw * ef.x);
        atomicAdd(p + 1, rw * ef.y);
        atomicAdd(p + 2, rw * ef.z);
        atomicAdd(p + 3, rw * ef.w);
        if (lane == 0) atomicAdd(&ssum[gi], rw);
    }
    __syncthreads();
    for (int i = t; i < NG * DE; i += 256)
        if (sacc[i] != 0.f) atomicAdd(&g_graphfeat[i], sacc[i]);
    if (t < NG && ssum[t] != 0.f) atomicAdd(&g_gsum[t], ssum[t]);
}

// ---------------- confidence (normalize here) ----------------
__global__ void k_conf(const float* __restrict__ Wscore, const float* __restrict__ bscore,
                       float* __restrict__ out) {
    int g = blockIdx.x, t = threadIdx.x;
    float v = g_graphfeat[g * 128 + t] / (g_gsum[g] + 1e-16f) * Wscore[t];
    v = wred(v);
    __shared__ float sm[4];
    if ((t & 31) == 0) sm[t >> 5] = v;
    __syncthreads();
    if (t == 0) {
        float s = sm[0] + sm[1] + sm[2] + sm[3] + bscore[0];
        out[(size_t)NE * DE + g] = 1.f / (1.f + expf(-s));
    }
}

// ---------------- launch ----------------
extern "C" void kernel_launch(void* const* d_in, const int* in_sizes, int n_in,
                              void* d_out, int out_size) {
    const float* x      = (const float*)d_in[0];
    const float* hef    = (const float*)d_in[1];
    const float* attr   = (const float*)d_in[2];
    const int*   ei     = (const int*)d_in[3];
    const int*   batch  = (const int*)d_in[4];
    const float* Wagg   = (const float*)d_in[6];
    const float* bagg   = (const float*)d_in[7];
    const float* W1     = (const float*)d_in[8];
    const float* b1     = (const float*)d_in[9];
    const float* W2     = (const float*)d_in[10];
    const float* b2     = (const float*)d_in[11];
    const float* Wupd   = (const float*)d_in[12];
    const float* bupd   = (const float*)d_in[13];
    const float* Wread  = (const float*)d_in[14];
    const float* bread  = (const float*)d_in[15];
    const float* Wscore = (const float*)d_in[16];
    const float* bscore = (const float*)d_in[17];
    float* out = (float*)d_out;

    static bool attr_set = false;
    if (!attr_set) {
        cudaFuncSetAttribute(k_gemm1, cudaFuncAttributeMaxDynamicSharedMemorySize, G1_WORDS * 4);
        cudaFuncSetAttribute(k_gemm2f, cudaFuncAttributeMaxDynamicSharedMemorySize, G2_WORDS * 4);
        attr_set = true;
    }

    k_init<<<(NN * DE + 255) / 256, 256>>>();
    k_xsplit<<<(NE * 8 + 255) / 256, 256>>>(x, attr);
    k_wsplit<<<(256 * 264 + 255) / 256, 256>>>(W1, W2);
    k_nodeproj<<<(NN + 7) / 8, 256>>>(x, Wagg, Wupd, Wread);
    k_agglogit<<<NE / 8, 256>>>(hef, attr, ei, Wagg, bagg, Wupd, Wread);
    k_expscatter<<<NE / 8, 256>>>(hef, ei);
    k_nnorm<<<(NN * 64 + 255) / 256, 256>>>();
    k_gemm1<<<dim3(NE / 128, 2), 256, G1_WORDS * 4>>>(ei, b1);
    k_gemm2f<<<NE / 128, 256, G2_WORDS * 4>>>(hef, ei, batch, b2, Wupd, bupd,
                                              Wread, bread, out);
    k_rscatter<<<296, 256>>>(ei, batch, out);
    k_conf<<<NG, 128>>>(Wscore, bscore, out);
}

// round 10
// speedup vs baseline: 1.9733x; 1.2695x over previous
#include <cuda_runtime.h>
#include <cuda_fp16.h>
#include <stdint.h>

#define NN 20000
#define NE 320000
#define DN 128
#define DE 128
#define DA 16
#define NH 256
#define NG 64
#define K1TOT 528
#define ST 12              // smem row stride in u32 words (8 used + 4 pad)

// ---------------- scratch ----------------
__device__ float g_nproj[NN * 8];
__device__ float g_eproj[NE * 2];
__device__ float g_logit[NE];
__device__ float g_nmax[NN];
__device__ float g_nsum[NN];
__device__ float g_nodefeat[NN * DE];
__device__ uint32_t g_xh[NN * 64];                        // x fp16x2 [n][kpair]
__device__ uint32_t g_nfh[NN * 64];                       // node_feat fp16x2
__device__ uint32_t g_ath[NE * 8];                        // attr fp16x2
__device__ uint32_t g_w1h[256 * 264], g_w1l[256 * 264];   // W1 fp16 hi/lo, [n][kpair]
__device__ uint32_t g_w2h[128 * 128], g_w2l[128 * 128];   // W2 fp16 hi/lo, [n][kpair]
__device__ uint32_t g_hh[40960000];                       // hidden fp16x2 [m][kpair]
__device__ float g_rlogit[NE];
__device__ float g_gmax[NG];
__device__ float g_gsum[NG];
__device__ float g_graphfeat[NG * DE];

// ---------------- helpers ----------------
__device__ __forceinline__ float dot4(float4 a, float4 b) {
    return fmaf(a.x, b.x, fmaf(a.y, b.y, fmaf(a.z, b.z, a.w * b.w)));
}

__device__ __forceinline__ float wred(float v) {
    v += __shfl_xor_sync(0xffffffffu, v, 16);
    v += __shfl_xor_sync(0xffffffffu, v, 8);
    v += __shfl_xor_sync(0xffffffffu, v, 4);
    v += __shfl_xor_sync(0xffffffffu, v, 2);
    v += __shfl_xor_sync(0xffffffffu, v, 1);
    return v;
}

__device__ __forceinline__ void atomicMaxF(float* addr, float v) {
    int* ia = (int*)addr;
    int old = __float_as_int(*addr);
    while (__int_as_float(old) < v) {
        int prev = atomicCAS(ia, old, __float_as_int(v));
        if (prev == old) break;
        old = prev;
    }
}

__device__ __forceinline__ uint32_t packhi16(float f0, float f1) {
    __half2 h = __floats2half2_rn(f0, f1);
    return *(uint32_t*)&h;
}
__device__ __forceinline__ uint32_t packlo16(float f0, float f1, uint32_t hi) {
    __half2 h = *(__half2*)&hi;
    __half2 l = __floats2half2_rn(f0 - __half2float(h.x), f1 - __half2float(h.y));
    return *(uint32_t*)&l;
}

__device__ __forceinline__ void mma16f(float* c, const uint32_t* a, uint32_t b0, uint32_t b1) {
    asm volatile("mma.sync.aligned.m16n8k16.row.col.f32.f16.f16.f32 "
        "{%0,%1,%2,%3}, {%4,%5,%6,%7}, {%8,%9}, {%0,%1,%2,%3};"
        : "+f"(c[0]), "+f"(c[1]), "+f"(c[2]), "+f"(c[3])
        : "r"(a[0]), "r"(a[1]), "r"(a[2]), "r"(a[3]), "r"(b0), "r"(b1));
}

__device__ __forceinline__ void ldsm4(uint32_t* r, uint32_t addr) {
    asm volatile("ldmatrix.sync.aligned.m8n8.x4.shared.b16 {%0,%1,%2,%3}, [%4];"
        : "=r"(r[0]), "=r"(r[1]), "=r"(r[2]), "=r"(r[3]) : "r"(addr));
}

__device__ __forceinline__ void cpa16(uint32_t dst, const void* src) {
    asm volatile("cp.async.cg.shared.global [%0], [%1], 16;" :: "r"(dst), "l"(src) : "memory");
}
#define CP_COMMIT() asm volatile("cp.async.commit_group;" ::: "memory")
#define CP_WAIT0()  asm volatile("cp.async.wait_group 0;" ::: "memory")

// ---------------- init ----------------
__global__ void k_init() {
    int i = blockIdx.x * 256 + threadIdx.x;
    if (i < NN * DE) g_nodefeat[i] = 0.f;
    if (i < NN) { g_nmax[i] = -1e30f; g_nsum[i] = 0.f; }
    if (i < NG * DE) g_graphfeat[i] = 0.f;
    if (i < NG) { g_gmax[i] = -1e30f; g_gsum[i] = 0.f; }
}

// ---------------- one-time splits: x, attr (fp16 hi only) ----------------
__global__ void k_xsplit(const float* __restrict__ x, const float* __restrict__ attr) {
    int i = blockIdx.x * 256 + threadIdx.x;
    if (i < NN * 64)
        g_xh[i] = packhi16(x[2 * i], x[2 * i + 1]);
    if (i < NE * 8)
        g_ath[i] = packhi16(attr[2 * i], attr[2 * i + 1]);
}

// ---------------- one-time weight fp16 hi/lo split (transposed [n][kp]) ----------------
__global__ void k_wsplit(const float* __restrict__ W1, const float* __restrict__ W2) {
    int i = blockIdx.x * 256 + threadIdx.x;
    if (i < 256 * 264) {
        int n = i / 264, kp = i % 264;
        float f0 = W1[(2 * kp) * 256 + n], f1 = W1[(2 * kp + 1) * 256 + n];
        uint32_t h = packhi16(f0, f1);
        g_w1h[i] = h; g_w1l[i] = packlo16(f0, f1, h);
    }
    if (i < 128 * 128) {
        int n = i >> 7, kp = i & 127;
        float f0 = W2[(2 * kp) * 128 + n], f1 = W2[(2 * kp + 1) * 128 + n];
        uint32_t h = packhi16(f0, f1);
        g_w2h[i] = h; g_w2l[i] = packlo16(f0, f1, h);
    }
}

// ---------------- per-node scalar projections ----------------
__global__ void k_nodeproj(const float* __restrict__ x, const float* __restrict__ Wagg,
                           const float* __restrict__ Wupd, const float* __restrict__ Wread) {
    int warp = threadIdx.x >> 5, lane = threadIdx.x & 31;
    int n = blockIdx.x * 8 + warp;
    if (n >= NN) return;
    float4 xv = ((const float4*)x)[n * 32 + lane];
    const float4* wa = (const float4*)Wagg;
    const float4* wu = (const float4*)Wupd;
    const float4* wr = (const float4*)Wread;
    float s0 = dot4(xv, wa[lane]);
    float s1 = dot4(xv, wa[32 + lane]);
    float s2 = dot4(xv, wu[lane]);
    float s3 = dot4(xv, wu[32 + lane]);
    float s4 = dot4(xv, wr[lane]);
    float s5 = dot4(xv, wr[32 + lane]);
    s0 = wred(s0); s1 = wred(s1); s2 = wred(s2);
    s3 = wred(s3); s4 = wred(s4); s5 = wred(s5);
    if (lane == 0) {
        g_nproj[n * 8 + 0] = s0; g_nproj[n * 8 + 1] = s1;
        g_nproj[n * 8 + 2] = s2; g_nproj[n * 8 + 3] = s3;
        g_nproj[n * 8 + 4] = s4; g_nproj[n * 8 + 5] = s5;
    }
}

// ---------------- agg logits + segment max + attr projections ----------------
__global__ void k_agglogit(const float* __restrict__ hef, const float* __restrict__ attr,
                           const int* __restrict__ ei, const float* __restrict__ Wagg,
                           const float* __restrict__ bagg, const float* __restrict__ Wupd,
                           const float* __restrict__ Wread) {
    int warp = threadIdx.x >> 5, lane = threadIdx.x & 31;
    int e = blockIdx.x * 8 + warp;
    if (e >= NE) return;
    int r = ei[e], c = ei[NE + e];
    float4 h4 = ((const float4*)hef)[e * 32 + lane];
    float4 wh = *(const float4*)&Wagg[272 + lane * 4];
    float p = dot4(h4, wh);
    float pu = 0.f, pr = 0.f;
    if (lane < 4) {
        float4 a4 = ((const float4*)attr)[e * 4 + lane];
        p += dot4(a4, *(const float4*)&Wagg[256 + lane * 4]);
        pu = dot4(a4, *(const float4*)&Wupd[256 + lane * 4]);
        pr = dot4(a4, *(const float4*)&Wread[384 + lane * 4]);
    }
    p = wred(p); pu = wred(pu); pr = wred(pr);
    if (lane == 0) {
        float logit = p + g_nproj[r * 8 + 0] + g_nproj[c * 8 + 1] + bagg[0];
        g_logit[e] = logit;
        g_eproj[e * 2 + 0] = pu;
        g_eproj[e * 2 + 1] = pr;
        atomicMaxF(&g_nmax[c], logit);
    }
}

// ---------------- exp + unnormalized scatter + segment sum ----------------
__global__ void k_expscatter(const float* __restrict__ hef, const int* __restrict__ ei) {
    int warp = threadIdx.x >> 5, lane = threadIdx.x & 31;
    int e = blockIdx.x * 8 + warp;
    if (e >= NE) return;
    int c = ei[NE + e];
    float w = expf(g_logit[e] - g_nmax[c]);
    float4 h4 = ((const float4*)hef)[e * 32 + lane];
    float* p = &g_nodefeat[c * 128 + lane * 4];
    asm volatile("red.global.add.v4.f32 [%0], {%1,%2,%3,%4};"
        :: "l"(p), "f"(w * h4.x), "f"(w * h4.y), "f"(w * h4.z), "f"(w * h4.w)
        : "memory");
    if (lane == 0) atomicAdd(&g_nsum[c], w);
}

// ---------------- normalize node_feat + pack fp16 ----------------
__global__ void k_nnorm() {
    int i = blockIdx.x * 256 + threadIdx.x;
    if (i >= NN * 64) return;
    int n = i >> 6;
    float inv = 1.f / (g_nsum[n] + 1e-16f);
    g_nfh[i] = packhi16(g_nodefeat[2 * i] * inv, g_nodefeat[2 * i + 1] * inv);
}

// ==================== GEMM1 (fp16 2-term, cp.async staging) ====================
// smem words: A[2][128][ST] @0 (3072), BH @3072, BL @6144, srol @9216, scol @9344
#define G1_WORDS 9472

__global__ void __launch_bounds__(256, 2)
k_gemm1(const int* __restrict__ ei, const float* __restrict__ b1) {
    extern __shared__ uint32_t sm_[];
    int* srol = (int*)(sm_ + 9216);
    int* scol = srol + 128;

    int t = threadIdx.x;
    int me0 = blockIdx.x * 128, hn0 = blockIdx.y * 128;
    if (t < 128) srol[t] = ei[me0 + t];
    else scol[t - 128] = ei[NE + me0 + t - 128];
    __syncthreads();

    int am = t >> 1, sw = (t & 1) * 4;
    int lane = t & 31, w = t >> 5;
    int wm = (w & 3) * 32, wn = (w >> 2) * 64;
    int grp = lane >> 2, quad = lane & 3;

    uint32_t smb = (uint32_t)__cvta_generic_to_shared(sm_);
    int arow = wm + (lane & 15);
    uint32_t rA = smb + arow * (ST * 4) + ((lane & 16) ? 16 : 0);
    int brow = wn + (lane & 7) + ((lane & 16) ? 8 : 0);
    uint32_t rB = smb + 3072 * 4 + brow * (ST * 4) + ((lane & 8) ? 16 : 0);
    const uint32_t BUFB  = 1536 * 4;   // bytes per buffer within a region
    const uint32_t BHOFF = 3072 * 4;   // A -> BH region offset
    const uint32_t BLOFF = 3072 * 4;   // BH -> BL region offset

    auto stage = [&](int kt, int buf) {
        int kp = kt * 8 + sw;
        const uint32_t* pa;
        if (kp < 64)       pa = g_xh  + (size_t)srol[am] * 64 + kp;
        else if (kp < 128) pa = g_nfh + (size_t)srol[am] * 64 + kp - 64;
        else if (kp < 192) pa = g_xh  + (size_t)scol[am] * 64 + kp - 128;
        else if (kp < 256) pa = g_nfh + (size_t)scol[am] * 64 + kp - 192;
        else               pa = g_ath + (size_t)(me0 + am) * 8 + kp - 256;
        uint32_t d = smb + (buf * 1536 + am * ST + sw) * 4;
        cpa16(d, pa);
        size_t bo = (size_t)(hn0 + am) * 264 + kp;
        cpa16(d + BHOFF, g_w1h + bo);
        cpa16(d + BHOFF + BLOFF, g_w1l + bo);
    };

    stage(0, 0);
    CP_COMMIT();
    CP_WAIT0();
    __syncthreads();

    float acc[2][8][4];
#pragma unroll
    for (int i = 0; i < 2; i++)
#pragma unroll
        for (int j = 0; j < 8; j++)
#pragma unroll
            for (int k = 0; k < 4; k++) acc[i][j][k] = 0.f;

    const int KT = K1TOT / 16;  // 33
    for (int kt = 0; kt < KT; ++kt) {
        int cur = kt & 1;
        if (kt < KT - 1) {
            stage(kt + 1, cur ^ 1);
            CP_COMMIT();
        }
        uint32_t aH[2][4];
#pragma unroll
        for (int mf = 0; mf < 2; mf++)
            ldsm4(aH[mf], rA + cur * BUFB + mf * (16 * ST * 4));
#pragma unroll
        for (int j = 0; j < 4; j++) {
            uint32_t bH[4], bL[4];
            uint32_t bd = rB + cur * BUFB + j * (16 * ST * 4);
            ldsm4(bH, bd);
            ldsm4(bL, bd + BLOFF);
#pragma unroll
            for (int mf = 0; mf < 2; mf++) {
                mma16f(acc[mf][2 * j],     aH[mf], bH[0], bH[1]);
                mma16f(acc[mf][2 * j],     aH[mf], bL[0], bL[1]);
                mma16f(acc[mf][2 * j + 1], aH[mf], bH[2], bH[3]);
                mma16f(acc[mf][2 * j + 1], aH[mf], bL[2], bL[3]);
            }
        }
        if (kt < KT - 1) CP_WAIT0();
        __syncthreads();
    }

    // epilogue: bias + relu, pack fp16, write g_hh only
#pragma unroll
    for (int mf = 0; mf < 2; mf++) {
        int m = me0 + wm + mf * 16 + grp;
#pragma unroll
        for (int nf = 0; nf < 8; nf++) {
            int c0 = hn0 + wn + nf * 8 + quad * 2;
            float bb0 = b1[c0], bb1 = b1[c0 + 1];
            int kp = c0 >> 1;
            float v0 = fmaxf(acc[mf][nf][0] + bb0, 0.f);
            float v1 = fmaxf(acc[mf][nf][1] + bb1, 0.f);
            g_hh[(size_t)m * 128 + kp] = packhi16(v0, v1);
            float v2 = fmaxf(acc[mf][nf][2] + bb0, 0.f);
            float v3 = fmaxf(acc[mf][nf][3] + bb1, 0.f);
            g_hh[(size_t)(m + 8) * 128 + kp] = packhi16(v2, v3);
        }
    }
}

// ==================== GEMM2 fused (fp16 2-term): cand -> gate -> ef -> readout ====================
// smem words: A @0 (3072), BH @3072, BL @6144, srol @9216, scol @9344, sred @9472, sg @9728
#define G2_WORDS 9856

__global__ void __launch_bounds__(256, 2)
k_gemm2f(const float* __restrict__ hef, const int* __restrict__ ei,
         const int* __restrict__ batch, const float* __restrict__ b2,
         const float* __restrict__ Wupd, const float* __restrict__ bupd,
         const float* __restrict__ Wread, const float* __restrict__ bread,
         float* __restrict__ out) {
    extern __shared__ uint32_t sm_[];
    int*   srol = (int*)(sm_ + 9216);
    int*   scol = (int*)(sm_ + 9344);
    float* sred = (float*)(sm_ + 9472);
    float* sg   = (float*)(sm_ + 9728);

    int t = threadIdx.x;
    int me0 = blockIdx.x * 128;
    if (t < 128) srol[t] = ei[me0 + t];
    else scol[t - 128] = ei[NE + me0 + t - 128];

    int am = t >> 1, sw = (t & 1) * 4;
    int lane = t & 31, w = t >> 5;
    int wm = (w & 3) * 32, wn = (w >> 2) * 64;
    int grp = lane >> 2, quad = lane & 3;

    uint32_t smb = (uint32_t)__cvta_generic_to_shared(sm_);
    int arow = wm + (lane & 15);
    uint32_t rA = smb + arow * (ST * 4) + ((lane & 16) ? 16 : 0);
    int brow = wn + (lane & 7) + ((lane & 16) ? 8 : 0);
    uint32_t rB = smb + 3072 * 4 + brow * (ST * 4) + ((lane & 8) ? 16 : 0);
    const uint32_t BUFB  = 1536 * 4;
    const uint32_t BHOFF = 3072 * 4;
    const uint32_t BLOFF = 3072 * 4;

    auto stage = [&](int kt, int buf) {
        int kp = kt * 8 + sw;
        uint32_t d = smb + (buf * 1536 + am * ST + sw) * 4;
        cpa16(d, g_hh + (size_t)(me0 + am) * 128 + kp);
        size_t bo = (size_t)am * 128 + kp;
        cpa16(d + BHOFF, g_w2h + bo);
        cpa16(d + BHOFF + BLOFF, g_w2l + bo);
    };

    stage(0, 0);
    CP_COMMIT();
    CP_WAIT0();
    __syncthreads();

    float acc[2][8][4];
#pragma unroll
    for (int i = 0; i < 2; i++)
#pragma unroll
        for (int j = 0; j < 8; j++)
#pragma unroll
            for (int k = 0; k < 4; k++) acc[i][j][k] = 0.f;

    const int KT = NH / 16;  // 16
    for (int kt = 0; kt < KT; ++kt) {
        int cur = kt & 1;
        if (kt < KT - 1) {
            stage(kt + 1, cur ^ 1);
            CP_COMMIT();
        }
        uint32_t aH[2][4];
#pragma unroll
        for (int mf = 0; mf < 2; mf++)
            ldsm4(aH[mf], rA + cur * BUFB + mf * (16 * ST * 4));
#pragma unroll
        for (int j = 0; j < 4; j++) {
            uint32_t bH[4], bL[4];
            uint32_t bd = rB + cur * BUFB + j * (16 * ST * 4);
            ldsm4(bH, bd);
            ldsm4(bL, bd + BLOFF);
#pragma unroll
            for (int mf = 0; mf < 2; mf++) {
                mma16f(acc[mf][2 * j],     aH[mf], bH[0], bH[1]);
                mma16f(acc[mf][2 * j],     aH[mf], bL[0], bL[1]);
                mma16f(acc[mf][2 * j + 1], aH[mf], bH[2], bH[3]);
                mma16f(acc[mf][2 * j + 1], aH[mf], bL[2], bL[3]);
            }
        }
        if (kt < KT - 1) CP_WAIT0();
        __syncthreads();
    }

    // acc += b2 -> cand
#pragma unroll
    for (int mf = 0; mf < 2; mf++)
#pragma unroll
        for (int nf = 0; nf < 8; nf++) {
            int c0 = wn + nf * 8 + quad * 2;
            float bb0 = b2[c0], bb1 = b2[c0 + 1];
            acc[mf][nf][0] += bb0; acc[mf][nf][1] += bb1;
            acc[mf][nf][2] += bb0; acc[mf][nf][3] += bb1;
        }

    // ---- epilogue pass 1: gate logit dot ----
    float s0 = 0.f, s1 = 0.f, s2 = 0.f, s3 = 0.f;
#pragma unroll
    for (int mf = 0; mf < 2; mf++) {
        int r0 = wm + mf * 16 + grp;
#pragma unroll
        for (int nf = 0; nf < 8; nf++) {
            int c = wn + nf * 8 + quad * 2;
            float2 wc = *(const float2*)&Wupd[400 + c];
            float2 whv = *(const float2*)&Wupd[272 + c];
            float2 h0 = *(const float2*)&hef[(size_t)(me0 + r0) * 128 + c];
            float2 h1 = *(const float2*)&hef[(size_t)(me0 + r0 + 8) * 128 + c];
            float p0 = acc[mf][nf][0] * wc.x + acc[mf][nf][1] * wc.y + h0.x * whv.x + h0.y * whv.y;
            float p1 = acc[mf][nf][2] * wc.x + acc[mf][nf][3] * wc.y + h1.x * whv.x + h1.y * whv.y;
            if (mf == 0) { s0 += p0; s1 += p1; } else { s2 += p0; s3 += p1; }
        }
    }
    s0 += __shfl_xor_sync(0xffffffffu, s0, 1); s0 += __shfl_xor_sync(0xffffffffu, s0, 2);
    s1 += __shfl_xor_sync(0xffffffffu, s1, 1); s1 += __shfl_xor_sync(0xffffffffu, s1, 2);
    s2 += __shfl_xor_sync(0xffffffffu, s2, 1); s2 += __shfl_xor_sync(0xffffffffu, s2, 2);
    s3 += __shfl_xor_sync(0xffffffffu, s3, 1); s3 += __shfl_xor_sync(0xffffffffu, s3, 2);
    if (quad == 0) {
        int nh = w >> 2;
        sred[(wm + grp) * 2 + nh] = s0;
        sred[(wm + 8 + grp) * 2 + nh] = s1;
        sred[(wm + 16 + grp) * 2 + nh] = s2;
        sred[(wm + 24 + grp) * 2 + nh] = s3;
    }
    __syncthreads();
    if (t < 128) {
        int e = me0 + t, r = srol[t], c = scol[t];
        float tot = sred[t * 2] + sred[t * 2 + 1];
        float gv = tot + g_eproj[e * 2] + g_nproj[r * 8 + 2] + g_nproj[c * 8 + 3] + bupd[0];
        sg[t] = 1.f / (1.f + expf(-gv));
    }
    __syncthreads();

    // ---- epilogue pass 2: ef = g*cand + (1-g)*hef, write out, readout dot ----
    s0 = s1 = s2 = s3 = 0.f;
#pragma unroll
    for (int mf = 0; mf < 2; mf++) {
        int r0 = wm + mf * 16 + grp;
        float g0 = sg[r0], g1 = sg[r0 + 8];
#pragma unroll
        for (int nf = 0; nf < 8; nf++) {
            int c = wn + nf * 8 + quad * 2;
            float2 h0 = *(const float2*)&hef[(size_t)(me0 + r0) * 128 + c];
            float2 h1 = *(const float2*)&hef[(size_t)(me0 + r0 + 8) * 128 + c];
            float2 e0, e1;
            e0.x = fmaf(g0, acc[mf][nf][0] - h0.x, h0.x);
            e0.y = fmaf(g0, acc[mf][nf][1] - h0.y, h0.y);
            e1.x = fmaf(g1, acc[mf][nf][2] - h1.x, h1.x);
            e1.y = fmaf(g1, acc[mf][nf][3] - h1.y, h1.y);
            *(float2*)&out[(size_t)(me0 + r0) * 128 + c] = e0;
            *(float2*)&out[(size_t)(me0 + r0 + 8) * 128 + c] = e1;
            float2 wr = *(const float2*)&Wread[256 + c];
            float p0 = e0.x * wr.x + e0.y * wr.y;
            float p1 = e1.x * wr.x + e1.y * wr.y;
            if (mf == 0) { s0 += p0; s1 += p1; } else { s2 += p0; s3 += p1; }
        }
    }
    s0 += __shfl_xor_sync(0xffffffffu, s0, 1); s0 += __shfl_xor_sync(0xffffffffu, s0, 2);
    s1 += __shfl_xor_sync(0xffffffffu, s1, 1); s1 += __shfl_xor_sync(0xffffffffu, s1, 2);
    s2 += __shfl_xor_sync(0xffffffffu, s2, 1); s2 += __shfl_xor_sync(0xffffffffu, s2, 2);
    s3 += __shfl_xor_sync(0xffffffffu, s3, 1); s3 += __shfl_xor_sync(0xffffffffu, s3, 2);
    if (quad == 0) {
        int nh = w >> 2;
        sred[(wm + grp) * 2 + nh] = s0;
        sred[(wm + 8 + grp) * 2 + nh] = s1;
        sred[(wm + 16 + grp) * 2 + nh] = s2;
        sred[(wm + 24 + grp) * 2 + nh] = s3;
    }
    __syncthreads();
    if (t < 128) {
        int e = me0 + t, r = srol[t], c = scol[t];
        float tot = sred[t * 2] + sred[t * 2 + 1];
        float rl = tot + g_eproj[e * 2 + 1] + g_nproj[r * 8 + 4] + g_nproj[c * 8 + 5] + bread[0];
        g_rlogit[e] = rl;
        atomicMaxF(&g_gmax[batch[r]], rl);
    }
}

// ---------------- readout: exp + unnormalized scatter + segment sum (merged) ----------------
__global__ void k_rscatter(const int* __restrict__ ei, const int* __restrict__ batch,
                           const float* __restrict__ out) {
    __shared__ float sacc[NG * DE];   // 32 KB
    __shared__ float ssum[NG];
    int t = threadIdx.x;
    for (int i = t; i < NG * DE; i += 256) sacc[i] = 0.f;
    if (t < NG) ssum[t] = 0.f;
    __syncthreads();
    int warp = t >> 5, lane = t & 31;
    for (int e = blockIdx.x * 8 + warp; e < NE; e += gridDim.x * 8) {
        int gi = batch[ei[e]];
        float rw = expf(g_rlogit[e] - g_gmax[gi]);
        float4 ef = ((const float4*)out)[e * 32 + lane];
        float* p = &sacc[gi * 128 + lane * 4];
        atomicAdd(p + 0, rw * ef.x);
        atomicAdd(p + 1, rw * ef.y);
        atomicAdd(p + 2, rw * ef.z);
        atomicAdd(p + 3, rw * ef.w);
        if (lane == 0) atomicAdd(&ssum[gi], rw);
    }
    __syncthreads();
    for (int i = t; i < NG * DE; i += 256)
        if (sacc[i] != 0.f) atomicAdd(&g_graphfeat[i], sacc[i]);
    if (t < NG && ssum[t] != 0.f) atomicAdd(&g_gsum[t], ssum[t]);
}

// ---------------- confidence (normalize here) ----------------
__global__ void k_conf(const float* __restrict__ Wscore, const float* __restrict__ bscore,
                       float* __restrict__ out) {
    int g = blockIdx.x, t = threadIdx.x;
    float v = g_graphfeat[g * 128 + t] / (g_gsum[g] + 1e-16f) * Wscore[t];
    v = wred(v);
    __shared__ float sm[4];
    if ((t & 31) == 0) sm[t >> 5] = v;
    __syncthreads();
    if (t == 0) {
        float s = sm[0] + sm[1] + sm[2] + sm[3] + bscore[0];
        out[(size_t)NE * DE + g] = 1.f / (1.f + expf(-s));
    }
}

// ---------------- launch ----------------
extern "C" void kernel_launch(void* const* d_in, const int* in_sizes, int n_in,
                              void* d_out, int out_size) {
    const float* x      = (const float*)d_in[0];
    const float* hef    = (const float*)d_in[1];
    const float* attr   = (const float*)d_in[2];
    const int*   ei     = (const int*)d_in[3];
    const int*   batch  = (const int*)d_in[4];
    const float* Wagg   = (const float*)d_in[6];
    const float* bagg   = (const float*)d_in[7];
    const float* W1     = (const float*)d_in[8];
    const float* b1     = (const float*)d_in[9];
    const float* W2     = (const float*)d_in[10];
    const float* b2     = (const float*)d_in[11];
    const float* Wupd   = (const float*)d_in[12];
    const float* bupd   = (const float*)d_in[13];
    const float* Wread  = (const float*)d_in[14];
    const float* bread  = (const float*)d_in[15];
    const float* Wscore = (const float*)d_in[16];
    const float* bscore = (const float*)d_in[17];
    float* out = (float*)d_out;

    static bool attr_set = false;
    if (!attr_set) {
        cudaFuncSetAttribute(k_gemm1, cudaFuncAttributeMaxDynamicSharedMemorySize, G1_WORDS * 4);
        cudaFuncSetAttribute(k_gemm2f, cudaFuncAttributeMaxDynamicSharedMemorySize, G2_WORDS * 4);
        attr_set = true;
    }

    k_init<<<(NN * DE + 255) / 256, 256>>>();
    k_xsplit<<<(NE * 8 + 255) / 256, 256>>>(x, attr);
    k_wsplit<<<(256 * 264 + 255) / 256, 256>>>(W1, W2);
    k_nodeproj<<<(NN + 7) / 8, 256>>>(x, Wagg, Wupd, Wread);
    k_agglogit<<<NE / 8, 256>>>(hef, attr, ei, Wagg, bagg, Wupd, Wread);
    k_expscatter<<<NE / 8, 256>>>(hef, ei);
    k_nnorm<<<(NN * 64 + 255) / 256, 256>>>();
    k_gemm1<<<dim3(NE / 128, 2), 256, G1_WORDS * 4>>>(ei, b1);
    k_gemm2f<<<NE / 128, 256, G2_WORDS * 4>>>(hef, ei, batch, b2, Wupd, bupd,
                                              Wread, bread, out);
    k_rscatter<<<296, 256>>>(ei, batch, out);
    k_conf<<<NG, 128>>>(Wscore, bscore, out);
}

// round 11
// speedup vs baseline: 2.3450x; 1.1884x over previous
#include <cuda_runtime.h>
#include <cuda_fp16.h>
#include <stdint.h>

#define NN 20000
#define NE 320000
#define DN 128
#define DE 128
#define DA 16
#define NH 256
#define NG 64
#define K1TOT 528
#define ST 12              // smem row stride in u32 words (8 used + 4 pad)

// ---------------- scratch ----------------
__device__ float g_nproj[NN * 8];
__device__ float g_eproj[NE * 2];
__device__ float g_logit[NE];
__device__ float g_nmax[NN];
__device__ float g_nsum[NN];
__device__ float g_nodefeat[NN * DE];
__device__ uint32_t g_xh[NN * 64];                        // x fp16x2 [n][kpair]
__device__ uint32_t g_nfh[NN * 64];                       // node_feat fp16x2
__device__ uint32_t g_ath[NE * 8];                        // attr fp16x2
__device__ uint32_t g_w1h[256 * 264];                     // W1 fp16, [n][kpair]
__device__ uint32_t g_w2h[128 * 128];                     // W2 fp16, [n][kpair]
__device__ uint32_t g_hh[40960000];                       // hidden fp16x2 [m][kpair]
__device__ float g_rlogit[NE];
__device__ float g_gmax[NG];
__device__ float g_gsum[NG];
__device__ float g_graphfeat[NG * DE];

// ---------------- helpers ----------------
__device__ __forceinline__ float dot4(float4 a, float4 b) {
    return fmaf(a.x, b.x, fmaf(a.y, b.y, fmaf(a.z, b.z, a.w * b.w)));
}

__device__ __forceinline__ float wred(float v) {
    v += __shfl_xor_sync(0xffffffffu, v, 16);
    v += __shfl_xor_sync(0xffffffffu, v, 8);
    v += __shfl_xor_sync(0xffffffffu, v, 4);
    v += __shfl_xor_sync(0xffffffffu, v, 2);
    v += __shfl_xor_sync(0xffffffffu, v, 1);
    return v;
}

__device__ __forceinline__ void atomicMaxF(float* addr, float v) {
    int* ia = (int*)addr;
    int old = __float_as_int(*addr);
    while (__int_as_float(old) < v) {
        int prev = atomicCAS(ia, old, __float_as_int(v));
        if (prev == old) break;
        old = prev;
    }
}

__device__ __forceinline__ uint32_t packhi16(float f0, float f1) {
    __half2 h = __floats2half2_rn(f0, f1);
    return *(uint32_t*)&h;
}

__device__ __forceinline__ void mma16f(float* c, const uint32_t* a, uint32_t b0, uint32_t b1) {
    asm volatile("mma.sync.aligned.m16n8k16.row.col.f32.f16.f16.f32 "
        "{%0,%1,%2,%3}, {%4,%5,%6,%7}, {%8,%9}, {%0,%1,%2,%3};"
        : "+f"(c[0]), "+f"(c[1]), "+f"(c[2]), "+f"(c[3])
        : "r"(a[0]), "r"(a[1]), "r"(a[2]), "r"(a[3]), "r"(b0), "r"(b1));
}

__device__ __forceinline__ void ldsm4(uint32_t* r, uint32_t addr) {
    asm volatile("ldmatrix.sync.aligned.m8n8.x4.shared.b16 {%0,%1,%2,%3}, [%4];"
        : "=r"(r[0]), "=r"(r[1]), "=r"(r[2]), "=r"(r[3]) : "r"(addr));
}

__device__ __forceinline__ void cpa16(uint32_t dst, const void* src) {
    asm volatile("cp.async.cg.shared.global [%0], [%1], 16;" :: "r"(dst), "l"(src) : "memory");
}
#define CP_COMMIT() asm volatile("cp.async.commit_group;" ::: "memory")
#define CP_WAIT0()  asm volatile("cp.async.wait_group 0;" ::: "memory")

// ---------------- init ----------------
__global__ void k_init() {
    int i = blockIdx.x * 256 + threadIdx.x;
    if (i < NN * DE) g_nodefeat[i] = 0.f;
    if (i < NN) { g_nmax[i] = -1e30f; g_nsum[i] = 0.f; }
    if (i < NG * DE) g_graphfeat[i] = 0.f;
    if (i < NG) { g_gmax[i] = -1e30f; g_gsum[i] = 0.f; }
}

// ---------------- one-time packs: x, attr ----------------
__global__ void k_xsplit(const float* __restrict__ x, const float* __restrict__ attr) {
    int i = blockIdx.x * 256 + threadIdx.x;
    if (i < NN * 64)
        g_xh[i] = packhi16(x[2 * i], x[2 * i + 1]);
    if (i < NE * 8)
        g_ath[i] = packhi16(attr[2 * i], attr[2 * i + 1]);
}

// ---------------- one-time weight fp16 pack (transposed [n][kp]) ----------------
__global__ void k_wsplit(const float* __restrict__ W1, const float* __restrict__ W2) {
    int i = blockIdx.x * 256 + threadIdx.x;
    if (i < 256 * 264) {
        int n = i / 264, kp = i % 264;
        g_w1h[i] = packhi16(W1[(2 * kp) * 256 + n], W1[(2 * kp + 1) * 256 + n]);
    }
    if (i < 128 * 128) {
        int n = i >> 7, kp = i & 127;
        g_w2h[i] = packhi16(W2[(2 * kp) * 128 + n], W2[(2 * kp + 1) * 128 + n]);
    }
}

// ---------------- per-node scalar projections ----------------
__global__ void k_nodeproj(const float* __restrict__ x, const float* __restrict__ Wagg,
                           const float* __restrict__ Wupd, const float* __restrict__ Wread) {
    int warp = threadIdx.x >> 5, lane = threadIdx.x & 31;
    int n = blockIdx.x * 8 + warp;
    if (n >= NN) return;
    float4 xv = ((const float4*)x)[n * 32 + lane];
    const float4* wa = (const float4*)Wagg;
    const float4* wu = (const float4*)Wupd;
    const float4* wr = (const float4*)Wread;
    float s0 = dot4(xv, wa[lane]);
    float s1 = dot4(xv, wa[32 + lane]);
    float s2 = dot4(xv, wu[lane]);
    float s3 = dot4(xv, wu[32 + lane]);
    float s4 = dot4(xv, wr[lane]);
    float s5 = dot4(xv, wr[32 + lane]);
    s0 = wred(s0); s1 = wred(s1); s2 = wred(s2);
    s3 = wred(s3); s4 = wred(s4); s5 = wred(s5);
    if (lane == 0) {
        g_nproj[n * 8 + 0] = s0; g_nproj[n * 8 + 1] = s1;
        g_nproj[n * 8 + 2] = s2; g_nproj[n * 8 + 3] = s3;
        g_nproj[n * 8 + 4] = s4; g_nproj[n * 8 + 5] = s5;
    }
}

// ---------------- agg logits + segment max + attr projections ----------------
__global__ void k_agglogit(const float* __restrict__ hef, const float* __restrict__ attr,
                           const int* __restrict__ ei, const float* __restrict__ Wagg,
                           const float* __restrict__ bagg, const float* __restrict__ Wupd,
                           const float* __restrict__ Wread) {
    int warp = threadIdx.x >> 5, lane = threadIdx.x & 31;
    int e = blockIdx.x * 8 + warp;
    if (e >= NE) return;
    int r = ei[e], c = ei[NE + e];
    float4 h4 = ((const float4*)hef)[e * 32 + lane];
    float4 wh = *(const float4*)&Wagg[272 + lane * 4];
    float p = dot4(h4, wh);
    float pu = 0.f, pr = 0.f;
    if (lane < 4) {
        float4 a4 = ((const float4*)attr)[e * 4 + lane];
        p += dot4(a4, *(const float4*)&Wagg[256 + lane * 4]);
        pu = dot4(a4, *(const float4*)&Wupd[256 + lane * 4]);
        pr = dot4(a4, *(const float4*)&Wread[384 + lane * 4]);
    }
    p = wred(p); pu = wred(pu); pr = wred(pr);
    if (lane == 0) {
        float logit = p + g_nproj[r * 8 + 0] + g_nproj[c * 8 + 1] + bagg[0];
        g_logit[e] = logit;
        g_eproj[e * 2 + 0] = pu;
        g_eproj[e * 2 + 1] = pr;
        atomicMaxF(&g_nmax[c], logit);
    }
}

// ---------------- exp + unnormalized scatter + segment sum ----------------
__global__ void k_expscatter(const float* __restrict__ hef, const int* __restrict__ ei) {
    int warp = threadIdx.x >> 5, lane = threadIdx.x & 31;
    int e = blockIdx.x * 8 + warp;
    if (e >= NE) return;
    int c = ei[NE + e];
    float w = expf(g_logit[e] - g_nmax[c]);
    float4 h4 = ((const float4*)hef)[e * 32 + lane];
    float* p = &g_nodefeat[c * 128 + lane * 4];
    asm volatile("red.global.add.v4.f32 [%0], {%1,%2,%3,%4};"
        :: "l"(p), "f"(w * h4.x), "f"(w * h4.y), "f"(w * h4.z), "f"(w * h4.w)
        : "memory");
    if (lane == 0) atomicAdd(&g_nsum[c], w);
}

// ---------------- normalize node_feat + pack fp16 ----------------
__global__ void k_nnorm() {
    int i = blockIdx.x * 256 + threadIdx.x;
    if (i >= NN * 64) return;
    int n = i >> 6;
    float inv = 1.f / (g_nsum[n] + 1e-16f);
    g_nfh[i] = packhi16(g_nodefeat[2 * i] * inv, g_nodefeat[2 * i + 1] * inv);
}

// ==================== GEMM1 (plain fp16, cp.async staging) ====================
// smem words: A[2][128][ST] @0 (3072), BH @3072, srol @6144, scol @6272
#define G1_WORDS 6400

__global__ void __launch_bounds__(256, 2)
k_gemm1(const int* __restrict__ ei, const float* __restrict__ b1) {
    extern __shared__ uint32_t sm_[];
    int* srol = (int*)(sm_ + 6144);
    int* scol = srol + 128;

    int t = threadIdx.x;
    int me0 = blockIdx.x * 128, hn0 = blockIdx.y * 128;
    if (t < 128) srol[t] = ei[me0 + t];
    else scol[t - 128] = ei[NE + me0 + t - 128];
    __syncthreads();

    int am = t >> 1, sw = (t & 1) * 4;
    int lane = t & 31, w = t >> 5;
    int wm = (w & 3) * 32, wn = (w >> 2) * 64;
    int grp = lane >> 2, quad = lane & 3;

    uint32_t smb = (uint32_t)__cvta_generic_to_shared(sm_);
    int arow = wm + (lane & 15);
    uint32_t rA = smb + arow * (ST * 4) + ((lane & 16) ? 16 : 0);
    int brow = wn + (lane & 7) + ((lane & 16) ? 8 : 0);
    uint32_t rB = smb + 3072 * 4 + brow * (ST * 4) + ((lane & 8) ? 16 : 0);
    const uint32_t BUFB  = 1536 * 4;   // bytes per buffer within a region
    const uint32_t BHOFF = 3072 * 4;   // A -> BH region offset

    auto stage = [&](int kt, int buf) {
        int kp = kt * 8 + sw;
        const uint32_t* pa;
        if (kp < 64)       pa = g_xh  + (size_t)srol[am] * 64 + kp;
        else if (kp < 128) pa = g_nfh + (size_t)srol[am] * 64 + kp - 64;
        else if (kp < 192) pa = g_xh  + (size_t)scol[am] * 64 + kp - 128;
        else if (kp < 256) pa = g_nfh + (size_t)scol[am] * 64 + kp - 192;
        else               pa = g_ath + (size_t)(me0 + am) * 8 + kp - 256;
        uint32_t d = smb + (buf * 1536 + am * ST + sw) * 4;
        cpa16(d, pa);
        cpa16(d + BHOFF, g_w1h + (size_t)(hn0 + am) * 264 + kp);
    };

    stage(0, 0);
    CP_COMMIT();
    CP_WAIT0();
    __syncthreads();

    float acc[2][8][4];
#pragma unroll
    for (int i = 0; i < 2; i++)
#pragma unroll
        for (int j = 0; j < 8; j++)
#pragma unroll
            for (int k = 0; k < 4; k++) acc[i][j][k] = 0.f;

    const int KT = K1TOT / 16;  // 33
    for (int kt = 0; kt < KT; ++kt) {
        int cur = kt & 1;
        if (kt < KT - 1) {
            stage(kt + 1, cur ^ 1);
            CP_COMMIT();
        }
        uint32_t aH[2][4];
#pragma unroll
        for (int mf = 0; mf < 2; mf++)
            ldsm4(aH[mf], rA + cur * BUFB + mf * (16 * ST * 4));
#pragma unroll
        for (int j = 0; j < 4; j++) {
            uint32_t bH[4];
            ldsm4(bH, rB + cur * BUFB + j * (16 * ST * 4));
#pragma unroll
            for (int mf = 0; mf < 2; mf++) {
                mma16f(acc[mf][2 * j],     aH[mf], bH[0], bH[1]);
                mma16f(acc[mf][2 * j + 1], aH[mf], bH[2], bH[3]);
            }
        }
        if (kt < KT - 1) CP_WAIT0();
        __syncthreads();
    }

    // epilogue: bias + relu, pack fp16, write g_hh
#pragma unroll
    for (int mf = 0; mf < 2; mf++) {
        int m = me0 + wm + mf * 16 + grp;
#pragma unroll
        for (int nf = 0; nf < 8; nf++) {
            int c0 = hn0 + wn + nf * 8 + quad * 2;
            float bb0 = b1[c0], bb1 = b1[c0 + 1];
            int kp = c0 >> 1;
            float v0 = fmaxf(acc[mf][nf][0] + bb0, 0.f);
            float v1 = fmaxf(acc[mf][nf][1] + bb1, 0.f);
            g_hh[(size_t)m * 128 + kp] = packhi16(v0, v1);
            float v2 = fmaxf(acc[mf][nf][2] + bb0, 0.f);
            float v3 = fmaxf(acc[mf][nf][3] + bb1, 0.f);
            g_hh[(size_t)(m + 8) * 128 + kp] = packhi16(v2, v3);
        }
    }
}

// ==================== GEMM2 fused (plain fp16): cand -> gate -> ef -> readout ====================
// smem words: A @0 (3072), BH @3072, srol @6144, scol @6272, sred @6400, sg @6656
#define G2_WORDS 6784

__global__ void __launch_bounds__(256, 2)
k_gemm2f(const float* __restrict__ hef, const int* __restrict__ ei,
         const int* __restrict__ batch, const float* __restrict__ b2,
         const float* __restrict__ Wupd, const float* __restrict__ bupd,
         const float* __restrict__ Wread, const float* __restrict__ bread,
         float* __restrict__ out) {
    extern __shared__ uint32_t sm_[];
    int*   srol = (int*)(sm_ + 6144);
    int*   scol = (int*)(sm_ + 6272);
    float* sred = (float*)(sm_ + 6400);
    float* sg   = (float*)(sm_ + 6656);

    int t = threadIdx.x;
    int me0 = blockIdx.x * 128;
    if (t < 128) srol[t] = ei[me0 + t];
    else scol[t - 128] = ei[NE + me0 + t - 128];

    int am = t >> 1, sw = (t & 1) * 4;
    int lane = t & 31, w = t >> 5;
    int wm = (w & 3) * 32, wn = (w >> 2) * 64;
    int grp = lane >> 2, quad = lane & 3;

    uint32_t smb = (uint32_t)__cvta_generic_to_shared(sm_);
    int arow = wm + (lane & 15);
    uint32_t rA = smb + arow * (ST * 4) + ((lane & 16) ? 16 : 0);
    int brow = wn + (lane & 7) + ((lane & 16) ? 8 : 0);
    uint32_t rB = smb + 3072 * 4 + brow * (ST * 4) + ((lane & 8) ? 16 : 0);
    const uint32_t BUFB  = 1536 * 4;
    const uint32_t BHOFF = 3072 * 4;

    auto stage = [&](int kt, int buf) {
        int kp = kt * 8 + sw;
        uint32_t d = smb + (buf * 1536 + am * ST + sw) * 4;
        cpa16(d, g_hh + (size_t)(me0 + am) * 128 + kp);
        cpa16(d + BHOFF, g_w2h + (size_t)am * 128 + kp);
    };

    stage(0, 0);
    CP_COMMIT();
    CP_WAIT0();
    __syncthreads();

    float acc[2][8][4];
#pragma unroll
    for (int i = 0; i < 2; i++)
#pragma unroll
        for (int j = 0; j < 8; j++)
#pragma unroll
            for (int k = 0; k < 4; k++) acc[i][j][k] = 0.f;

    const int KT = NH / 16;  // 16
    for (int kt = 0; kt < KT; ++kt) {
        int cur = kt & 1;
        if (kt < KT - 1) {
            stage(kt + 1, cur ^ 1);
            CP_COMMIT();
        }
        uint32_t aH[2][4];
#pragma unroll
        for (int mf = 0; mf < 2; mf++)
            ldsm4(aH[mf], rA + cur * BUFB + mf * (16 * ST * 4));
#pragma unroll
        for (int j = 0; j < 4; j++) {
            uint32_t bH[4];
            ldsm4(bH, rB + cur * BUFB + j * (16 * ST * 4));
#pragma unroll
            for (int mf = 0; mf < 2; mf++) {
                mma16f(acc[mf][2 * j],     aH[mf], bH[0], bH[1]);
                mma16f(acc[mf][2 * j + 1], aH[mf], bH[2], bH[3]);
            }
        }
        if (kt < KT - 1) CP_WAIT0();
        __syncthreads();
    }

    // acc += b2 -> cand
#pragma unroll
    for (int mf = 0; mf < 2; mf++)
#pragma unroll
        for (int nf = 0; nf < 8; nf++) {
            int c0 = wn + nf * 8 + quad * 2;
            float bb0 = b2[c0], bb1 = b2[c0 + 1];
            acc[mf][nf][0] += bb0; acc[mf][nf][1] += bb1;
            acc[mf][nf][2] += bb0; acc[mf][nf][3] += bb1;
        }

    // ---- epilogue pass 1: gate logit dot ----
    float s0 = 0.f, s1 = 0.f, s2 = 0.f, s3 = 0.f;
#pragma unroll
    for (int mf = 0; mf < 2; mf++) {
        int r0 = wm + mf * 16 + grp;
#pragma unroll
        for (int nf = 0; nf < 8; nf++) {
            int c = wn + nf * 8 + quad * 2;
            float2 wc = *(const float2*)&Wupd[400 + c];
            float2 whv = *(const float2*)&Wupd[272 + c];
            float2 h0 = *(const float2*)&hef[(size_t)(me0 + r0) * 128 + c];
            float2 h1 = *(const float2*)&hef[(size_t)(me0 + r0 + 8) * 128 + c];
            float p0 = acc[mf][nf][0] * wc.x + acc[mf][nf][1] * wc.y + h0.x * whv.x + h0.y * whv.y;
            float p1 = acc[mf][nf][2] * wc.x + acc[mf][nf][3] * wc.y + h1.x * whv.x + h1.y * whv.y;
            if (mf == 0) { s0 += p0; s1 += p1; } else { s2 += p0; s3 += p1; }
        }
    }
    s0 += __shfl_xor_sync(0xffffffffu, s0, 1); s0 += __shfl_xor_sync(0xffffffffu, s0, 2);
    s1 += __shfl_xor_sync(0xffffffffu, s1, 1); s1 += __shfl_xor_sync(0xffffffffu, s1, 2);
    s2 += __shfl_xor_sync(0xffffffffu, s2, 1); s2 += __shfl_xor_sync(0xffffffffu, s2, 2);
    s3 += __shfl_xor_sync(0xffffffffu, s3, 1); s3 += __shfl_xor_sync(0xffffffffu, s3, 2);
    if (quad == 0) {
        int nh = w >> 2;
        sred[(wm + grp) * 2 + nh] = s0;
        sred[(wm + 8 + grp) * 2 + nh] = s1;
        sred[(wm + 16 + grp) * 2 + nh] = s2;
        sred[(wm + 24 + grp) * 2 + nh] = s3;
    }
    __syncthreads();
    if (t < 128) {
        int e = me0 + t, r = srol[t], c = scol[t];
        float tot = sred[t * 2] + sred[t * 2 + 1];
        float gv = tot + g_eproj[e * 2] + g_nproj[r * 8 + 2] + g_nproj[c * 8 + 3] + bupd[0];
        sg[t] = 1.f / (1.f + expf(-gv));
    }
    __syncthreads();

    // ---- epilogue pass 2: ef = g*cand + (1-g)*hef, write out, readout dot ----
    s0 = s1 = s2 = s3 = 0.f;
#pragma unroll
    for (int mf = 0; mf < 2; mf++) {
        int r0 = wm + mf * 16 + grp;
        float g0 = sg[r0], g1 = sg[r0 + 8];
#pragma unroll
        for (int nf = 0; nf < 8; nf++) {
            int c = wn + nf * 8 + quad * 2;
            float2 h0 = *(const float2*)&hef[(size_t)(me0 + r0) * 128 + c];
            float2 h1 = *(const float2*)&hef[(size_t)(me0 + r0 + 8) * 128 + c];
            float2 e0, e1;
            e0.x = fmaf(g0, acc[mf][nf][0] - h0.x, h0.x);
            e0.y = fmaf(g0, acc[mf][nf][1] - h0.y, h0.y);
            e1.x = fmaf(g1, acc[mf][nf][2] - h1.x, h1.x);
            e1.y = fmaf(g1, acc[mf][nf][3] - h1.y, h1.y);
            *(float2*)&out[(size_t)(me0 + r0) * 128 + c] = e0;
            *(float2*)&out[(size_t)(me0 + r0 + 8) * 128 + c] = e1;
            float2 wr = *(const float2*)&Wread[256 + c];
            float p0 = e0.x * wr.x + e0.y * wr.y;
            float p1 = e1.x * wr.x + e1.y * wr.y;
            if (mf == 0) { s0 += p0; s1 += p1; } else { s2 += p0; s3 += p1; }
        }
    }
    s0 += __shfl_xor_sync(0xffffffffu, s0, 1); s0 += __shfl_xor_sync(0xffffffffu, s0, 2);
    s1 += __shfl_xor_sync(0xffffffffu, s1, 1); s1 += __shfl_xor_sync(0xffffffffu, s1, 2);
    s2 += __shfl_xor_sync(0xffffffffu, s2, 1); s2 += __shfl_xor_sync(0xffffffffu, s2, 2);
    s3 += __shfl_xor_sync(0xffffffffu, s3, 1); s3 += __shfl_xor_sync(0xffffffffu, s3, 2);
    if (quad == 0) {
        int nh = w >> 2;
        sred[(wm + grp) * 2 + nh] = s0;
        sred[(wm + 8 + grp) * 2 + nh] = s1;
        sred[(wm + 16 + grp) * 2 + nh] = s2;
        sred[(wm + 24 + grp) * 2 + nh] = s3;
    }
    __syncthreads();
    if (t < 128) {
        int e = me0 + t, r = srol[t], c = scol[t];
        float tot = sred[t * 2] + sred[t * 2 + 1];
        float rl = tot + g_eproj[e * 2 + 1] + g_nproj[r * 8 + 4] + g_nproj[c * 8 + 5] + bread[0];
        g_rlogit[e] = rl;
        atomicMaxF(&g_gmax[batch[r]], rl);
    }
}

// ---------------- readout: exp + unnormalized scatter + segment sum (merged) ----------------
__global__ void k_rscatter(const int* __restrict__ ei, const int* __restrict__ batch,
                           const float* __restrict__ out) {
    __shared__ float sacc[NG * DE];   // 32 KB
    __shared__ float ssum[NG];
    int t = threadIdx.x;
    for (int i = t; i < NG * DE; i += 256) sacc[i] = 0.f;
    if (t < NG) ssum[t] = 0.f;
    __syncthreads();
    int warp = t >> 5, lane = t & 31;
    for (int e = blockIdx.x * 8 + warp; e < NE; e += gridDim.x * 8) {
        int gi = batch[ei[e]];
        float rw = expf(g_rlogit[e] - g_gmax[gi]);
        float4 ef = ((const float4*)out)[e * 32 + lane];
        float* p = &sacc[gi * 128 + lane * 4];
        atomicAdd(p + 0, rw * ef.x);
        atomicAdd(p + 1, rw * ef.y);
        atomicAdd(p + 2, rw * ef.z);
        atomicAdd(p + 3, rw * ef.w);
        if (lane == 0) atomicAdd(&ssum[gi], rw);
    }
    __syncthreads();
    for (int i = t; i < NG * DE; i += 256)
        if (sacc[i] != 0.f) atomicAdd(&g_graphfeat[i], sacc[i]);
    if (t < NG && ssum[t] != 0.f) atomicAdd(&g_gsum[t], ssum[t]);
}

// ---------------- confidence (normalize here) ----------------
__global__ void k_conf(const float* __restrict__ Wscore, const float* __restrict__ bscore,
                       float* __restrict__ out) {
    int g = blockIdx.x, t = threadIdx.x;
    float v = g_graphfeat[g * 128 + t] / (g_gsum[g] + 1e-16f) * Wscore[t];
    v = wred(v);
    __shared__ float sm[4];
    if ((t & 31) == 0) sm[t >> 5] = v;
    __syncthreads();
    if (t == 0) {
        float s = sm[0] + sm[1] + sm[2] + sm[3] + bscore[0];
        out[(size_t)NE * DE + g] = 1.f / (1.f + expf(-s));
    }
}

// ---------------- launch ----------------
extern "C" void kernel_launch(void* const* d_in, const int* in_sizes, int n_in,
                              void* d_out, int out_size) {
    const float* x      = (const float*)d_in[0];
    const float* hef    = (const float*)d_in[1];
    const float* attr   = (const float*)d_in[2];
    const int*   ei     = (const int*)d_in[3];
    const int*   batch  = (const int*)d_in[4];
    const float* Wagg   = (const float*)d_in[6];
    const float* bagg   = (const float*)d_in[7];
    const float* W1     = (const float*)d_in[8];
    const float* b1     = (const float*)d_in[9];
    const float* W2     = (const float*)d_in[10];
    const float* b2     = (const float*)d_in[11];
    const float* Wupd   = (const float*)d_in[12];
    const float* bupd   = (const float*)d_in[13];
    const float* Wread  = (const float*)d_in[14];
    const float* bread  = (const float*)d_in[15];
    const float* Wscore = (const float*)d_in[16];
    const float* bscore = (const float*)d_in[17];
    float* out = (float*)d_out;

    static bool attr_set = false;
    if (!attr_set) {
        cudaFuncSetAttribute(k_gemm1, cudaFuncAttributeMaxDynamicSharedMemorySize, G1_WORDS * 4);
        cudaFuncSetAttribute(k_gemm2f, cudaFuncAttributeMaxDynamicSharedMemorySize, G2_WORDS * 4);
        attr_set = true;
    }

    k_init<<<(NN * DE + 255) / 256, 256>>>();
    k_xsplit<<<(NE * 8 + 255) / 256, 256>>>(x, attr);
    k_wsplit<<<(256 * 264 + 255) / 256, 256>>>(W1, W2);
    k_nodeproj<<<(NN + 7) / 8, 256>>>(x, Wagg, Wupd, Wread);
    k_agglogit<<<NE / 8, 256>>>(hef, attr, ei, Wagg, bagg, Wupd, Wread);
    k_expscatter<<<NE / 8, 256>>>(hef, ei);
    k_nnorm<<<(NN * 64 + 255) / 256, 256>>>();
    k_gemm1<<<dim3(NE / 128, 2), 256, G1_WORDS * 4>>>(ei, b1);
    k_gemm2f<<<NE / 128, 256, G2_WORDS * 4>>>(hef, ei, batch, b2, Wupd, bupd,
                                              Wread, bread, out);
    k_rscatter<<<296, 256>>>(ei, batch, out);
    k_conf<<<NG, 128>>>(Wscore, bscore, out);
}

// round 12
// speedup vs baseline: 2.6823x; 1.1438x over previous
#include <cuda_runtime.h>
#include <cuda_fp16.h>
#include <stdint.h>

#define NN 20000
#define NE 320000
#define DN 128
#define DE 128
#define DA 16
#define NH 256
#define NG 64
#define K1TOT 528
#define ST 12              // smem row stride in u32 words (8 used + 4 pad)

// ---------------- scratch ----------------
__device__ float g_nproj[NN * 8];
__device__ float g_eproj[NE * 2];
__device__ float g_nsum[NN];
__device__ float g_nodefeat[NN * DE];
__device__ uint32_t g_xh[NN * 64];                        // x fp16x2 [n][kpair]
__device__ uint32_t g_nfh[NN * 64];                       // node_feat fp16x2
__device__ uint32_t g_ath[NE * 8];                        // attr fp16x2
__device__ uint32_t g_w1h[256 * 264];                     // W1 fp16, [n][kpair]
__device__ uint32_t g_w2h[128 * 128];                     // W2 fp16, [n][kpair]
__device__ uint32_t g_hh[40960000];                       // hidden fp16x2 [m][kpair]
__device__ float g_rw[NE];
__device__ float g_gsum[NG];
__device__ float g_graphfeat[NG * DE];

// ---------------- helpers ----------------
__device__ __forceinline__ float dot4(float4 a, float4 b) {
    return fmaf(a.x, b.x, fmaf(a.y, b.y, fmaf(a.z, b.z, a.w * b.w)));
}

__device__ __forceinline__ float wred(float v) {
    v += __shfl_xor_sync(0xffffffffu, v, 16);
    v += __shfl_xor_sync(0xffffffffu, v, 8);
    v += __shfl_xor_sync(0xffffffffu, v, 4);
    v += __shfl_xor_sync(0xffffffffu, v, 2);
    v += __shfl_xor_sync(0xffffffffu, v, 1);
    return v;
}

__device__ __forceinline__ uint32_t packhi16(float f0, float f1) {
    __half2 h = __floats2half2_rn(f0, f1);
    return *(uint32_t*)&h;
}

__device__ __forceinline__ void mma16f(float* c, const uint32_t* a, uint32_t b0, uint32_t b1) {
    asm volatile("mma.sync.aligned.m16n8k16.row.col.f32.f16.f16.f32 "
        "{%0,%1,%2,%3}, {%4,%5,%6,%7}, {%8,%9}, {%0,%1,%2,%3};"
        : "+f"(c[0]), "+f"(c[1]), "+f"(c[2]), "+f"(c[3])
        : "r"(a[0]), "r"(a[1]), "r"(a[2]), "r"(a[3]), "r"(b0), "r"(b1));
}

__device__ __forceinline__ void ldsm4(uint32_t* r, uint32_t addr) {
    asm volatile("ldmatrix.sync.aligned.m8n8.x4.shared.b16 {%0,%1,%2,%3}, [%4];"
        : "=r"(r[0]), "=r"(r[1]), "=r"(r[2]), "=r"(r[3]) : "r"(addr));
}

__device__ __forceinline__ void cpa16(uint32_t dst, const void* src) {
    asm volatile("cp.async.cg.shared.global [%0], [%1], 16;" :: "r"(dst), "l"(src) : "memory");
}
#define CP_COMMIT() asm volatile("cp.async.commit_group;" ::: "memory")
#define CP_WAIT0()  asm volatile("cp.async.wait_group 0;" ::: "memory")

// ---------------- init ----------------
__global__ void k_init() {
    int i = blockIdx.x * 256 + threadIdx.x;
    if (i < NN * DE) g_nodefeat[i] = 0.f;
    if (i < NN) g_nsum[i] = 0.f;
    if (i < NG * DE) g_graphfeat[i] = 0.f;
    if (i < NG) g_gsum[i] = 0.f;
}

// ---------------- one-time packs: x, attr ----------------
__global__ void k_xsplit(const float* __restrict__ x, const float* __restrict__ attr) {
    int i = blockIdx.x * 256 + threadIdx.x;
    if (i < NN * 64)
        g_xh[i] = packhi16(x[2 * i], x[2 * i + 1]);
    if (i < NE * 8)
        g_ath[i] = packhi16(attr[2 * i], attr[2 * i + 1]);
}

// ---------------- one-time weight fp16 pack (transposed [n][kp]) ----------------
__global__ void k_wsplit(const float* __restrict__ W1, const float* __restrict__ W2) {
    int i = blockIdx.x * 256 + threadIdx.x;
    if (i < 256 * 264) {
        int n = i / 264, kp = i % 264;
        g_w1h[i] = packhi16(W1[(2 * kp) * 256 + n], W1[(2 * kp + 1) * 256 + n]);
    }
    if (i < 128 * 128) {
        int n = i >> 7, kp = i & 127;
        g_w2h[i] = packhi16(W2[(2 * kp) * 128 + n], W2[(2 * kp + 1) * 128 + n]);
    }
}

// ---------------- per-node scalar projections ----------------
__global__ void k_nodeproj(const float* __restrict__ x, const float* __restrict__ Wagg,
                           const float* __restrict__ Wupd, const float* __restrict__ Wread) {
    int warp = threadIdx.x >> 5, lane = threadIdx.x & 31;
    int n = blockIdx.x * 8 + warp;
    if (n >= NN) return;
    float4 xv = ((const float4*)x)[n * 32 + lane];
    const float4* wa = (const float4*)Wagg;
    const float4* wu = (const float4*)Wupd;
    const float4* wr = (const float4*)Wread;
    float s0 = dot4(xv, wa[lane]);
    float s1 = dot4(xv, wa[32 + lane]);
    float s2 = dot4(xv, wu[lane]);
    float s3 = dot4(xv, wu[32 + lane]);
    float s4 = dot4(xv, wr[lane]);
    float s5 = dot4(xv, wr[32 + lane]);
    s0 = wred(s0); s1 = wred(s1); s2 = wred(s2);
    s3 = wred(s3); s4 = wred(s4); s5 = wred(s5);
    if (lane == 0) {
        g_nproj[n * 8 + 0] = s0; g_nproj[n * 8 + 1] = s1;
        g_nproj[n * 8 + 2] = s2; g_nproj[n * 8 + 3] = s3;
        g_nproj[n * 8 + 4] = s4; g_nproj[n * 8 + 5] = s5;
    }
}

// ---------------- agg logit + exp + scatter + attr projections (ONE pass) ----------------
__global__ void k_aggscatter(const float* __restrict__ hef, const float* __restrict__ attr,
                             const int* __restrict__ ei, const float* __restrict__ Wagg,
                             const float* __restrict__ bagg, const float* __restrict__ Wupd,
                             const float* __restrict__ Wread) {
    int warp = threadIdx.x >> 5, lane = threadIdx.x & 31;
    int e = blockIdx.x * 8 + warp;
    if (e >= NE) return;
    int r = ei[e], c = ei[NE + e];
    float4 h4 = ((const float4*)hef)[e * 32 + lane];
    float4 wh = *(const float4*)&Wagg[272 + lane * 4];
    float p = dot4(h4, wh);
    float pu = 0.f, pr = 0.f;
    if (lane < 4) {
        float4 a4 = ((const float4*)attr)[e * 4 + lane];
        p += dot4(a4, *(const float4*)&Wagg[256 + lane * 4]);
        pu = dot4(a4, *(const float4*)&Wupd[256 + lane * 4]);
        pr = dot4(a4, *(const float4*)&Wread[384 + lane * 4]);
    }
    p = wred(p); pu = wred(pu); pr = wred(pr);
    float w;
    if (lane == 0) {
        float logit = p + g_nproj[r * 8 + 0] + g_nproj[c * 8 + 1] + bagg[0];
        w = expf(logit);     // no-max softmax: logits are O(1), no overflow risk
        g_eproj[e * 2 + 0] = pu;
        g_eproj[e * 2 + 1] = pr;
        atomicAdd(&g_nsum[c], w);
    }
    w = __shfl_sync(0xffffffffu, w, 0);
    float* ptr = &g_nodefeat[c * 128 + lane * 4];
    asm volatile("red.global.add.v4.f32 [%0], {%1,%2,%3,%4};"
        :: "l"(ptr), "f"(w * h4.x), "f"(w * h4.y), "f"(w * h4.z), "f"(w * h4.w)
        : "memory");
}

// ---------------- normalize node_feat + pack fp16 ----------------
__global__ void k_nnorm() {
    int i = blockIdx.x * 256 + threadIdx.x;
    if (i >= NN * 64) return;
    int n = i >> 6;
    float inv = 1.f / (g_nsum[n] + 1e-16f);
    g_nfh[i] = packhi16(g_nodefeat[2 * i] * inv, g_nodefeat[2 * i + 1] * inv);
}

// ==================== GEMM1 (plain fp16, cp.async staging) ====================
// smem words: A[2][128][ST] @0 (3072), BH @3072, srol @6144, scol @6272
#define G1_WORDS 6400

__global__ void __launch_bounds__(256, 2)
k_gemm1(const int* __restrict__ ei, const float* __restrict__ b1) {
    extern __shared__ uint32_t sm_[];
    int* srol = (int*)(sm_ + 6144);
    int* scol = srol + 128;

    int t = threadIdx.x;
    int me0 = blockIdx.x * 128, hn0 = blockIdx.y * 128;
    if (t < 128) srol[t] = ei[me0 + t];
    else scol[t - 128] = ei[NE + me0 + t - 128];
    __syncthreads();

    int am = t >> 1, sw = (t & 1) * 4;
    int lane = t & 31, w = t >> 5;
    int wm = (w & 3) * 32, wn = (w >> 2) * 64;
    int grp = lane >> 2, quad = lane & 3;

    uint32_t smb = (uint32_t)__cvta_generic_to_shared(sm_);
    int arow = wm + (lane & 15);
    uint32_t rA = smb + arow * (ST * 4) + ((lane & 16) ? 16 : 0);
    int brow = wn + (lane & 7) + ((lane & 16) ? 8 : 0);
    uint32_t rB = smb + 3072 * 4 + brow * (ST * 4) + ((lane & 8) ? 16 : 0);
    const uint32_t BUFB  = 1536 * 4;
    const uint32_t BHOFF = 3072 * 4;

    auto stage = [&](int kt, int buf) {
        int kp = kt * 8 + sw;
        const uint32_t* pa;
        if (kp < 64)       pa = g_xh  + (size_t)srol[am] * 64 + kp;
        else if (kp < 128) pa = g_nfh + (size_t)srol[am] * 64 + kp - 64;
        else if (kp < 192) pa = g_xh  + (size_t)scol[am] * 64 + kp - 128;
        else if (kp < 256) pa = g_nfh + (size_t)scol[am] * 64 + kp - 192;
        else               pa = g_ath + (size_t)(me0 + am) * 8 + kp - 256;
        uint32_t d = smb + (buf * 1536 + am * ST + sw) * 4;
        cpa16(d, pa);
        cpa16(d + BHOFF, g_w1h + (size_t)(hn0 + am) * 264 + kp);
    };

    stage(0, 0);
    CP_COMMIT();
    CP_WAIT0();
    __syncthreads();

    float acc[2][8][4];
#pragma unroll
    for (int i = 0; i < 2; i++)
#pragma unroll
        for (int j = 0; j < 8; j++)
#pragma unroll
            for (int k = 0; k < 4; k++) acc[i][j][k] = 0.f;

    const int KT = K1TOT / 16;  // 33
    for (int kt = 0; kt < KT; ++kt) {
        int cur = kt & 1;
        if (kt < KT - 1) {
            stage(kt + 1, cur ^ 1);
            CP_COMMIT();
        }
        uint32_t aH[2][4];
#pragma unroll
        for (int mf = 0; mf < 2; mf++)
            ldsm4(aH[mf], rA + cur * BUFB + mf * (16 * ST * 4));
#pragma unroll
        for (int j = 0; j < 4; j++) {
            uint32_t bH[4];
            ldsm4(bH, rB + cur * BUFB + j * (16 * ST * 4));
#pragma unroll
            for (int mf = 0; mf < 2; mf++) {
                mma16f(acc[mf][2 * j],     aH[mf], bH[0], bH[1]);
                mma16f(acc[mf][2 * j + 1], aH[mf], bH[2], bH[3]);
            }
        }
        if (kt < KT - 1) CP_WAIT0();
        __syncthreads();
    }

    // epilogue: bias + relu, pack fp16, write g_hh
#pragma unroll
    for (int mf = 0; mf < 2; mf++) {
        int m = me0 + wm + mf * 16 + grp;
#pragma unroll
        for (int nf = 0; nf < 8; nf++) {
            int c0 = hn0 + wn + nf * 8 + quad * 2;
            float bb0 = b1[c0], bb1 = b1[c0 + 1];
            int kp = c0 >> 1;
            float v0 = fmaxf(acc[mf][nf][0] + bb0, 0.f);
            float v1 = fmaxf(acc[mf][nf][1] + bb1, 0.f);
            g_hh[(size_t)m * 128 + kp] = packhi16(v0, v1);
            float v2 = fmaxf(acc[mf][nf][2] + bb0, 0.f);
            float v3 = fmaxf(acc[mf][nf][3] + bb1, 0.f);
            g_hh[(size_t)(m + 8) * 128 + kp] = packhi16(v2, v3);
        }
    }
}

// ==================== GEMM2 fused (plain fp16): cand -> gate -> ef -> readout ====================
// smem words: A @0 (3072), BH @3072, srol @6144, scol @6272, sred @6400, sg @6656
#define G2_WORDS 6784

__global__ void __launch_bounds__(256, 2)
k_gemm2f(const float* __restrict__ hef, const int* __restrict__ ei,
         const float* __restrict__ b2,
         const float* __restrict__ Wupd, const float* __restrict__ bupd,
         const float* __restrict__ Wread, const float* __restrict__ bread,
         float* __restrict__ out) {
    extern __shared__ uint32_t sm_[];
    int*   srol = (int*)(sm_ + 6144);
    int*   scol = (int*)(sm_ + 6272);
    float* sred = (float*)(sm_ + 6400);
    float* sg   = (float*)(sm_ + 6656);

    int t = threadIdx.x;
    int me0 = blockIdx.x * 128;
    if (t < 128) srol[t] = ei[me0 + t];
    else scol[t - 128] = ei[NE + me0 + t - 128];

    int am = t >> 1, sw = (t & 1) * 4;
    int lane = t & 31, w = t >> 5;
    int wm = (w & 3) * 32, wn = (w >> 2) * 64;
    int grp = lane >> 2, quad = lane & 3;

    uint32_t smb = (uint32_t)__cvta_generic_to_shared(sm_);
    int arow = wm + (lane & 15);
    uint32_t rA = smb + arow * (ST * 4) + ((lane & 16) ? 16 : 0);
    int brow = wn + (lane & 7) + ((lane & 16) ? 8 : 0);
    uint32_t rB = smb + 3072 * 4 + brow * (ST * 4) + ((lane & 8) ? 16 : 0);
    const uint32_t BUFB  = 1536 * 4;
    const uint32_t BHOFF = 3072 * 4;

    auto stage = [&](int kt, int buf) {
        int kp = kt * 8 + sw;
        uint32_t d = smb + (buf * 1536 + am * ST + sw) * 4;
        cpa16(d, g_hh + (size_t)(me0 + am) * 128 + kp);
        cpa16(d + BHOFF, g_w2h + (size_t)am * 128 + kp);
    };

    stage(0, 0);
    CP_COMMIT();
    CP_WAIT0();
    __syncthreads();

    float acc[2][8][4];
#pragma unroll
    for (int i = 0; i < 2; i++)
#pragma unroll
        for (int j = 0; j < 8; j++)
#pragma unroll
            for (int k = 0; k < 4; k++) acc[i][j][k] = 0.f;

    const int KT = NH / 16;  // 16
    for (int kt = 0; kt < KT; ++kt) {
        int cur = kt & 1;
        if (kt < KT - 1) {
            stage(kt + 1, cur ^ 1);
            CP_COMMIT();
        }
        uint32_t aH[2][4];
#pragma unroll
        for (int mf = 0; mf < 2; mf++)
            ldsm4(aH[mf], rA + cur * BUFB + mf * (16 * ST * 4));
#pragma unroll
        for (int j = 0; j < 4; j++) {
            uint32_t bH[4];
            ldsm4(bH, rB + cur * BUFB + j * (16 * ST * 4));
#pragma unroll
            for (int mf = 0; mf < 2; mf++) {
                mma16f(acc[mf][2 * j],     aH[mf], bH[0], bH[1]);
                mma16f(acc[mf][2 * j + 1], aH[mf], bH[2], bH[3]);
            }
        }
        if (kt < KT - 1) CP_WAIT0();
        __syncthreads();
    }

    // acc += b2 -> cand
#pragma unroll
    for (int mf = 0; mf < 2; mf++)
#pragma unroll
        for (int nf = 0; nf < 8; nf++) {
            int c0 = wn + nf * 8 + quad * 2;
            float bb0 = b2[c0], bb1 = b2[c0 + 1];
            acc[mf][nf][0] += bb0; acc[mf][nf][1] += bb1;
            acc[mf][nf][2] += bb0; acc[mf][nf][3] += bb1;
        }

    // ---- epilogue pass 1: gate logit dot ----
    float s0 = 0.f, s1 = 0.f, s2 = 0.f, s3 = 0.f;
#pragma unroll
    for (int mf = 0; mf < 2; mf++) {
        int r0 = wm + mf * 16 + grp;
#pragma unroll
        for (int nf = 0; nf < 8; nf++) {
            int c = wn + nf * 8 + quad * 2;
            float2 wc = *(const float2*)&Wupd[400 + c];
            float2 whv = *(const float2*)&Wupd[272 + c];
            float2 h0 = *(const float2*)&hef[(size_t)(me0 + r0) * 128 + c];
            float2 h1 = *(const float2*)&hef[(size_t)(me0 + r0 + 8) * 128 + c];
            float p0 = acc[mf][nf][0] * wc.x + acc[mf][nf][1] * wc.y + h0.x * whv.x + h0.y * whv.y;
            float p1 = acc[mf][nf][2] * wc.x + acc[mf][nf][3] * wc.y + h1.x * whv.x + h1.y * whv.y;
            if (mf == 0) { s0 += p0; s1 += p1; } else { s2 += p0; s3 += p1; }
        }
    }
    s0 += __shfl_xor_sync(0xffffffffu, s0, 1); s0 += __shfl_xor_sync(0xffffffffu, s0, 2);
    s1 += __shfl_xor_sync(0xffffffffu, s1, 1); s1 += __shfl_xor_sync(0xffffffffu, s1, 2);
    s2 += __shfl_xor_sync(0xffffffffu, s2, 1); s2 += __shfl_xor_sync(0xffffffffu, s2, 2);
    s3 += __shfl_xor_sync(0xffffffffu, s3, 1); s3 += __shfl_xor_sync(0xffffffffu, s3, 2);
    if (quad == 0) {
        int nh = w >> 2;
        sred[(wm + grp) * 2 + nh] = s0;
        sred[(wm + 8 + grp) * 2 + nh] = s1;
        sred[(wm + 16 + grp) * 2 + nh] = s2;
        sred[(wm + 24 + grp) * 2 + nh] = s3;
    }
    __syncthreads();
    if (t < 128) {
        int e = me0 + t, r = srol[t], c = scol[t];
        float tot = sred[t * 2] + sred[t * 2 + 1];
        float gv = tot + g_eproj[e * 2] + g_nproj[r * 8 + 2] + g_nproj[c * 8 + 3] + bupd[0];
        sg[t] = 1.f / (1.f + expf(-gv));
    }
    __syncthreads();

    // ---- epilogue pass 2: ef = g*cand + (1-g)*hef, write out, readout dot ----
    s0 = s1 = s2 = s3 = 0.f;
#pragma unroll
    for (int mf = 0; mf < 2; mf++) {
        int r0 = wm + mf * 16 + grp;
        float g0 = sg[r0], g1 = sg[r0 + 8];
#pragma unroll
        for (int nf = 0; nf < 8; nf++) {
            int c = wn + nf * 8 + quad * 2;
            float2 h0 = *(const float2*)&hef[(size_t)(me0 + r0) * 128 + c];
            float2 h1 = *(const float2*)&hef[(size_t)(me0 + r0 + 8) * 128 + c];
            float2 e0, e1;
            e0.x = fmaf(g0, acc[mf][nf][0] - h0.x, h0.x);
            e0.y = fmaf(g0, acc[mf][nf][1] - h0.y, h0.y);
            e1.x = fmaf(g1, acc[mf][nf][2] - h1.x, h1.x);
            e1.y = fmaf(g1, acc[mf][nf][3] - h1.y, h1.y);
            *(float2*)&out[(size_t)(me0 + r0) * 128 + c] = e0;
            *(float2*)&out[(size_t)(me0 + r0 + 8) * 128 + c] = e1;
            float2 wr = *(const float2*)&Wread[256 + c];
            float p0 = e0.x * wr.x + e0.y * wr.y;
            float p1 = e1.x * wr.x + e1.y * wr.y;
            if (mf == 0) { s0 += p0; s1 += p1; } else { s2 += p0; s3 += p1; }
        }
    }
    s0 += __shfl_xor_sync(0xffffffffu, s0, 1); s0 += __shfl_xor_sync(0xffffffffu, s0, 2);
    s1 += __shfl_xor_sync(0xffffffffu, s1, 1); s1 += __shfl_xor_sync(0xffffffffu, s1, 2);
    s2 += __shfl_xor_sync(0xffffffffu, s2, 1); s2 += __shfl_xor_sync(0xffffffffu, s2, 2);
    s3 += __shfl_xor_sync(0xffffffffu, s3, 1); s3 += __shfl_xor_sync(0xffffffffu, s3, 2);
    if (quad == 0) {
        int nh = w >> 2;
        sred[(wm + grp) * 2 + nh] = s0;
        sred[(wm + 8 + grp) * 2 + nh] = s1;
        sred[(wm + 16 + grp) * 2 + nh] = s2;
        sred[(wm + 24 + grp) * 2 + nh] = s3;
    }
    __syncthreads();
    if (t < 128) {
        int e = me0 + t, r = srol[t], c = scol[t];
        float tot = sred[t * 2] + sred[t * 2 + 1];
        float rl = tot + g_eproj[e * 2 + 1] + g_nproj[r * 8 + 4] + g_nproj[c * 8 + 5] + bread[0];
        g_rw[e] = expf(rl);   // no-max readout softmax
    }
}

// ---------------- readout: unnormalized scatter + segment sum ----------------
__global__ void k_rscatter(const int* __restrict__ ei, const int* __restrict__ batch,
                           const float* __restrict__ out) {
    __shared__ float sacc[NG * DE];   // 32 KB
    __shared__ float ssum[NG];
    int t = threadIdx.x;
    for (int i = t; i < NG * DE; i += 256) sacc[i] = 0.f;
    if (t < NG) ssum[t] = 0.f;
    __syncthreads();
    int warp = t >> 5, lane = t & 31;
    for (int e = blockIdx.x * 8 + warp; e < NE; e += gridDim.x * 8) {
        int gi = batch[ei[e]];
        float rw = g_rw[e];
        float4 ef = ((const float4*)out)[e * 32 + lane];
        float* p = &sacc[gi * 128 + lane * 4];
        atomicAdd(p + 0, rw * ef.x);
        atomicAdd(p + 1, rw * ef.y);
        atomicAdd(p + 2, rw * ef.z);
        atomicAdd(p + 3, rw * ef.w);
        if (lane == 0) atomicAdd(&ssum[gi], rw);
    }
    __syncthreads();
    for (int i = t; i < NG * DE; i += 256)
        if (sacc[i] != 0.f) atomicAdd(&g_graphfeat[i], sacc[i]);
    if (t < NG && ssum[t] != 0.f) atomicAdd(&g_gsum[t], ssum[t]);
}

// ---------------- confidence (normalize here) ----------------
__global__ void k_conf(const float* __restrict__ Wscore, const float* __restrict__ bscore,
                       float* __restrict__ out) {
    int g = blockIdx.x, t = threadIdx.x;
    float v = g_graphfeat[g * 128 + t] / (g_gsum[g] + 1e-16f) * Wscore[t];
    v = wred(v);
    __shared__ float sm[4];
    if ((t & 31) == 0) sm[t >> 5] = v;
    __syncthreads();
    if (t == 0) {
        float s = sm[0] + sm[1] + sm[2] + sm[3] + bscore[0];
        out[(size_t)NE * DE + g] = 1.f / (1.f + expf(-s));
    }
}

// ---------------- launch ----------------
extern "C" void kernel_launch(void* const* d_in, const int* in_sizes, int n_in,
                              void* d_out, int out_size) {
    const float* x      = (const float*)d_in[0];
    const float* hef    = (const float*)d_in[1];
    const float* attr   = (const float*)d_in[2];
    const int*   ei     = (const int*)d_in[3];
    const int*   batch  = (const int*)d_in[4];
    const float* Wagg   = (const float*)d_in[6];
    const float* bagg   = (const float*)d_in[7];
    const float* W1     = (const float*)d_in[8];
    const float* b1     = (const float*)d_in[9];
    const float* W2     = (const float*)d_in[10];
    const float* b2     = (const float*)d_in[11];
    const float* Wupd   = (const float*)d_in[12];
    const float* bupd   = (const float*)d_in[13];
    const float* Wread  = (const float*)d_in[14];
    const float* bread  = (const float*)d_in[15];
    const float* Wscore = (const float*)d_in[16];
    const float* bscore = (const float*)d_in[17];
    float* out = (float*)d_out;

    static bool attr_set = false;
    if (!attr_set) {
        cudaFuncSetAttribute(k_gemm1, cudaFuncAttributeMaxDynamicSharedMemorySize, G1_WORDS * 4);
        cudaFuncSetAttribute(k_gemm2f, cudaFuncAttributeMaxDynamicSharedMemorySize, G2_WORDS * 4);
        attr_set = true;
    }

    k_init<<<(NN * DE + 255) / 256, 256>>>();
    k_xsplit<<<(NE * 8 + 255) / 256, 256>>>(x, attr);
    k_wsplit<<<(256 * 264 + 255) / 256, 256>>>(W1, W2);
    k_nodeproj<<<(NN + 7) / 8, 256>>>(x, Wagg, Wupd, Wread);
    k_aggscatter<<<NE / 8, 256>>>(hef, attr, ei, Wagg, bagg, Wupd, Wread);
    k_nnorm<<<(NN * 64 + 255) / 256, 256>>>();
    k_gemm1<<<dim3(NE / 128, 2), 256, G1_WORDS * 4>>>(ei, b1);
    k_gemm2f<<<NE / 128, 256, G2_WORDS * 4>>>(hef, ei, b2, Wupd, bupd,
                                              Wread, bread, out);
    k_rscatter<<<296, 256>>>(ei, batch, out);
    k_conf<<<NG, 128>>>(Wscore, bscore, out);
}

// round 13
// speedup vs baseline: 3.4736x; 1.2950x over previous
#include <cuda_runtime.h>
#include <cuda_fp16.h>
#include <stdint.h>

#define NN 20000
#define NE 320000
#define DN 128
#define DE 128
#define DA 16
#define NH 256
#define NG 64
#define K1TOT 528
#define ST 12              // smem row stride in u32 words (8 used + 4 pad)

// ---------------- scratch ----------------
__device__ float g_nproj[NN * 8];
__device__ float g_eproj[NE * 2];
__device__ float g_nsum[NN];
__device__ float g_nodefeat[NN * DE];
__device__ uint32_t g_xh[NN * 64];                        // x fp16x2 [n][kpair]
__device__ uint32_t g_nfh[NN * 64];                       // node_feat fp16x2
__device__ uint32_t g_ath[NE * 8];                        // attr fp16x2
__device__ uint32_t g_w1h[256 * 264];                     // W1 fp16, [n][kpair] (incl attr rows kp 256..263)
__device__ uint32_t g_w2h[128 * 128];                     // W2 fp16, [n][kpair]
__device__ uint32_t g_pnh[NN * 256];                      // node proj: [n][kp] kp0..127=Pr, 128..255=Pc (fp16x2)
__device__ uint32_t g_hh[40960000];                       // hidden fp16x2 [m][kpair]
__device__ float g_rw[NE];
__device__ float g_gsum[NG];
__device__ float g_graphfeat[NG * DE];

// ---------------- helpers ----------------
__device__ __forceinline__ float dot4(float4 a, float4 b) {
    return fmaf(a.x, b.x, fmaf(a.y, b.y, fmaf(a.z, b.z, a.w * b.w)));
}

__device__ __forceinline__ float wred(float v) {
    v += __shfl_xor_sync(0xffffffffu, v, 16);
    v += __shfl_xor_sync(0xffffffffu, v, 8);
    v += __shfl_xor_sync(0xffffffffu, v, 4);
    v += __shfl_xor_sync(0xffffffffu, v, 2);
    v += __shfl_xor_sync(0xffffffffu, v, 1);
    return v;
}

__device__ __forceinline__ uint32_t packhi16(float f0, float f1) {
    __half2 h = __floats2half2_rn(f0, f1);
    return *(uint32_t*)&h;
}

__device__ __forceinline__ void mma16f(float* c, const uint32_t* a, uint32_t b0, uint32_t b1) {
    asm volatile("mma.sync.aligned.m16n8k16.row.col.f32.f16.f16.f32 "
        "{%0,%1,%2,%3}, {%4,%5,%6,%7}, {%8,%9}, {%0,%1,%2,%3};"
        : "+f"(c[0]), "+f"(c[1]), "+f"(c[2]), "+f"(c[3])
        : "r"(a[0]), "r"(a[1]), "r"(a[2]), "r"(a[3]), "r"(b0), "r"(b1));
}

__device__ __forceinline__ void ldsm4(uint32_t* r, uint32_t addr) {
    asm volatile("ldmatrix.sync.aligned.m8n8.x4.shared.b16 {%0,%1,%2,%3}, [%4];"
        : "=r"(r[0]), "=r"(r[1]), "=r"(r[2]), "=r"(r[3]) : "r"(addr));
}

__device__ __forceinline__ void cpa16(uint32_t dst, const void* src) {
    asm volatile("cp.async.cg.shared.global [%0], [%1], 16;" :: "r"(dst), "l"(src) : "memory");
}
#define CP_COMMIT() asm volatile("cp.async.commit_group;" ::: "memory")
#define CP_WAIT0()  asm volatile("cp.async.wait_group 0;" ::: "memory")

// ---------------- init ----------------
__global__ void k_init() {
    int i = blockIdx.x * 256 + threadIdx.x;
    if (i < NN * DE) g_nodefeat[i] = 0.f;
    if (i < NN) g_nsum[i] = 0.f;
    if (i < NG * DE) g_graphfeat[i] = 0.f;
    if (i < NG) g_gsum[i] = 0.f;
}

// ---------------- one-time packs: x, attr ----------------
__global__ void k_xsplit(const float* __restrict__ x, const float* __restrict__ attr) {
    int i = blockIdx.x * 256 + threadIdx.x;
    if (i < NN * 64)
        g_xh[i] = packhi16(x[2 * i], x[2 * i + 1]);
    if (i < NE * 8)
        g_ath[i] = packhi16(attr[2 * i], attr[2 * i + 1]);
}

// ---------------- one-time weight fp16 pack (transposed [n][kp]) ----------------
__global__ void k_wsplit(const float* __restrict__ W1, const float* __restrict__ W2) {
    int i = blockIdx.x * 256 + threadIdx.x;
    if (i < 256 * 264) {
        int n = i / 264, kp = i % 264;
        g_w1h[i] = packhi16(W1[(2 * kp) * 256 + n], W1[(2 * kp + 1) * 256 + n]);
    }
    if (i < 128 * 128) {
        int n = i >> 7, kp = i & 127;
        g_w2h[i] = packhi16(W2[(2 * kp) * 128 + n], W2[(2 * kp + 1) * 128 + n]);
    }
}

// ---------------- per-node scalar projections ----------------
__global__ void k_nodeproj(const float* __restrict__ x, const float* __restrict__ Wagg,
                           const float* __restrict__ Wupd, const float* __restrict__ Wread) {
    int warp = threadIdx.x >> 5, lane = threadIdx.x & 31;
    int n = blockIdx.x * 8 + warp;
    if (n >= NN) return;
    float4 xv = ((const float4*)x)[n * 32 + lane];
    const float4* wa = (const float4*)Wagg;
    const float4* wu = (const float4*)Wupd;
    const float4* wr = (const float4*)Wread;
    float s0 = dot4(xv, wa[lane]);
    float s1 = dot4(xv, wa[32 + lane]);
    float s2 = dot4(xv, wu[lane]);
    float s3 = dot4(xv, wu[32 + lane]);
    float s4 = dot4(xv, wr[lane]);
    float s5 = dot4(xv, wr[32 + lane]);
    s0 = wred(s0); s1 = wred(s1); s2 = wred(s2);
    s3 = wred(s3); s4 = wred(s4); s5 = wred(s5);
    if (lane == 0) {
        g_nproj[n * 8 + 0] = s0; g_nproj[n * 8 + 1] = s1;
        g_nproj[n * 8 + 2] = s2; g_nproj[n * 8 + 3] = s3;
        g_nproj[n * 8 + 4] = s4; g_nproj[n * 8 + 5] = s5;
    }
}

// ---------------- agg logit + exp + scatter + attr projections (ONE pass) ----------------
__global__ void k_aggscatter(const float* __restrict__ hef, const float* __restrict__ attr,
                             const int* __restrict__ ei, const float* __restrict__ Wagg,
                             const float* __restrict__ bagg, const float* __restrict__ Wupd,
                             const float* __restrict__ Wread) {
    int warp = threadIdx.x >> 5, lane = threadIdx.x & 31;
    int e = blockIdx.x * 8 + warp;
    if (e >= NE) return;
    int r = ei[e], c = ei[NE + e];
    float4 h4 = ((const float4*)hef)[e * 32 + lane];
    float4 wh = *(const float4*)&Wagg[272 + lane * 4];
    float p = dot4(h4, wh);
    float pu = 0.f, pr = 0.f;
    if (lane < 4) {
        float4 a4 = ((const float4*)attr)[e * 4 + lane];
        p += dot4(a4, *(const float4*)&Wagg[256 + lane * 4]);
        pu = dot4(a4, *(const float4*)&Wupd[256 + lane * 4]);
        pr = dot4(a4, *(const float4*)&Wread[384 + lane * 4]);
    }
    p = wred(p); pu = wred(pu); pr = wred(pr);
    float w;
    if (lane == 0) {
        float logit = p + g_nproj[r * 8 + 0] + g_nproj[c * 8 + 1] + bagg[0];
        w = expf(logit);     // no-max softmax: logits O(1), no overflow risk
        g_eproj[e * 2 + 0] = pu;
        g_eproj[e * 2 + 1] = pr;
        atomicAdd(&g_nsum[c], w);
    }
    w = __shfl_sync(0xffffffffu, w, 0);
    float* ptr = &g_nodefeat[c * 128 + lane * 4];
    asm volatile("red.global.add.v4.f32 [%0], {%1,%2,%3,%4};"
        :: "l"(ptr), "f"(w * h4.x), "f"(w * h4.y), "f"(w * h4.z), "f"(w * h4.w)
        : "memory");
}

// ---------------- normalize node_feat + pack fp16 ----------------
__global__ void k_nnorm() {
    int i = blockIdx.x * 256 + threadIdx.x;
    if (i >= NN * 64) return;
    int n = i >> 6;
    float inv = 1.f / (g_nsum[n] + 1e-16f);
    g_nfh[i] = packhi16(g_nodefeat[2 * i] * inv, g_nodefeat[2 * i + 1] * inv);
}

// ==================== NODE GEMM: P[n] = [x|nf][n] @ [W1[0:256] | W1[256:512]] ====================
// M=NN (157 blocks of 128, guarded), K=256 (16 k-tiles), N=512 (grid.y=4).
#define NGM_WORDS 6144

__global__ void __launch_bounds__(256, 2)
k_nodegemm() {
    extern __shared__ uint32_t sm_[];
    int t = threadIdx.x;
    int mb0 = blockIdx.x * 128, hn0 = blockIdx.y * 128;   // hn0 in 0..511 step 128

    int am = t >> 1, sw = (t & 1) * 4;
    int lane = t & 31, w = t >> 5;
    int wm = (w & 3) * 32, wn = (w >> 2) * 64;
    int grp = lane >> 2, quad = lane & 3;

    int n = mb0 + am; if (n >= NN) n = NN - 1;            // clamp gather (pad rows unused)
    int np = hn0 + am;                                    // output column (0..511)
    const uint32_t* bptr = (np < 256) ? (g_w1h + (size_t)np * 264)
                                      : (g_w1h + (size_t)(np - 256) * 264 + 128);

    uint32_t smb = (uint32_t)__cvta_generic_to_shared(sm_);
    int arow = wm + (lane & 15);
    uint32_t rA = smb + arow * (ST * 4) + ((lane & 16) ? 16 : 0);
    int brow = wn + (lane & 7) + ((lane & 16) ? 8 : 0);
    uint32_t rB = smb + 3072 * 4 + brow * (ST * 4) + ((lane & 8) ? 16 : 0);
    const uint32_t BUFB  = 1536 * 4;
    const uint32_t BHOFF = 3072 * 4;

    auto stage = [&](int kt, int buf) {
        int kp = kt * 8 + sw;                              // 0..127
        const uint32_t* pa = (kp < 64) ? (g_xh + (size_t)n * 64 + kp)
                                       : (g_nfh + (size_t)n * 64 + kp - 64);
        uint32_t d = smb + (buf * 1536 + am * ST + sw) * 4;
        cpa16(d, pa);
        cpa16(d + BHOFF, bptr + kp);
    };

    stage(0, 0);
    CP_COMMIT();
    CP_WAIT0();
    __syncthreads();

    float acc[2][8][4];
#pragma unroll
    for (int i = 0; i < 2; i++)
#pragma unroll
        for (int j = 0; j < 8; j++)
#pragma unroll
            for (int k = 0; k < 4; k++) acc[i][j][k] = 0.f;

    const int KT = 16;
    for (int kt = 0; kt < KT; ++kt) {
        int cur = kt & 1;
        if (kt < KT - 1) {
            stage(kt + 1, cur ^ 1);
            CP_COMMIT();
        }
        uint32_t aH[2][4];
#pragma unroll
        for (int mf = 0; mf < 2; mf++)
            ldsm4(aH[mf], rA + cur * BUFB + mf * (16 * ST * 4));
#pragma unroll
        for (int j = 0; j < 4; j++) {
            uint32_t bH[4];
            ldsm4(bH, rB + cur * BUFB + j * (16 * ST * 4));
#pragma unroll
            for (int mf = 0; mf < 2; mf++) {
                mma16f(acc[mf][2 * j],     aH[mf], bH[0], bH[1]);
                mma16f(acc[mf][2 * j + 1], aH[mf], bH[2], bH[3]);
            }
        }
        if (kt < KT - 1) CP_WAIT0();
        __syncthreads();
    }

    // epilogue: pack fp16, write g_pnh (guard pad rows)
#pragma unroll
    for (int mf = 0; mf < 2; mf++) {
        int m = mb0 + wm + mf * 16 + grp;
#pragma unroll
        for (int nf = 0; nf < 8; nf++) {
            int c0 = hn0 + wn + nf * 8 + quad * 2;        // 0..511
            int kp = c0 >> 1;                              // 0..255
            if (m < NN)
                g_pnh[(size_t)m * 256 + kp] = packhi16(acc[mf][nf][0], acc[mf][nf][1]);
            if (m + 8 < NN)
                g_pnh[(size_t)(m + 8) * 256 + kp] = packhi16(acc[mf][nf][2], acc[mf][nf][3]);
        }
    }
}

// ==================== HBUILD: hidden = relu(attr@W1e + Pr[rol] + Pc[col] + b1) ====================
// smem words: A 1536 @0, B 1536 @1536, srol @3072, scol @3200
#define HB_WORDS 3328

__global__ void __launch_bounds__(256, 2)
k_hbuild(const int* __restrict__ ei, const float* __restrict__ b1) {
    extern __shared__ uint32_t sm_[];
    int* srol = (int*)(sm_ + 3072);
    int* scol = srol + 128;

    int t = threadIdx.x;
    int me0 = blockIdx.x * 128, hn0 = blockIdx.y * 128;   // hidden col block (0 or 128)
    if (t < 128) srol[t] = ei[me0 + t];
    else scol[t - 128] = ei[NE + me0 + t - 128];

    int am = t >> 1, sw = (t & 1) * 4;
    int lane = t & 31, w = t >> 5;
    int wm = (w & 3) * 32, wn = (w >> 2) * 64;
    int grp = lane >> 2, quad = lane & 3;

    uint32_t smb = (uint32_t)__cvta_generic_to_shared(sm_);
    int arow = wm + (lane & 15);
    uint32_t rA = smb + arow * (ST * 4) + ((lane & 16) ? 16 : 0);
    int brow = wn + (lane & 7) + ((lane & 16) ? 8 : 0);
    uint32_t rB = smb + 1536 * 4 + brow * (ST * 4) + ((lane & 8) ? 16 : 0);

    // stage attr (A) and W1 attr rows (B, kpairs 256..263)
    {
        uint32_t d = smb + (am * ST + sw) * 4;
        cpa16(d, g_ath + (size_t)(me0 + am) * 8 + sw);
        cpa16(d + 1536 * 4, g_w1h + (size_t)(hn0 + am) * 264 + 256 + sw);
    }
    CP_COMMIT();
    CP_WAIT0();
    __syncthreads();

    float acc[2][8][4];
#pragma unroll
    for (int i = 0; i < 2; i++)
#pragma unroll
        for (int j = 0; j < 8; j++)
#pragma unroll
            for (int k = 0; k < 4; k++) acc[i][j][k] = 0.f;

    uint32_t aH[2][4];
#pragma unroll
    for (int mf = 0; mf < 2; mf++)
        ldsm4(aH[mf], rA + mf * (16 * ST * 4));
#pragma unroll
    for (int j = 0; j < 4; j++) {
        uint32_t bH[4];
        ldsm4(bH, rB + j * (16 * ST * 4));
#pragma unroll
        for (int mf = 0; mf < 2; mf++) {
            mma16f(acc[mf][2 * j],     aH[mf], bH[0], bH[1]);
            mma16f(acc[mf][2 * j + 1], aH[mf], bH[2], bH[3]);
        }
    }

    // epilogue: + Pr[rol] + Pc[col] + b1, relu, pack, store g_hh
#pragma unroll
    for (int mf = 0; mf < 2; mf++) {
        int ml0 = wm + mf * 16 + grp;
        int r0 = srol[ml0], c0n = scol[ml0];
        int r1 = srol[ml0 + 8], c1n = scol[ml0 + 8];
#pragma unroll
        for (int nf = 0; nf < 8; nf++) {
            int c = hn0 + wn + nf * 8 + quad * 2;          // 0..255
            int kp = c >> 1;
            float2 bb = *(const float2*)&b1[c];
            float2 pr0 = __half22float2(*(const __half2*)&g_pnh[(size_t)r0 * 256 + kp]);
            float2 pc0 = __half22float2(*(const __half2*)&g_pnh[(size_t)c0n * 256 + 128 + kp]);
            float v0 = fmaxf(acc[mf][nf][0] + pr0.x + pc0.x + bb.x, 0.f);
            float v1 = fmaxf(acc[mf][nf][1] + pr0.y + pc0.y + bb.y, 0.f);
            g_hh[(size_t)(me0 + ml0) * 128 + kp] = packhi16(v0, v1);
            float2 pr1 = __half22float2(*(const __half2*)&g_pnh[(size_t)r1 * 256 + kp]);
            float2 pc1 = __half22float2(*(const __half2*)&g_pnh[(size_t)c1n * 256 + 128 + kp]);
            float v2 = fmaxf(acc[mf][nf][2] + pr1.x + pc1.x + bb.x, 0.f);
            float v3 = fmaxf(acc[mf][nf][3] + pr1.y + pc1.y + bb.y, 0.f);
            g_hh[(size_t)(me0 + ml0 + 8) * 128 + kp] = packhi16(v2, v3);
        }
    }
}

// ==================== GEMM2 fused (plain fp16): cand -> gate -> ef -> readout ====================
// smem words: A @0 (3072), BH @3072, srol @6144, scol @6272, sred @6400, sg @6656
#define G2_WORDS 6784

__global__ void __launch_bounds__(256, 2)
k_gemm2f(const float* __restrict__ hef, const int* __restrict__ ei,
         const float* __restrict__ b2,
         const float* __restrict__ Wupd, const float* __restrict__ bupd,
         const float* __restrict__ Wread, const float* __restrict__ bread,
         float* __restrict__ out) {
    extern __shared__ uint32_t sm_[];
    int*   srol = (int*)(sm_ + 6144);
    int*   scol = (int*)(sm_ + 6272);
    float* sred = (float*)(sm_ + 6400);
    float* sg   = (float*)(sm_ + 6656);

    int t = threadIdx.x;
    int me0 = blockIdx.x * 128;
    if (t < 128) srol[t] = ei[me0 + t];
    else scol[t - 128] = ei[NE + me0 + t - 128];

    int am = t >> 1, sw = (t & 1) * 4;
    int lane = t & 31, w = t >> 5;
    int wm = (w & 3) * 32, wn = (w >> 2) * 64;
    int grp = lane >> 2, quad = lane & 3;

    uint32_t smb = (uint32_t)__cvta_generic_to_shared(sm_);
    int arow = wm + (lane & 15);
    uint32_t rA = smb + arow * (ST * 4) + ((lane & 16) ? 16 : 0);
    int brow = wn + (lane & 7) + ((lane & 16) ? 8 : 0);
    uint32_t rB = smb + 3072 * 4 + brow * (ST * 4) + ((lane & 8) ? 16 : 0);
    const uint32_t BUFB  = 1536 * 4;
    const uint32_t BHOFF = 3072 * 4;

    auto stage = [&](int kt, int buf) {
        int kp = kt * 8 + sw;
        uint32_t d = smb + (buf * 1536 + am * ST + sw) * 4;
        cpa16(d, g_hh + (size_t)(me0 + am) * 128 + kp);
        cpa16(d + BHOFF, g_w2h + (size_t)am * 128 + kp);
    };

    stage(0, 0);
    CP_COMMIT();
    CP_WAIT0();
    __syncthreads();

    float acc[2][8][4];
#pragma unroll
    for (int i = 0; i < 2; i++)
#pragma unroll
        for (int j = 0; j < 8; j++)
#pragma unroll
            for (int k = 0; k < 4; k++) acc[i][j][k] = 0.f;

    const int KT = NH / 16;  // 16
    for (int kt = 0; kt < KT; ++kt) {
        int cur = kt & 1;
        if (kt < KT - 1) {
            stage(kt + 1, cur ^ 1);
            CP_COMMIT();
        }
        uint32_t aH[2][4];
#pragma unroll
        for (int mf = 0; mf < 2; mf++)
            ldsm4(aH[mf], rA + cur * BUFB + mf * (16 * ST * 4));
#pragma unroll
        for (int j = 0; j < 4; j++) {
            uint32_t bH[4];
            ldsm4(bH, rB + cur * BUFB + j * (16 * ST * 4));
#pragma unroll
            for (int mf = 0; mf < 2; mf++) {
                mma16f(acc[mf][2 * j],     aH[mf], bH[0], bH[1]);
                mma16f(acc[mf][2 * j + 1], aH[mf], bH[2], bH[3]);
            }
        }
        if (kt < KT - 1) CP_WAIT0();
        __syncthreads();
    }

    // acc += b2 -> cand
#pragma unroll
    for (int mf = 0; mf < 2; mf++)
#pragma unroll
        for (int nf = 0; nf < 8; nf++) {
            int c0 = wn + nf * 8 + quad * 2;
            float bb0 = b2[c0], bb1 = b2[c0 + 1];
            acc[mf][nf][0] += bb0; acc[mf][nf][1] += bb1;
            acc[mf][nf][2] += bb0; acc[mf][nf][3] += bb1;
        }

    // ---- epilogue pass 1: gate logit dot ----
    float s0 = 0.f, s1 = 0.f, s2 = 0.f, s3 = 0.f;
#pragma unroll
    for (int mf = 0; mf < 2; mf++) {
        int r0 = wm + mf * 16 + grp;
#pragma unroll
        for (int nf = 0; nf < 8; nf++) {
            int c = wn + nf * 8 + quad * 2;
            float2 wc = *(const float2*)&Wupd[400 + c];
            float2 whv = *(const float2*)&Wupd[272 + c];
            float2 h0 = *(const float2*)&hef[(size_t)(me0 + r0) * 128 + c];
            float2 h1 = *(const float2*)&hef[(size_t)(me0 + r0 + 8) * 128 + c];
            float p0 = acc[mf][nf][0] * wc.x + acc[mf][nf][1] * wc.y + h0.x * whv.x + h0.y * whv.y;
            float p1 = acc[mf][nf][2] * wc.x + acc[mf][nf][3] * wc.y + h1.x * whv.x + h1.y * whv.y;
            if (mf == 0) { s0 += p0; s1 += p1; } else { s2 += p0; s3 += p1; }
        }
    }
    s0 += __shfl_xor_sync(0xffffffffu, s0, 1); s0 += __shfl_xor_sync(0xffffffffu, s0, 2);
    s1 += __shfl_xor_sync(0xffffffffu, s1, 1); s1 += __shfl_xor_sync(0xffffffffu, s1, 2);
    s2 += __shfl_xor_sync(0xffffffffu, s2, 1); s2 += __shfl_xor_sync(0xffffffffu, s2, 2);
    s3 += __shfl_xor_sync(0xffffffffu, s3, 1); s3 += __shfl_xor_sync(0xffffffffu, s3, 2);
    if (quad == 0) {
        int nh = w >> 2;
        sred[(wm + grp) * 2 + nh] = s0;
        sred[(wm + 8 + grp) * 2 + nh] = s1;
        sred[(wm + 16 + grp) * 2 + nh] = s2;
        sred[(wm + 24 + grp) * 2 + nh] = s3;
    }
    __syncthreads();
    if (t < 128) {
        int e = me0 + t, r = srol[t], c = scol[t];
        float tot = sred[t * 2] + sred[t * 2 + 1];
        float gv = tot + g_eproj[e * 2] + g_nproj[r * 8 + 2] + g_nproj[c * 8 + 3] + bupd[0];
        sg[t] = 1.f / (1.f + expf(-gv));
    }
    __syncthreads();

    // ---- epilogue pass 2: ef = g*cand + (1-g)*hef, write out, readout dot ----
    s0 = s1 = s2 = s3 = 0.f;
#pragma unroll
    for (int mf = 0; mf < 2; mf++) {
        int r0 = wm + mf * 16 + grp;
        float g0 = sg[r0], g1 = sg[r0 + 8];
#pragma unroll
        for (int nf = 0; nf < 8; nf++) {
            int c = wn + nf * 8 + quad * 2;
            float2 h0 = *(const float2*)&hef[(size_t)(me0 + r0) * 128 + c];
            float2 h1 = *(const float2*)&hef[(size_t)(me0 + r0 + 8) * 128 + c];
            float2 e0, e1;
            e0.x = fmaf(g0, acc[mf][nf][0] - h0.x, h0.x);
            e0.y = fmaf(g0, acc[mf][nf][1] - h0.y, h0.y);
            e1.x = fmaf(g1, acc[mf][nf][2] - h1.x, h1.x);
            e1.y = fmaf(g1, acc[mf][nf][3] - h1.y, h1.y);
            *(float2*)&out[(size_t)(me0 + r0) * 128 + c] = e0;
            *(float2*)&out[(size_t)(me0 + r0 + 8) * 128 + c] = e1;
            float2 wr = *(const float2*)&Wread[256 + c];
            float p0 = e0.x * wr.x + e0.y * wr.y;
            float p1 = e1.x * wr.x + e1.y * wr.y;
            if (mf == 0) { s0 += p0; s1 += p1; } else { s2 += p0; s3 += p1; }
        }
    }
    s0 += __shfl_xor_sync(0xffffffffu, s0, 1); s0 += __shfl_xor_sync(0xffffffffu, s0, 2);
    s1 += __shfl_xor_sync(0xffffffffu, s1, 1); s1 += __shfl_xor_sync(0xffffffffu, s1, 2);
    s2 += __shfl_xor_sync(0xffffffffu, s2, 1); s2 += __shfl_xor_sync(0xffffffffu, s2, 2);
    s3 += __shfl_xor_sync(0xffffffffu, s3, 1); s3 += __shfl_xor_sync(0xffffffffu, s3, 2);
    if (quad == 0) {
        int nh = w >> 2;
        sred[(wm + grp) * 2 + nh] = s0;
        sred[(wm + 8 + grp) * 2 + nh] = s1;
        sred[(wm + 16 + grp) * 2 + nh] = s2;
        sred[(wm + 24 + grp) * 2 + nh] = s3;
    }
    __syncthreads();
    if (t < 128) {
        int e = me0 + t, r = srol[t], c = scol[t];
        float tot = sred[t * 2] + sred[t * 2 + 1];
        float rl = tot + g_eproj[e * 2 + 1] + g_nproj[r * 8 + 4] + g_nproj[c * 8 + 5] + bread[0];
        g_rw[e] = expf(rl);   // no-max readout softmax
    }
}

// ---------------- readout: unnormalized scatter + segment sum ----------------
__global__ void k_rscatter(const int* __restrict__ ei, const int* __restrict__ batch,
                           const float* __restrict__ out) {
    __shared__ float sacc[NG * DE];   // 32 KB
    __shared__ float ssum[NG];
    int t = threadIdx.x;
    for (int i = t; i < NG * DE; i += 256) sacc[i] = 0.f;
    if (t < NG) ssum[t] = 0.f;
    __syncthreads();
    int warp = t >> 5, lane = t & 31;
    for (int e = blockIdx.x * 8 + warp; e < NE; e += gridDim.x * 8) {
        int gi = batch[ei[e]];
        float rw = g_rw[e];
        float4 ef = ((const float4*)out)[e * 32 + lane];
        float* p = &sacc[gi * 128 + lane * 4];
        atomicAdd(p + 0, rw * ef.x);
        atomicAdd(p + 1, rw * ef.y);
        atomicAdd(p + 2, rw * ef.z);
        atomicAdd(p + 3, rw * ef.w);
        if (lane == 0) atomicAdd(&ssum[gi], rw);
    }
    __syncthreads();
    for (int i = t; i < NG * DE; i += 256)
        if (sacc[i] != 0.f) atomicAdd(&g_graphfeat[i], sacc[i]);
    if (t < NG && ssum[t] != 0.f) atomicAdd(&g_gsum[t], ssum[t]);
}

// ---------------- confidence (normalize here) ----------------
__global__ void k_conf(const float* __restrict__ Wscore, const float* __restrict__ bscore,
                       float* __restrict__ out) {
    int g = blockIdx.x, t = threadIdx.x;
    float v = g_graphfeat[g * 128 + t] / (g_gsum[g] + 1e-16f) * Wscore[t];
    v = wred(v);
    __shared__ float sm[4];
    if ((t & 31) == 0) sm[t >> 5] = v;
    __syncthreads();
    if (t == 0) {
        float s = sm[0] + sm[1] + sm[2] + sm[3] + bscore[0];
        out[(size_t)NE * DE + g] = 1.f / (1.f + expf(-s));
    }
}

// ---------------- launch ----------------
extern "C" void kernel_launch(void* const* d_in, const int* in_sizes, int n_in,
                              void* d_out, int out_size) {
    const float* x      = (const float*)d_in[0];
    const float* hef    = (const float*)d_in[1];
    const float* attr   = (const float*)d_in[2];
    const int*   ei     = (const int*)d_in[3];
    const int*   batch  = (const int*)d_in[4];
    const float* Wagg   = (const float*)d_in[6];
    const float* bagg   = (const float*)d_in[7];
    const float* W1     = (const float*)d_in[8];
    const float* b1     = (const float*)d_in[9];
    const float* W2     = (const float*)d_in[10];
    const float* b2     = (const float*)d_in[11];
    const float* Wupd   = (const float*)d_in[12];
    const float* bupd   = (const float*)d_in[13];
    const float* Wread  = (const float*)d_in[14];
    const float* bread  = (const float*)d_in[15];
    const float* Wscore = (const float*)d_in[16];
    const float* bscore = (const float*)d_in[17];
    float* out = (float*)d_out;

    static bool attr_set = false;
    if (!attr_set) {
        cudaFuncSetAttribute(k_nodegemm, cudaFuncAttributeMaxDynamicSharedMemorySize, NGM_WORDS * 4);
        cudaFuncSetAttribute(k_hbuild, cudaFuncAttributeMaxDynamicSharedMemorySize, HB_WORDS * 4);
        cudaFuncSetAttribute(k_gemm2f, cudaFuncAttributeMaxDynamicSharedMemorySize, G2_WORDS * 4);
        attr_set = true;
    }

    k_init<<<(NN * DE + 255) / 256, 256>>>();
    k_xsplit<<<(NE * 8 + 255) / 256, 256>>>(x, attr);
    k_wsplit<<<(256 * 264 + 255) / 256, 256>>>(W1, W2);
    k_nodeproj<<<(NN + 7) / 8, 256>>>(x, Wagg, Wupd, Wread);
    k_aggscatter<<<NE / 8, 256>>>(hef, attr, ei, Wagg, bagg, Wupd, Wread);
    k_nnorm<<<(NN * 64 + 255) / 256, 256>>>();
    k_nodegemm<<<dim3((NN + 127) / 128, 4), 256, NGM_WORDS * 4>>>();
    k_hbuild<<<dim3(NE / 128, 2), 256, HB_WORDS * 4>>>(ei, b1);
    k_gemm2f<<<NE / 128, 256, G2_WORDS * 4>>>(hef, ei, b2, Wupd, bupd,
                                              Wread, bread, out);
    k_rscatter<<<296, 256>>>(ei, batch, out);
    k_conf<<<NG, 128>>>(Wscore, bscore, out);
}

// round 14
// speedup vs baseline: 4.3219x; 1.2442x over previous
#include <cuda_runtime.h>
#include <cuda_fp16.h>
#include <stdint.h>

#define NN 20000
#define NE 320000
#define DN 128
#define DE 128
#define DA 16
#define NH 256
#define NG 64
#define ST 12              // staging row stride in u32 words (8 used + 4 pad)
#define HST 132            // hidden smem row stride in words (128 + 4)

// ---------------- scratch ----------------
__device__ float g_nproj[NN * 8];
__device__ float g_eproj[NE * 2];
__device__ float g_nsum[NN];
__device__ float g_nodefeat[NN * DE];
__device__ uint32_t g_xh[NN * 64];                        // x fp16x2 [n][kpair]
__device__ uint32_t g_nfh[NN * 64];                       // node_feat fp16x2
__device__ uint32_t g_ath[NE * 8];                        // attr fp16x2
__device__ uint32_t g_w1h[256 * 264];                     // W1 fp16, [n][kpair]
__device__ uint32_t g_w2h[128 * 128];                     // W2 fp16, [n][kpair]
__device__ uint32_t g_pnh[NN * 256];                      // node proj fp16x2: kp0..127=Pr, 128..255=Pc
__device__ float g_rw[NE];
__device__ float g_gsum[NG];
__device__ float g_graphfeat[NG * DE];

// ---------------- helpers ----------------
__device__ __forceinline__ float dot4(float4 a, float4 b) {
    return fmaf(a.x, b.x, fmaf(a.y, b.y, fmaf(a.z, b.z, a.w * b.w)));
}

__device__ __forceinline__ float wred(float v) {
    v += __shfl_xor_sync(0xffffffffu, v, 16);
    v += __shfl_xor_sync(0xffffffffu, v, 8);
    v += __shfl_xor_sync(0xffffffffu, v, 4);
    v += __shfl_xor_sync(0xffffffffu, v, 2);
    v += __shfl_xor_sync(0xffffffffu, v, 1);
    return v;
}

__device__ __forceinline__ uint32_t packhi16(float f0, float f1) {
    __half2 h = __floats2half2_rn(f0, f1);
    return *(uint32_t*)&h;
}

__device__ __forceinline__ void mma16f(float* c, const uint32_t* a, uint32_t b0, uint32_t b1) {
    asm volatile("mma.sync.aligned.m16n8k16.row.col.f32.f16.f16.f32 "
        "{%0,%1,%2,%3}, {%4,%5,%6,%7}, {%8,%9}, {%0,%1,%2,%3};"
        : "+f"(c[0]), "+f"(c[1]), "+f"(c[2]), "+f"(c[3])
        : "r"(a[0]), "r"(a[1]), "r"(a[2]), "r"(a[3]), "r"(b0), "r"(b1));
}

__device__ __forceinline__ void ldsm4(uint32_t* r, uint32_t addr) {
    asm volatile("ldmatrix.sync.aligned.m8n8.x4.shared.b16 {%0,%1,%2,%3}, [%4];"
        : "=r"(r[0]), "=r"(r[1]), "=r"(r[2]), "=r"(r[3]) : "r"(addr));
}

__device__ __forceinline__ void cpa16(uint32_t dst, const void* src) {
    asm volatile("cp.async.cg.shared.global [%0], [%1], 16;" :: "r"(dst), "l"(src) : "memory");
}
#define CP_COMMIT() asm volatile("cp.async.commit_group;" ::: "memory")
#define CP_WAIT0()  asm volatile("cp.async.wait_group 0;" ::: "memory")

// ---------------- prep: init scratch + pack x/attr + pack weights ----------------
__global__ void k_prep(const float* __restrict__ x, const float* __restrict__ attr,
                       const float* __restrict__ W1, const float* __restrict__ W2) {
    int i = blockIdx.x * 256 + threadIdx.x;
    if (i < NN * DE) g_nodefeat[i] = 0.f;
    if (i < NN) g_nsum[i] = 0.f;
    if (i < NG * DE) g_graphfeat[i] = 0.f;
    if (i < NG) g_gsum[i] = 0.f;
    if (i < NN * 64)
        g_xh[i] = packhi16(x[2 * i], x[2 * i + 1]);
    if (i < NE * 8)
        g_ath[i] = packhi16(attr[2 * i], attr[2 * i + 1]);
    if (i < 256 * 264) {
        int n = i / 264, kp = i % 264;
        g_w1h[i] = packhi16(W1[(2 * kp) * 256 + n], W1[(2 * kp + 1) * 256 + n]);
    }
    if (i < 128 * 128) {
        int n = i >> 7, kp = i & 127;
        g_w2h[i] = packhi16(W2[(2 * kp) * 128 + n], W2[(2 * kp + 1) * 128 + n]);
    }
}

// ---------------- per-node scalar projections ----------------
__global__ void k_nodeproj(const float* __restrict__ x, const float* __restrict__ Wagg,
                           const float* __restrict__ Wupd, const float* __restrict__ Wread) {
    int warp = threadIdx.x >> 5, lane = threadIdx.x & 31;
    int n = blockIdx.x * 8 + warp;
    if (n >= NN) return;
    float4 xv = ((const float4*)x)[n * 32 + lane];
    const float4* wa = (const float4*)Wagg;
    const float4* wu = (const float4*)Wupd;
    const float4* wr = (const float4*)Wread;
    float s0 = dot4(xv, wa[lane]);
    float s1 = dot4(xv, wa[32 + lane]);
    float s2 = dot4(xv, wu[lane]);
    float s3 = dot4(xv, wu[32 + lane]);
    float s4 = dot4(xv, wr[lane]);
    float s5 = dot4(xv, wr[32 + lane]);
    s0 = wred(s0); s1 = wred(s1); s2 = wred(s2);
    s3 = wred(s3); s4 = wred(s4); s5 = wred(s5);
    if (lane == 0) {
        g_nproj[n * 8 + 0] = s0; g_nproj[n * 8 + 1] = s1;
        g_nproj[n * 8 + 2] = s2; g_nproj[n * 8 + 3] = s3;
        g_nproj[n * 8 + 4] = s4; g_nproj[n * 8 + 5] = s5;
    }
}

// ---------------- agg logit + exp + scatter + attr projections ----------------
__global__ void k_aggscatter(const float* __restrict__ hef, const float* __restrict__ attr,
                             const int* __restrict__ ei, const float* __restrict__ Wagg,
                             const float* __restrict__ bagg, const float* __restrict__ Wupd,
                             const float* __restrict__ Wread) {
    int warp = threadIdx.x >> 5, lane = threadIdx.x & 31;
    int e = blockIdx.x * 8 + warp;
    if (e >= NE) return;
    int r = ei[e], c = ei[NE + e];
    float4 h4 = ((const float4*)hef)[e * 32 + lane];
    float4 wh = *(const float4*)&Wagg[272 + lane * 4];
    float p = dot4(h4, wh);
    float pu = 0.f, pr = 0.f;
    if (lane < 4) {
        float4 a4 = ((const float4*)attr)[e * 4 + lane];
        p += dot4(a4, *(const float4*)&Wagg[256 + lane * 4]);
        pu = dot4(a4, *(const float4*)&Wupd[256 + lane * 4]);
        pr = dot4(a4, *(const float4*)&Wread[384 + lane * 4]);
    }
    p = wred(p); pu = wred(pu); pr = wred(pr);
    float w;
    if (lane == 0) {
        float logit = p + g_nproj[r * 8 + 0] + g_nproj[c * 8 + 1] + bagg[0];
        w = expf(logit);
        g_eproj[e * 2 + 0] = pu;
        g_eproj[e * 2 + 1] = pr;
        atomicAdd(&g_nsum[c], w);
    }
    w = __shfl_sync(0xffffffffu, w, 0);
    float* ptr = &g_nodefeat[c * 128 + lane * 4];
    asm volatile("red.global.add.v4.f32 [%0], {%1,%2,%3,%4};"
        :: "l"(ptr), "f"(w * h4.x), "f"(w * h4.y), "f"(w * h4.z), "f"(w * h4.w)
        : "memory");
}

// ---------------- normalize node_feat + pack fp16 ----------------
__global__ void k_nnorm() {
    int i = blockIdx.x * 256 + threadIdx.x;
    if (i >= NN * 64) return;
    int n = i >> 6;
    float inv = 1.f / (g_nsum[n] + 1e-16f);
    g_nfh[i] = packhi16(g_nodefeat[2 * i] * inv, g_nodefeat[2 * i + 1] * inv);
}

// ==================== NODE GEMM: P[n] = [x|nf][n] @ [W1[0:256] | W1[256:512]] ====================
#define NGM_WORDS 6144

__global__ void __launch_bounds__(256, 2)
k_nodegemm() {
    extern __shared__ uint32_t sm_[];
    int t = threadIdx.x;
    int mb0 = blockIdx.x * 128, hn0 = blockIdx.y * 128;

    int am = t >> 1, sw = (t & 1) * 4;
    int lane = t & 31, w = t >> 5;
    int wm = (w & 3) * 32, wn = (w >> 2) * 64;
    int grp = lane >> 2, quad = lane & 3;

    int n = mb0 + am; if (n >= NN) n = NN - 1;
    int np = hn0 + am;
    const uint32_t* bptr = (np < 256) ? (g_w1h + (size_t)np * 264)
                                      : (g_w1h + (size_t)(np - 256) * 264 + 128);

    uint32_t smb = (uint32_t)__cvta_generic_to_shared(sm_);
    int arow = wm + (lane & 15);
    uint32_t rA = smb + arow * (ST * 4) + ((lane & 16) ? 16 : 0);
    int brow = wn + (lane & 7) + ((lane & 16) ? 8 : 0);
    uint32_t rB = smb + 3072 * 4 + brow * (ST * 4) + ((lane & 8) ? 16 : 0);
    const uint32_t BUFB  = 1536 * 4;
    const uint32_t BHOFF = 3072 * 4;

    auto stage = [&](int kt, int buf) {
        int kp = kt * 8 + sw;
        const uint32_t* pa = (kp < 64) ? (g_xh + (size_t)n * 64 + kp)
                                       : (g_nfh + (size_t)n * 64 + kp - 64);
        uint32_t d = smb + (buf * 1536 + am * ST + sw) * 4;
        cpa16(d, pa);
        cpa16(d + BHOFF, bptr + kp);
    };

    stage(0, 0);
    CP_COMMIT();
    CP_WAIT0();
    __syncthreads();

    float acc[2][8][4];
#pragma unroll
    for (int i = 0; i < 2; i++)
#pragma unroll
        for (int j = 0; j < 8; j++)
#pragma unroll
            for (int k = 0; k < 4; k++) acc[i][j][k] = 0.f;

    const int KT = 16;
    for (int kt = 0; kt < KT; ++kt) {
        int cur = kt & 1;
        if (kt < KT - 1) {
            stage(kt + 1, cur ^ 1);
            CP_COMMIT();
        }
        uint32_t aH[2][4];
#pragma unroll
        for (int mf = 0; mf < 2; mf++)
            ldsm4(aH[mf], rA + cur * BUFB + mf * (16 * ST * 4));
#pragma unroll
        for (int j = 0; j < 4; j++) {
            uint32_t bH[4];
            ldsm4(bH, rB + cur * BUFB + j * (16 * ST * 4));
#pragma unroll
            for (int mf = 0; mf < 2; mf++) {
                mma16f(acc[mf][2 * j],     aH[mf], bH[0], bH[1]);
                mma16f(acc[mf][2 * j + 1], aH[mf], bH[2], bH[3]);
            }
        }
        if (kt < KT - 1) CP_WAIT0();
        __syncthreads();
    }

#pragma unroll
    for (int mf = 0; mf < 2; mf++) {
        int m = mb0 + wm + mf * 16 + grp;
#pragma unroll
        for (int nf = 0; nf < 8; nf++) {
            int c0 = hn0 + wn + nf * 8 + quad * 2;
            int kp = c0 >> 1;
            if (m < NN)
                g_pnh[(size_t)m * 256 + kp] = packhi16(acc[mf][nf][0], acc[mf][nf][1]);
            if (m + 8 < NN)
                g_pnh[(size_t)(m + 8) * 256 + kp] = packhi16(acc[mf][nf][2], acc[mf][nf][3]);
        }
    }
}

// ==================== EDGE FUSED: hidden(smem) -> cand -> gate -> ef(out) -> readout ====================
// smem words: SA 1536 @0 | SB 2x1536 @1536 | Hs 128*HST @4608 |
//             srol @21504 scol @21632 sred @21760 sg @22016  -> 22144 words (86.5 KB)
#define SA_W    0
#define SB_W    1536
#define HS_W    4608
#define EF_WORDS 22144

__global__ void __launch_bounds__(256, 2)
k_edge(const float* __restrict__ hef, const int* __restrict__ ei,
       const float* __restrict__ b1, const float* __restrict__ b2,
       const float* __restrict__ Wupd, const float* __restrict__ bupd,
       const float* __restrict__ Wread, const float* __restrict__ bread,
       float* __restrict__ out) {
    extern __shared__ uint32_t sm_[];
    int*   srol = (int*)(sm_ + 21504);
    int*   scol = (int*)(sm_ + 21632);
    float* sred = (float*)(sm_ + 21760);
    float* sg   = (float*)(sm_ + 22016);

    int t = threadIdx.x;
    int me0 = blockIdx.x * 128;
    if (t < 128) srol[t] = ei[me0 + t];
    else scol[t - 128] = ei[NE + me0 + t - 128];

    int am = t >> 1, sw = (t & 1) * 4;
    int lane = t & 31, w = t >> 5;
    int wm = (w & 3) * 32, wn = (w >> 2) * 64;
    int grp = lane >> 2, quad = lane & 3;

    uint32_t smb = (uint32_t)__cvta_generic_to_shared(sm_);
    int arow = wm + (lane & 15);
    int brow = wn + (lane & 7) + ((lane & 16) ? 8 : 0);
    uint32_t rSA = smb + SA_W * 4 + arow * (ST * 4) + ((lane & 16) ? 16 : 0);
    uint32_t rSB = smb + SB_W * 4 + brow * (ST * 4) + ((lane & 8) ? 16 : 0);
    uint32_t rHs = smb + HS_W * 4 + arow * (HST * 4) + ((lane & 16) ? 16 : 0);
    const uint32_t BUFB = 1536 * 4;

    // ---- phase A staging: attr A-tile + both W1-attr B half-tiles ----
    {
        uint32_t d = smb + (SA_W + am * ST + sw) * 4;
        cpa16(d, g_ath + (size_t)(me0 + am) * 8 + sw);
        cpa16(smb + (SB_W + am * ST + sw) * 4,
              g_w1h + (size_t)am * 264 + 256 + sw);            // hn0=0 half
        cpa16(smb + (SB_W + 1536 + am * ST + sw) * 4,
              g_w1h + (size_t)(128 + am) * 264 + 256 + sw);    // hn0=128 half
    }
    CP_COMMIT();
    CP_WAIT0();
    __syncthreads();

    float acc[2][8][4];

    // ---- phase A: hidden = relu(attr@W1attr + Pr[rol] + Pc[col] + b1) -> Hs ----
#pragma unroll
    for (int half = 0; half < 2; half++) {
#pragma unroll
        for (int i = 0; i < 2; i++)
#pragma unroll
            for (int j = 0; j < 8; j++)
#pragma unroll
                for (int k = 0; k < 4; k++) acc[i][j][k] = 0.f;

        uint32_t aH[2][4];
#pragma unroll
        for (int mf = 0; mf < 2; mf++)
            ldsm4(aH[mf], rSA + mf * (16 * ST * 4));
#pragma unroll
        for (int j = 0; j < 4; j++) {
            uint32_t bH[4];
            ldsm4(bH, rSB + half * BUFB + j * (16 * ST * 4));
#pragma unroll
            for (int mf = 0; mf < 2; mf++) {
                mma16f(acc[mf][2 * j],     aH[mf], bH[0], bH[1]);
                mma16f(acc[mf][2 * j + 1], aH[mf], bH[2], bH[3]);
            }
        }

#pragma unroll
        for (int mf = 0; mf < 2; mf++) {
            int ml0 = wm + mf * 16 + grp;
            int r0 = srol[ml0], c0n = scol[ml0];
            int r1 = srol[ml0 + 8], c1n = scol[ml0 + 8];
#pragma unroll
            for (int nf = 0; nf < 8; nf++) {
                int c = half * 128 + wn + nf * 8 + quad * 2;
                int kp = c >> 1;
                float2 bb = *(const float2*)&b1[c];
                float2 pr0 = __half22float2(*(const __half2*)&g_pnh[(size_t)r0 * 256 + kp]);
                float2 pc0 = __half22float2(*(const __half2*)&g_pnh[(size_t)c0n * 256 + 128 + kp]);
                float v0 = fmaxf(acc[mf][nf][0] + pr0.x + pc0.x + bb.x, 0.f);
                float v1 = fmaxf(acc[mf][nf][1] + pr0.y + pc0.y + bb.y, 0.f);
                sm_[HS_W + ml0 * HST + kp] = packhi16(v0, v1);
                float2 pr1 = __half22float2(*(const __half2*)&g_pnh[(size_t)r1 * 256 + kp]);
                float2 pc1 = __half22float2(*(const __half2*)&g_pnh[(size_t)c1n * 256 + 128 + kp]);
                float v2 = fmaxf(acc[mf][nf][2] + pr1.x + pc1.x + bb.x, 0.f);
                float v3 = fmaxf(acc[mf][nf][3] + pr1.y + pc1.y + bb.y, 0.f);
                sm_[HS_W + (ml0 + 8) * HST + kp] = packhi16(v2, v3);
            }
        }
    }
    __syncthreads();   // Hs complete; SB free for reuse

    // ---- phase B: cand = hidden @ W2 (A from Hs, B double-buffered) ----
    auto stageB = [&](int kt, int buf) {
        int kp = kt * 8 + sw;
        cpa16(smb + (SB_W + buf * 1536 + am * ST + sw) * 4,
              g_w2h + (size_t)am * 128 + kp);
    };

    stageB(0, 0);
    CP_COMMIT();
    CP_WAIT0();
    __syncthreads();

#pragma unroll
    for (int i = 0; i < 2; i++)
#pragma unroll
        for (int j = 0; j < 8; j++)
#pragma unroll
            for (int k = 0; k < 4; k++) acc[i][j][k] = 0.f;

    const int KT = NH / 16;  // 16
    for (int kt = 0; kt < KT; ++kt) {
        int cur = kt & 1;
        if (kt < KT - 1) {
            stageB(kt + 1, cur ^ 1);
            CP_COMMIT();
        }
        uint32_t aH[2][4];
#pragma unroll
        for (int mf = 0; mf < 2; mf++)
            ldsm4(aH[mf], rHs + kt * 32 + mf * (16 * HST * 4));
#pragma unroll
        for (int j = 0; j < 4; j++) {
            uint32_t bH[4];
            ldsm4(bH, rSB + cur * BUFB + j * (16 * ST * 4));
#pragma unroll
            for (int mf = 0; mf < 2; mf++) {
                mma16f(acc[mf][2 * j],     aH[mf], bH[0], bH[1]);
                mma16f(acc[mf][2 * j + 1], aH[mf], bH[2], bH[3]);
            }
        }
        if (kt < KT - 1) CP_WAIT0();
        __syncthreads();
    }

    // acc += b2 -> cand
#pragma unroll
    for (int mf = 0; mf < 2; mf++)
#pragma unroll
        for (int nf = 0; nf < 8; nf++) {
            int c0 = wn + nf * 8 + quad * 2;
            float bb0 = b2[c0], bb1 = b2[c0 + 1];
            acc[mf][nf][0] += bb0; acc[mf][nf][1] += bb1;
            acc[mf][nf][2] += bb0; acc[mf][nf][3] += bb1;
        }

    // ---- epilogue pass 1: gate logit dot ----
    float s0 = 0.f, s1 = 0.f, s2 = 0.f, s3 = 0.f;
#pragma unroll
    for (int mf = 0; mf < 2; mf++) {
        int r0 = wm + mf * 16 + grp;
#pragma unroll
        for (int nf = 0; nf < 8; nf++) {
            int c = wn + nf * 8 + quad * 2;
            float2 wc = *(const float2*)&Wupd[400 + c];
            float2 whv = *(const float2*)&Wupd[272 + c];
            float2 h0 = *(const float2*)&hef[(size_t)(me0 + r0) * 128 + c];
            float2 h1 = *(const float2*)&hef[(size_t)(me0 + r0 + 8) * 128 + c];
            float p0 = acc[mf][nf][0] * wc.x + acc[mf][nf][1] * wc.y + h0.x * whv.x + h0.y * whv.y;
            float p1 = acc[mf][nf][2] * wc.x + acc[mf][nf][3] * wc.y + h1.x * whv.x + h1.y * whv.y;
            if (mf == 0) { s0 += p0; s1 += p1; } else { s2 += p0; s3 += p1; }
        }
    }
    s0 += __shfl_xor_sync(0xffffffffu, s0, 1); s0 += __shfl_xor_sync(0xffffffffu, s0, 2);
    s1 += __shfl_xor_sync(0xffffffffu, s1, 1); s1 += __shfl_xor_sync(0xffffffffu, s1, 2);
    s2 += __shfl_xor_sync(0xffffffffu, s2, 1); s2 += __shfl_xor_sync(0xffffffffu, s2, 2);
    s3 += __shfl_xor_sync(0xffffffffu, s3, 1); s3 += __shfl_xor_sync(0xffffffffu, s3, 2);
    if (quad == 0) {
        int nh = w >> 2;
        sred[(wm + grp) * 2 + nh] = s0;
        sred[(wm + 8 + grp) * 2 + nh] = s1;
        sred[(wm + 16 + grp) * 2 + nh] = s2;
        sred[(wm + 24 + grp) * 2 + nh] = s3;
    }
    __syncthreads();
    if (t < 128) {
        int e = me0 + t, r = srol[t], c = scol[t];
        float tot = sred[t * 2] + sred[t * 2 + 1];
        float gv = tot + g_eproj[e * 2] + g_nproj[r * 8 + 2] + g_nproj[c * 8 + 3] + bupd[0];
        sg[t] = 1.f / (1.f + expf(-gv));
    }
    __syncthreads();

    // ---- epilogue pass 2: ef = g*cand + (1-g)*hef, write out, readout dot ----
    s0 = s1 = s2 = s3 = 0.f;
#pragma unroll
    for (int mf = 0; mf < 2; mf++) {
        int r0 = wm + mf * 16 + grp;
        float g0 = sg[r0], g1 = sg[r0 + 8];
#pragma unroll
        for (int nf = 0; nf < 8; nf++) {
            int c = wn + nf * 8 + quad * 2;
            float2 h0 = *(const float2*)&hef[(size_t)(me0 + r0) * 128 + c];
            float2 h1 = *(const float2*)&hef[(size_t)(me0 + r0 + 8) * 128 + c];
            float2 e0, e1;
            e0.x = fmaf(g0, acc[mf][nf][0] - h0.x, h0.x);
            e0.y = fmaf(g0, acc[mf][nf][1] - h0.y, h0.y);
            e1.x = fmaf(g1, acc[mf][nf][2] - h1.x, h1.x);
            e1.y = fmaf(g1, acc[mf][nf][3] - h1.y, h1.y);
            *(float2*)&out[(size_t)(me0 + r0) * 128 + c] = e0;
            *(float2*)&out[(size_t)(me0 + r0 + 8) * 128 + c] = e1;
            float2 wr = *(const float2*)&Wread[256 + c];
            float p0 = e0.x * wr.x + e0.y * wr.y;
            float p1 = e1.x * wr.x + e1.y * wr.y;
            if (mf == 0) { s0 += p0; s1 += p1; } else { s2 += p0; s3 += p1; }
        }
    }
    s0 += __shfl_xor_sync(0xffffffffu, s0, 1); s0 += __shfl_xor_sync(0xffffffffu, s0, 2);
    s1 += __shfl_xor_sync(0xffffffffu, s1, 1); s1 += __shfl_xor_sync(0xffffffffu, s1, 2);
    s2 += __shfl_xor_sync(0xffffffffu, s2, 1); s2 += __shfl_xor_sync(0xffffffffu, s2, 2);
    s3 += __shfl_xor_sync(0xffffffffu, s3, 1); s3 += __shfl_xor_sync(0xffffffffu, s3, 2);
    if (quad == 0) {
        int nh = w >> 2;
        sred[(wm + grp) * 2 + nh] = s0;
        sred[(wm + 8 + grp) * 2 + nh] = s1;
        sred[(wm + 16 + grp) * 2 + nh] = s2;
        sred[(wm + 24 + grp) * 2 + nh] = s3;
    }
    __syncthreads();
    if (t < 128) {
        int e = me0 + t, r = srol[t], c = scol[t];
        float tot = sred[t * 2] + sred[t * 2 + 1];
        float rl = tot + g_eproj[e * 2 + 1] + g_nproj[r * 8 + 4] + g_nproj[c * 8 + 5] + bread[0];
        g_rw[e] = expf(rl);
    }
}

// ---------------- readout: unnormalized scatter + segment sum ----------------
__global__ void k_rscatter(const int* __restrict__ ei, const int* __restrict__ batch,
                           const float* __restrict__ out) {
    __shared__ float sacc[NG * DE];
    __shared__ float ssum[NG];
    int t = threadIdx.x;
    for (int i = t; i < NG * DE; i += 256) sacc[i] = 0.f;
    if (t < NG) ssum[t] = 0.f;
    __syncthreads();
    int warp = t >> 5, lane = t & 31;
    for (int e = blockIdx.x * 8 + warp; e < NE; e += gridDim.x * 8) {
        int gi = batch[ei[e]];
        float rw = g_rw[e];
        float4 ef = ((const float4*)out)[e * 32 + lane];
        float* p = &sacc[gi * 128 + lane * 4];
        atomicAdd(p + 0, rw * ef.x);
        atomicAdd(p + 1, rw * ef.y);
        atomicAdd(p + 2, rw * ef.z);
        atomicAdd(p + 3, rw * ef.w);
        if (lane == 0) atomicAdd(&ssum[gi], rw);
    }
    __syncthreads();
    for (int i = t; i < NG * DE; i += 256)
        if (sacc[i] != 0.f) atomicAdd(&g_graphfeat[i], sacc[i]);
    if (t < NG && ssum[t] != 0.f) atomicAdd(&g_gsum[t], ssum[t]);
}

// ---------------- confidence ----------------
__global__ void k_conf(const float* __restrict__ Wscore, const float* __restrict__ bscore,
                       float* __restrict__ out) {
    int g = blockIdx.x, t = threadIdx.x;
    float v = g_graphfeat[g * 128 + t] / (g_gsum[g] + 1e-16f) * Wscore[t];
    v = wred(v);
    __shared__ float sm[4];
    if ((t & 31) == 0) sm[t >> 5] = v;
    __syncthreads();
    if (t == 0) {
        float s = sm[0] + sm[1] + sm[2] + sm[3] + bscore[0];
        out[(size_t)NE * DE + g] = 1.f / (1.f + expf(-s));
    }
}

// ---------------- launch ----------------
extern "C" void kernel_launch(void* const* d_in, const int* in_sizes, int n_in,
                              void* d_out, int out_size) {
    const float* x      = (const float*)d_in[0];
    const float* hef    = (const float*)d_in[1];
    const float* attr   = (const float*)d_in[2];
    const int*   ei     = (const int*)d_in[3];
    const int*   batch  = (const int*)d_in[4];
    const float* Wagg   = (const float*)d_in[6];
    const float* bagg   = (const float*)d_in[7];
    const float* W1     = (const float*)d_in[8];
    const float* b1     = (const float*)d_in[9];
    const float* W2     = (const float*)d_in[10];
    const float* b2     = (const float*)d_in[11];
    const float* Wupd   = (const float*)d_in[12];
    const float* bupd   = (const float*)d_in[13];
    const float* Wread  = (const float*)d_in[14];
    const float* bread  = (const float*)d_in[15];
    const float* Wscore = (const float*)d_in[16];
    const float* bscore = (const float*)d_in[17];
    float* out = (float*)d_out;

    static bool attr_set = false;
    if (!attr_set) {
        cudaFuncSetAttribute(k_nodegemm, cudaFuncAttributeMaxDynamicSharedMemorySize, NGM_WORDS * 4);
        cudaFuncSetAttribute(k_edge, cudaFuncAttributeMaxDynamicSharedMemorySize, EF_WORDS * 4);
        attr_set = true;
    }

    k_prep<<<(NE * 8 + 255) / 256, 256>>>(x, attr, W1, W2);
    k_nodeproj<<<(NN + 7) / 8, 256>>>(x, Wagg, Wupd, Wread);
    k_aggscatter<<<NE / 8, 256>>>(hef, attr, ei, Wagg, bagg, Wupd, Wread);
    k_nnorm<<<(NN * 64 + 255) / 256, 256>>>();
    k_nodegemm<<<dim3((NN + 127) / 128, 4), 256, NGM_WORDS * 4>>>();
    k_edge<<<NE / 128, 256, EF_WORDS * 4>>>(hef, ei, b1, b2, Wupd, bupd,
                                            Wread, bread, out);
    k_rscatter<<<296, 256>>>(ei, batch, out);
    k_conf<<<NG, 128>>>(Wscore, bscore, out);
}